// round 9
// baseline (speedup 1.0000x reference)
#include <cuda_runtime.h>
#include <math.h>
#include <stdint.h>

// Problem constants (fixed by setup_inputs)
#define BATCH 4
#define TLEN  1024
#define KD    64
#define HNUM  8
#define R32   32
#define NSEQ  32      // BATCH*HNUM
#define MROWS 4096    // BATCH*TLEN

// ---------------- scratch (static device globals; no allocation) --------------
__device__ float g_xin[BATCH * TLEN * KD];          // tf32-exact
__device__ float g_WB[320 * 1024];                  // tap-major reordered wq|wk, tf32-exact
__device__ float g_WB2[64 * 1024];                  // wv|wl transposed, tf32-exact
__device__ float g_WU[1024 * 64];                   // uni_w, tf32-exact
__device__ float g_q[NSEQ * TLEN * KD];             // [g][t][p64(d)] tf32-exact
__device__ float g_k[NSEQ * TLEN * KD];             // [g][t][p64(d)]
__device__ float g_v[NSEQ * KD * TLEN];             // [g][d][t: 64-tilewise pqk(nom64(key))]
__device__ float g_l[NSEQ * TLEN * KD];             // natural
__device__ float g_og[NSEQ * TLEN * KD];
__device__ float g_ol[NSEQ * TLEN * KD];
__device__ float g_part[4 * MROWS * KD];            // uni GEMM K-split partials

__device__ __forceinline__ float sigmoid_exact(float x) { return 1.f / (1.f + expf(-x)); }
__device__ __forceinline__ float sigmoid_fast(float x) {
    float t;
    asm("tanh.approx.f32 %0, %1;" : "=f"(t) : "f"(0.5f * x));
    return 0.5f * t + 0.5f;
}
__device__ __forceinline__ float silu_fast(float x) { return x * sigmoid_fast(x); }

// round f32 -> nearest tf32 (result is a valid f32 with low mantissa zeroed)
__device__ __forceinline__ float tf32r(float x) {
    uint32_t u;
    asm("cvt.rna.tf32.f32 %0, %1;" : "=r"(u) : "f"(x));
    return __uint_as_float(u);
}

// fragment-vectorization permutation of a 64-long contraction dim
__device__ __forceinline__ int pqk(int k) {
    return ((k & 3) << 3) | ((k >> 5) << 5) | (((k >> 4) & 1) << 2) |
           (((k >> 3) & 1) << 1) | ((k >> 2) & 1);
}
// within-8 interleave so S C-fragments serve directly as PV A-fragments:
// actual key t -> nominal PV contraction slot
__device__ __forceinline__ int nom64(int t) {
    return (t & 56) | ((t >> 1) & 3) | ((t & 1) << 2);
}

__device__ __forceinline__ void mma8(float* c,
                                     uint32_t a0, uint32_t a1, uint32_t a2, uint32_t a3,
                                     uint32_t b0, uint32_t b1) {
    asm volatile(
        "mma.sync.aligned.m16n8k8.row.col.f32.tf32.tf32.f32 "
        "{%0,%1,%2,%3}, {%4,%5,%6,%7}, {%8,%9}, {%0,%1,%2,%3};"
        : "+f"(c[0]), "+f"(c[1]), "+f"(c[2]), "+f"(c[3])
        : "r"(a0), "r"(a1), "r"(a2), "r"(a3), "r"(b0), "r"(b1));
}

__device__ __forceinline__ void cp16(uint32_t dst, const void* src) {
    asm volatile("cp.async.ca.shared.global [%0], [%1], 16;" :: "r"(dst), "l"(src) : "memory");
}
__device__ __forceinline__ void cp16p(uint32_t dst, const void* src, int sz) {
    asm volatile("cp.async.ca.shared.global [%0], [%1], 16, %2;" :: "r"(dst), "l"(src), "r"(sz) : "memory");
}
#define CPCOMMIT() asm volatile("cp.async.commit_group;" ::: "memory")
#define CPWAIT0()  asm volatile("cp.async.wait_group 0;" ::: "memory")
#define CPWAIT1()  asm volatile("cp.async.wait_group 1;" ::: "memory")
#define CPWAIT2()  asm volatile("cp.async.wait_group 2;" ::: "memory")

__device__ __forceinline__ void barg(int id) {
    asm volatile("bar.sync %0, 128;" :: "r"(id) : "memory");
}

// ================= fused action + pos_emb -> xin (tf32-exact) ==================
__global__ __launch_bounds__(256) void fused_xin_kernel(
    const float* __restrict__ x, const float* __restrict__ sq_w,
    const float* __restrict__ bn_g, const float* __restrict__ bn_b,
    const float* __restrict__ dw_w, const float* __restrict__ ex_w,
    const float* __restrict__ pos_emb)
{
    __shared__ float xs[34][68];
    __shared__ float x3s[34][36];
    __shared__ float xp3[32][32];
    __shared__ float sqT[64][32];
    __shared__ float exT[32][64];
    __shared__ float bng_s[32], bnb_s[32];

    int bi = blockIdx.x;
    int t0 = blockIdx.y * 32;
    int tid = threadIdx.x;
    int nrows = min(34, TLEN - t0);

    for (int i = tid; i < nrows * 16; i += 256) {
        int row = i >> 4, c4 = (i & 15) << 2;
        *(float4*)&xs[row][c4] = *(const float4*)&x[((size_t)bi * TLEN + t0 + row) * KD + c4];
    }
    for (int i = tid; i < 2048; i += 256) { int r = i >> 6, c = i & 63; sqT[c][r] = sq_w[i]; }
    for (int i = tid; i < 2048; i += 256) { int c = i >> 5, r = i & 31; exT[r][c] = ex_w[i]; }
    if (tid < 32) { bng_s[tid] = bn_g[tid] * 0.9999950000374997f; bnb_s[tid] = bn_b[tid]; }
    __syncthreads();

    {
        int j = tid >> 2, rg = (tid & 3) << 3;
        if (j < nrows) {
            float acc[8];
#pragma unroll
            for (int i = 0; i < 8; ++i) acc[i] = 0.f;
#pragma unroll
            for (int c4 = 0; c4 < 64; c4 += 4) {
                float4 xv = *(const float4*)&xs[j][c4];
#pragma unroll
                for (int t = 0; t < 4; ++t) {
                    float xc = (t == 0) ? xv.x : (t == 1) ? xv.y : (t == 2) ? xv.z : xv.w;
                    float4 s0 = *(const float4*)&sqT[c4 + t][rg];
                    float4 s1 = *(const float4*)&sqT[c4 + t][rg + 4];
                    acc[0] += xc * s0.x; acc[1] += xc * s0.y;
                    acc[2] += xc * s0.z; acc[3] += xc * s0.w;
                    acc[4] += xc * s1.x; acc[5] += xc * s1.y;
                    acc[6] += xc * s1.z; acc[7] += xc * s1.w;
                }
            }
#pragma unroll
            for (int i = 0; i < 8; ++i)
                x3s[j][rg + i] = acc[i] * bng_s[rg + i] + bnb_s[rg + i];
        }
    }
    __syncthreads();

    for (int idx = tid; idx < 32 * 32; idx += 256) {
        int r = idx & 31, jj = idx >> 5;
        int pos = t0 + jj;
        float base = x3s[jj][r];
        float v;
        if (pos == TLEN - 1) {
            v = base;
        } else {
            float d0 = dw_w[r * 3 + 0], d1 = dw_w[r * 3 + 1], d2 = dw_w[r * 3 + 2];
            float a = base * d0 + x3s[jj + 1][r] * d1 +
                      ((pos + 2 < TLEN) ? x3s[jj + 2][r] * d2 : 0.f);
            v = a - base;
        }
        xp3[jj][r] = v;
    }
    __syncthreads();

    for (int idx = tid; idx < 32 * 64; idx += 256) {
        int c = idx & 63, j = idx >> 6;
        int pos = t0 + j;
        float gsum = 0.f;
#pragma unroll
        for (int r = 0; r < R32; ++r) gsum += xp3[j][r] * exT[r][c];
        float sig = sigmoid_exact(gsum);
        size_t off = ((size_t)bi * TLEN + pos) * KD + c;
        g_xin[off] = tf32r(xs[j][c] * sig + pos_emb[pos * KD + c]);
    }
}

// ---------------- weight prep (reorder + tf32 round, single kernel) ------------
__global__ __launch_bounds__(256) void prep_w_kernel(
    const float* __restrict__ wq, const float* __restrict__ wk,
    const float* __restrict__ wv, const float* __restrict__ wl,
    const float* __restrict__ uni_w)
{
    int idx = blockIdx.x * 256 + threadIdx.x;
    if (idx < 320 * 1024) {
        int n = idx & 1023, kcol = idx >> 10;
        int mm = kcol >> 6, c = kcol & 63;
        float w = (n < 512) ? wq[n * 320 + c * 5 + mm] : wk[(n - 512) * 320 + c * 5 + mm];
        g_WB[idx] = tf32r(w);
    } else if (idx < 320 * 1024 + 65536) {
        int j = idx - 320 * 1024;
        int n = j & 1023, c = j >> 10;
        g_WB2[j] = tf32r((n < 512) ? wv[n * 64 + c] : wl[(n - 512) * 64 + c]);
    } else if (idx < 320 * 1024 + 131072) {
        int j = idx - (320 * 1024 + 65536);
        g_WU[j] = tf32r(uni_w[j]);
    }
}

// ---------------- conv GEMMs (tf32 mma, cp.async dbl-buffered, mode=blockIdx.z) --
__global__ __launch_bounds__(256, 2) void convgemm_kernel(
    const float* __restrict__ bias0, const float* __restrict__ bias1)
{
    int mode = blockIdx.z;
    const int NSTAGE = (mode == 0) ? 10 : 2;
    extern __shared__ float sm[];
    float* As = sm;                   // [2][128][36]
    float* Bs = sm + 2 * 128 * 36;    // [2][32][68]
    const float* __restrict__ Bg = (mode == 0) ? g_WB : g_WB2;

    int tid = threadIdx.x, lane = tid & 31, wid = tid >> 5;
    int wm = wid & 3, wn = wid >> 2, gi = lane >> 2, ci = lane & 3;
    int m0 = blockIdx.x * 128, n0 = blockIdx.y * 64;
    int bi = m0 >> 10, tibase = m0 & 1023;
    uint32_t sb = (uint32_t)__cvta_generic_to_shared(sm);
    uint32_t a_sb = sb, b_sb = sb + 2 * 128 * 36 * 4;

    auto issue_stage = [&](int s_, int buf_) {
        int mm_ = (mode == 0) ? (s_ >> 1) : 0;
        int c0_ = (mode == 0) ? ((s_ & 1) << 5) : (s_ << 5);
        int sh_ = (mode == 0) ? (2 * mm_ - 8) : 0;
#pragma unroll
        for (int i_ = 0; i_ < 4; ++i_) {
            int f4 = tid + i_ * 256;
            int row = f4 >> 3, c4 = (f4 & 7) << 2;
            int tsrc = tibase + row + sh_;
            const float* srcp = g_xin + ((size_t)(bi << 10) + tsrc) * 64 + c0_ + c4;
            uint32_t dstp = a_sb + (uint32_t)((buf_ * 4608 + row * 36 + c4) * 4);
            cp16p(dstp, srcp, (tsrc >= 0) ? 16 : 0);
        }
#pragma unroll
        for (int i_ = 0; i_ < 2; ++i_) {
            int f4 = tid + i_ * 256;
            int row = f4 >> 4, c4 = (f4 & 15) << 2;
            const float* srcp = Bg + (size_t)(s_ * 32 + row) * 1024 + n0 + c4;
            uint32_t dstp = b_sb + (uint32_t)((buf_ * 2176 + row * 68 + c4) * 4);
            cp16(dstp, srcp);
        }
        CPCOMMIT();
    };

    float acc[2][4][4];
#pragma unroll
    for (int a = 0; a < 2; ++a)
#pragma unroll
        for (int b = 0; b < 4; ++b)
#pragma unroll
            for (int c = 0; c < 4; ++c) acc[a][b][c] = 0.f;

    issue_stage(0, 0);
    for (int s = 0; s < NSTAGE; ++s) {
        if (s + 1 < NSTAGE) { issue_stage(s + 1, (s + 1) & 1); CPWAIT1(); }
        else CPWAIT0();
        __syncthreads();
        const float* Ab = As + (s & 1) * 4608;
        const float* Bb = Bs + (s & 1) * 2176;
#pragma unroll
        for (int kk = 0; kk < 4; ++kk) {
            int k = kk * 8;
            uint32_t af[2][4];
#pragma unroll
            for (int mi = 0; mi < 2; ++mi) {
                int r = wm * 32 + mi * 16 + gi;
                af[mi][0] = __float_as_uint(Ab[r * 36 + k + ci]);
                af[mi][1] = __float_as_uint(Ab[(r + 8) * 36 + k + ci]);
                af[mi][2] = __float_as_uint(Ab[r * 36 + k + ci + 4]);
                af[mi][3] = __float_as_uint(Ab[(r + 8) * 36 + k + ci + 4]);
            }
            uint32_t bf[4][2];
#pragma unroll
            for (int ni = 0; ni < 4; ++ni) {
                int n = wn * 32 + ni * 8 + gi;
                bf[ni][0] = __float_as_uint(Bb[(k + ci) * 68 + n]);
                bf[ni][1] = __float_as_uint(Bb[(k + ci + 4) * 68 + n]);
            }
#pragma unroll
            for (int mi = 0; mi < 2; ++mi)
#pragma unroll
                for (int ni = 0; ni < 4; ++ni)
                    mma8(acc[mi][ni], af[mi][0], af[mi][1], af[mi][2], af[mi][3],
                         bf[ni][0], bf[ni][1]);
        }
        __syncthreads();
    }

#pragma unroll
    for (int mi = 0; mi < 2; ++mi)
#pragma unroll
        for (int ni = 0; ni < 4; ++ni)
#pragma unroll
            for (int j = 0; j < 4; ++j) {
                int m = m0 + wm * 32 + mi * 16 + gi + ((j >= 2) ? 8 : 0);
                int n = n0 + wn * 32 + ni * 8 + 2 * ci + (j & 1);
                float v = acc[mi][ni][j];
                int o = n & 511, ki = o >> 3, h = o & 7;
                int bb = m >> 10, ti = m & 1023;
                int gg = bb * 8 + (ti >> 7);
                int tj = ((ti & 127) << 3) | h;
                if (mode == 0) {
                    float bias = (n < 512) ? bias0[n] : bias1[n - 512];
                    float s = silu_fast(v + bias) * 0.35355339059327373f;  // / 64^0.25
                    float* dst = (n < 512) ? g_q : g_k;
                    dst[((size_t)gg * TLEN + tj) * KD + pqk(ki)] = tf32r(s);
                } else {
                    float s = silu_fast(v);
                    if (n < 512) {
                        // V transposed [g][d][key], key permuted so S C-frags = PV A-frags
                        g_v[((size_t)gg * KD + ki) * TLEN + (tj & ~63) + pqk(nom64(tj & 63))] = tf32r(s);
                    } else {
                        g_l[((size_t)gg * TLEN + tj) * KD + ki] = tf32r(s);
                    }
                }
            }
}

// ---------------- flash attention v5: zero-shuffle PV via key-permuted V --------
// block (g, p): group B (warps 4-7): q-tile qb=15-p, k-tiles 0..8.
// group A (warps 0-3): q-tile qa=p fully (p+1 tiles) + qb k-tiles 9..15-p.
// Groups decoupled (named barriers, private smem). Split-KV merge for qb.
__global__ __launch_bounds__(256, 2) void flash_mma_kernel()
{
    extern __shared__ float sm[];   // A: K[2][4096] V[4096] @0 | B: same @12288
    int g  = blockIdx.x;
    int p  = blockIdx.y;
    int qa = p, qb = 15 - p;
    int tid = threadIdx.x, lane = tid & 31, wid = tid >> 5;
    int gi = lane >> 2, ci = lane & 3;
    int wa = wid & 3;
    bool grpB = wid >= 4;
    int barid = grpB ? 2 : 1;
    int Na = p + 1;
    int NIT = grpB ? 9 : 8;
    uint32_t sb = (uint32_t)__cvta_generic_to_shared(sm);
    int KO = grpB ? 12288 : 0;
    int VO = KO + 8192;
    int lt = wa * 32 + lane;

    // hoisted swizzled chunk offsets (row&7 == gi for all fragment rows)
    int offw[4];
#pragma unroll
    for (int t4 = 0; t4 < 4; ++t4)
        offw[t4] = (((2 * ci + (t4 & 1) + ((t4 >> 1) << 3)) ^ gi) << 2);

    const float* Qg  = g_q + (size_t)g * (TLEN * KD);
    const float* Kg0 = g_k + (size_t)g * (TLEN * KD);
    const float* Vg0 = g_v + (size_t)g * (KD * TLEN);

    int qt = grpB ? qb : qa;
    int qbase = qt * 64 + wa * 16;
    int r0 = qbase + gi;

    uint32_t qf[8][4];
    auto load_qf = [&]() {
#pragma unroll
        for (int t4 = 0; t4 < 4; ++t4) {
            int woff = (2 * ci + (t4 & 1) + ((t4 >> 1) << 3)) << 2;
            float4 lo = *(const float4*)&Qg[(size_t)r0 * KD + woff];
            float4 hi = *(const float4*)&Qg[(size_t)(r0 + 8) * KD + woff];
            int kk0 = ((t4 >> 1) << 2) + ((t4 & 1) << 1);
            qf[kk0][0]     = __float_as_uint(lo.x); qf[kk0][2]     = __float_as_uint(lo.y);
            qf[kk0 + 1][0] = __float_as_uint(lo.z); qf[kk0 + 1][2] = __float_as_uint(lo.w);
            qf[kk0][1]     = __float_as_uint(hi.x); qf[kk0][3]     = __float_as_uint(hi.y);
            qf[kk0 + 1][1] = __float_as_uint(hi.z); qf[kk0 + 1][3] = __float_as_uint(hi.w);
        }
    };
    load_qf();

    float o[8][4];
#pragma unroll
    for (int a = 0; a < 8; ++a)
#pragma unroll
        for (int b = 0; b < 4; ++b) o[a][b] = 0.f;
    float m0v = -1e30f, m1v = -1e30f, l0 = 0.f, l1 = 0.f;

    auto kt_of = [&](int i) {
        if (grpB) return i;
        return (i < Na) ? i : (9 + i - Na);
    };

    auto issueK = [&](int i, int buf) {
        int k0 = kt_of(i) * 64;
#pragma unroll
        for (int j = 0; j < 8; ++j) {
            int f4 = lt + j * 128;
            int row = f4 >> 4, chunk = f4 & 15;
            int swc = chunk ^ (row & 7);
            cp16(sb + (uint32_t)((KO + buf * 4096 + row * 64 + swc * 4) * 4),
                 Kg0 + (size_t)(k0 + row) * 64 + chunk * 4);
        }
        CPCOMMIT();
    };
    auto issueV = [&](int i) {
        int k0 = kt_of(i) * 64;
#pragma unroll
        for (int j = 0; j < 8; ++j) {
            int f4 = lt + j * 128;
            int row = f4 >> 4, chunk = f4 & 15;
            int swc = chunk ^ (row & 7);
            cp16(sb + (uint32_t)((VO + row * 64 + swc * 4) * 4),
                 Vg0 + (size_t)row * TLEN + k0 + chunk * 4);
        }
        CPCOMMIT();
    };

    auto epilogue_store = [&]() {
        float inv0 = 1.f / l0, inv1 = 1.f / l1;
        float* Og = g_og + (size_t)g * (TLEN * KD);
#pragma unroll
        for (int nd = 0; nd < 8; ++nd) {
            int c = nd * 8 + 2 * ci;
            float2 t0; t0.x = o[nd][0] * inv0; t0.y = o[nd][1] * inv0;
            float2 t1; t1.x = o[nd][2] * inv1; t1.y = o[nd][3] * inv1;
            *(float2*)&Og[(size_t)r0 * KD + c] = t0;
            *(float2*)&Og[(size_t)(r0 + 8) * KD + c] = t1;
        }
    };
    auto reset_state = [&]() {
#pragma unroll
        for (int a = 0; a < 8; ++a)
#pragma unroll
            for (int b = 0; b < 4; ++b) o[a][b] = 0.f;
        m0v = -1e30f; m1v = -1e30f; l0 = 0.f; l1 = 0.f;
    };

    issueK(0, 0);
    for (int i = 0; i < NIT; ++i) {
        if (!grpB && i == Na) {
            epilogue_store();
            reset_state();
            qt = qb; qbase = qt * 64 + wa * 16; r0 = qbase + gi;
            load_qf();
        }
        bool more = (i + 1 < NIT);
        issueV(i);
        if (more) issueK(i + 1, (i + 1) & 1);
        if (more) CPWAIT2(); else CPWAIT1();    // K(i) ready
        barg(barid);

        int k0 = kt_of(i) * 64;
        const float* Ks = sm + KO + (i & 1) * 4096;
        const float* Vs = sm + VO;

        // S = Q K^T : per ni, 4 LDS128 + 8 MMA
        float s[8][4];
#pragma unroll
        for (int ni = 0; ni < 8; ++ni) {
            s[ni][0] = s[ni][1] = s[ni][2] = s[ni][3] = 0.f;
            const uint32_t* Krow = (const uint32_t*)(Ks + (ni * 8 + gi) * 64);
#pragma unroll
            for (int t4 = 0; t4 < 4; ++t4) {
                uint4 F = *(const uint4*)(Krow + offw[t4]);
                int kk0 = ((t4 >> 1) << 2) + ((t4 & 1) << 1);
                mma8(s[ni], qf[kk0][0], qf[kk0][1], qf[kk0][2], qf[kk0][3], F.x, F.y);
                mma8(s[ni], qf[kk0 + 1][0], qf[kk0 + 1][1], qf[kk0 + 1][2], qf[kk0 + 1][3], F.z, F.w);
            }
        }
        if (k0 + 63 > qbase) {   // diagonal tile: causal mask
#pragma unroll
            for (int ni = 0; ni < 8; ++ni)
#pragma unroll
                for (int j = 0; j < 4; ++j) {
                    int col = k0 + ni * 8 + 2 * ci + (j & 1);
                    int row = r0 + ((j >= 2) ? 8 : 0);
                    if (col > row) s[ni][j] = -1e30f;
                }
        }
        // online softmax
        float mx0 = -1e30f, mx1 = -1e30f;
#pragma unroll
        for (int ni = 0; ni < 8; ++ni) {
            mx0 = fmaxf(mx0, fmaxf(s[ni][0], s[ni][1]));
            mx1 = fmaxf(mx1, fmaxf(s[ni][2], s[ni][3]));
        }
        mx0 = fmaxf(mx0, __shfl_xor_sync(0xffffffffu, mx0, 1));
        mx0 = fmaxf(mx0, __shfl_xor_sync(0xffffffffu, mx0, 2));
        mx1 = fmaxf(mx1, __shfl_xor_sync(0xffffffffu, mx1, 1));
        mx1 = fmaxf(mx1, __shfl_xor_sync(0xffffffffu, mx1, 2));
        float m0n = fmaxf(m0v, mx0), m1n = fmaxf(m1v, mx1);
        float corr0 = __expf(m0v - m0n), corr1 = __expf(m1v - m1n);

        float sum0 = 0.f, sum1 = 0.f;
#pragma unroll
        for (int ni = 0; ni < 8; ++ni) {
            s[ni][0] = tf32r(__expf(s[ni][0] - m0n));
            s[ni][1] = tf32r(__expf(s[ni][1] - m0n));
            s[ni][2] = tf32r(__expf(s[ni][2] - m1n));
            s[ni][3] = tf32r(__expf(s[ni][3] - m1n));
            sum0 += s[ni][0] + s[ni][1];
            sum1 += s[ni][2] + s[ni][3];
        }
        sum0 += __shfl_xor_sync(0xffffffffu, sum0, 1);
        sum0 += __shfl_xor_sync(0xffffffffu, sum0, 2);
        sum1 += __shfl_xor_sync(0xffffffffu, sum1, 1);
        sum1 += __shfl_xor_sync(0xffffffffu, sum1, 2);
        l0 = l0 * corr0 + sum0;
        l1 = l1 * corr1 + sum1;
        m0v = m0n; m1v = m1n;
#pragma unroll
        for (int nd = 0; nd < 8; ++nd) {
            o[nd][0] *= corr0; o[nd][1] *= corr0;
            o[nd][2] *= corr1; o[nd][3] *= corr1;
        }
        // V(i) ready?
        if (more) CPWAIT1(); else CPWAIT0();
        barg(barid);
        // P @ V : S C-fragments ARE the A-fragments (a0=c0,a1=c2,a2=c1,a3=c3)
        // thanks to the nom64 key interleave baked into V's layout. No shuffles.
#pragma unroll
        for (int nd = 0; nd < 8; ++nd) {
            const uint32_t* Vrow = (const uint32_t*)(Vs + (nd * 8 + gi) * 64);
#pragma unroll
            for (int t4 = 0; t4 < 4; ++t4) {
                uint4 F = *(const uint4*)(Vrow + offw[t4]);
                int kg0 = ((t4 >> 1) << 2) + ((t4 & 1) << 1);
                mma8(o[nd], __float_as_uint(s[kg0][0]), __float_as_uint(s[kg0][2]),
                     __float_as_uint(s[kg0][1]), __float_as_uint(s[kg0][3]), F.x, F.y);
                mma8(o[nd], __float_as_uint(s[kg0 + 1][0]), __float_as_uint(s[kg0 + 1][2]),
                     __float_as_uint(s[kg0 + 1][1]), __float_as_uint(s[kg0 + 1][3]), F.z, F.w);
            }
        }
        barg(barid);   // protect V buffer before next issues
    }

    if (!grpB && Na == NIT) {    // p==7: finalize qa, empty qb partial
        epilogue_store();
        reset_state();
        qt = qb; qbase = qt * 64 + wa * 16; r0 = qbase + gi;
    }

    // ---- split-KV merge for q-tile qb
    float* ob = sm + 12288;
    float* mb = sm + 12288 + 4352;
    float* lb = mb + 64;
    if (grpB) {
        int rr = wa * 16 + gi;
#pragma unroll
        for (int nd = 0; nd < 8; ++nd) {
            int c = nd * 8 + 2 * ci;
            *(float2*)&ob[rr * 68 + c]       = make_float2(o[nd][0], o[nd][1]);
            *(float2*)&ob[(rr + 8) * 68 + c] = make_float2(o[nd][2], o[nd][3]);
        }
        if (ci == 0) {
            mb[rr] = m0v; lb[rr] = l0;
            mb[rr + 8] = m1v; lb[rr + 8] = l1;
        }
    }
    __syncthreads();
    if (!grpB) {
        int rr = wa * 16 + gi;
        float mB0 = mb[rr], lB0 = lb[rr], mB1 = mb[rr + 8], lB1 = lb[rr + 8];
        float mS0 = fmaxf(m0v, mB0), mS1 = fmaxf(m1v, mB1);
        float cA0 = __expf(m0v - mS0), cB0 = __expf(mB0 - mS0);
        float cA1 = __expf(m1v - mS1), cB1 = __expf(mB1 - mS1);
        l0 = l0 * cA0 + lB0 * cB0;
        l1 = l1 * cA1 + lB1 * cB1;
#pragma unroll
        for (int nd = 0; nd < 8; ++nd) {
            int c = nd * 8 + 2 * ci;
            float2 b0 = *(float2*)&ob[rr * 68 + c];
            float2 b1 = *(float2*)&ob[(rr + 8) * 68 + c];
            o[nd][0] = o[nd][0] * cA0 + b0.x * cB0;
            o[nd][1] = o[nd][1] * cA0 + b0.y * cB0;
            o[nd][2] = o[nd][2] * cA1 + b1.x * cB1;
            o[nd][3] = o[nd][3] * cA1 + b1.y * cB1;
        }
        epilogue_store();
    }
}

// ---------------- local windowed causal attention (smem, quad-per-query) -------
__global__ __launch_bounds__(256) void local_attn_kernel()
{
    __shared__ float Ls[69][68];
    int g = blockIdx.x, t0 = blockIdx.y * 64;
    int tid = threadIdx.x;
    const float* Lg = g_l + (size_t)g * (TLEN * KD);
    for (int i = tid; i < 69 * 16; i += 256) {
        int r = i >> 4, c4 = (i & 15) << 2;
        int tg = t0 - 5 + r;
        float4 v = make_float4(0.f, 0.f, 0.f, 0.f);
        if (tg >= 0) v = *(const float4*)&Lg[(size_t)tg * 64 + c4];
        *(float4*)&Ls[r][c4] = v;
    }
    __syncthreads();

    int q = tid >> 2, pi = tid & 3;
    int tj = t0 + q;
    float4 xq[4];
#pragma unroll
    for (int i = 0; i < 4; ++i)
        xq[i] = *(const float4*)&Ls[q + 5][pi * 4 + i * 16];

    float sc[6], mx = -1e30f;
#pragma unroll
    for (int w = 0; w < 6; ++w) {
        float d = 0.f;
#pragma unroll
        for (int i = 0; i < 4; ++i) {
            float4 rv = *(const float4*)&Ls[q + w][pi * 4 + i * 16];
            d += xq[i].x * rv.x + xq[i].y * rv.y + xq[i].z * rv.z + xq[i].w * rv.w;
        }
        d += __shfl_xor_sync(0xffffffffu, d, 1);
        d += __shfl_xor_sync(0xffffffffu, d, 2);
        sc[w] = (tj - 5 + w >= 0) ? d * 0.125f : -1e30f;   // / sqrt(64)
        mx = fmaxf(mx, sc[w]);
    }
    float e[6], den = 0.f;
#pragma unroll
    for (int w = 0; w < 6; ++w) { e[w] = __expf(sc[w] - mx); den += e[w]; }
    float inv = 1.f / den;

    float4 acc[4];
#pragma unroll
    for (int i = 0; i < 4; ++i) acc[i] = make_float4(0.f, 0.f, 0.f, 0.f);
#pragma unroll
    for (int w = 0; w < 6; ++w) {
        float ew = e[w];
#pragma unroll
        for (int i = 0; i < 4; ++i) {
            float4 rv = *(const float4*)&Ls[q + w][pi * 4 + i * 16];
            acc[i].x += ew * rv.x; acc[i].y += ew * rv.y;
            acc[i].z += ew * rv.z; acc[i].w += ew * rv.w;
        }
    }
    float* Og = g_ol + (size_t)g * (TLEN * KD) + (size_t)tj * 64;
#pragma unroll
    for (int i = 0; i < 4; ++i) {
        float4 t;
        t.x = acc[i].x * inv; t.y = acc[i].y * inv;
        t.z = acc[i].z * inv; t.w = acc[i].w * inv;
        *(float4*)&Og[pi * 4 + i * 16] = t;
    }
}

// ---------------- uni projection: fused gating + K-split tf32 GEMM -------------
__global__ __launch_bounds__(256, 2) void unigemm_kernel()
{
    __shared__ float As[128][36];
    __shared__ float Bs[32][68];
    int tid = threadIdx.x, lane = tid & 31, wid = tid >> 5;
    int wm = wid & 3, wn = wid >> 2, gi = lane >> 2, ci = lane & 3;
    int m0 = blockIdx.x * 128;
    int kz = blockIdx.y;
    int bi = m0 >> 10, tib = m0 & 1023;
    uint32_t b_sb = (uint32_t)__cvta_generic_to_shared(&Bs[0][0]);

    float acc[2][4][4];
#pragma unroll
    for (int a = 0; a < 2; ++a)
#pragma unroll
        for (int b = 0; b < 4; ++b)
#pragma unroll
            for (int c = 0; c < 4; ++c) acc[a][b][c] = 0.f;

    for (int s = 0; s < 8; ++s) {
        int k0 = kz * 256 + s * 32;
        int ch = k0 >> 6, ki0 = k0 & 63;
        int h2 = ch & 7;
        bool lohalf = ch < 8;
        const float* Og = g_og + (size_t)(bi * 8 + h2) * (TLEN * KD);
        const float* Lg = g_ol + (size_t)(bi * 8 + h2) * (TLEN * KD);
        __syncthreads();
#pragma unroll
        for (int i = 0; i < 2; ++i) {
            int f4 = tid + i * 256;
            int row = f4 >> 4, c4 = (f4 & 15) << 2;
            cp16(b_sb + (uint32_t)((row * 68 + c4) * 4), g_WU + (size_t)(k0 + row) * 64 + c4);
        }
        CPCOMMIT();
#pragma unroll
        for (int i = 0; i < 4; ++i) {
            int f4 = tid + i * 256;
            int row = f4 >> 3, c4 = (f4 & 7) << 2;
            int ti2 = tib + row;
            const float4 o4 = *(const float4*)(Og + (size_t)ti2 * 64 + ki0 + c4);
            const float4 l4 = *(const float4*)(Lg + (size_t)ti2 * 64 + ki0 + c4);
            float g0 = sigmoid_fast(o4.x), g1 = sigmoid_fast(o4.y);
            float g2 = sigmoid_fast(o4.z), g3 = sigmoid_fast(o4.w);
            float r0 = lohalf ? (1.f - g0) * l4.x : g0 * o4.x;
            float r1 = lohalf ? (1.f - g1) * l4.y : g1 * o4.y;
            float r2 = lohalf ? (1.f - g2) * l4.z : g2 * o4.z;
            float r3 = lohalf ? (1.f - g3) * l4.w : g3 * o4.w;
            As[row][c4 + 0] = tf32r(r0);
            As[row][c4 + 1] = tf32r(r1);
            As[row][c4 + 2] = tf32r(r2);
            As[row][c4 + 3] = tf32r(r3);
        }
        CPWAIT0();
        __syncthreads();
#pragma unroll
        for (int kk = 0; kk < 4; ++kk) {
            int k = kk * 8;
            uint32_t af[2][4];
#pragma unroll
            for (int mi = 0; mi < 2; ++mi) {
                int r = wm * 32 + mi * 16 + gi;
                af[mi][0] = __float_as_uint(As[r][k + ci]);
                af[mi][1] = __float_as_uint(As[r + 8][k + ci]);
                af[mi][2] = __float_as_uint(As[r][k + ci + 4]);
                af[mi][3] = __float_as_uint(As[r + 8][k + ci + 4]);
            }
            uint32_t bf[4][2];
#pragma unroll
            for (int ni = 0; ni < 4; ++ni) {
                int n = wn * 32 + ni * 8 + gi;
                bf[ni][0] = __float_as_uint(Bs[k + ci][n]);
                bf[ni][1] = __float_as_uint(Bs[k + ci + 4][n]);
            }
#pragma unroll
            for (int mi = 0; mi < 2; ++mi)
#pragma unroll
                for (int ni = 0; ni < 4; ++ni)
                    mma8(acc[mi][ni], af[mi][0], af[mi][1], af[mi][2], af[mi][3],
                         bf[ni][0], bf[ni][1]);
        }
    }

    float* P = g_part + ((size_t)kz * MROWS + m0) * 64;
#pragma unroll
    for (int mi = 0; mi < 2; ++mi)
#pragma unroll
        for (int ni = 0; ni < 4; ++ni)
#pragma unroll
            for (int j = 0; j < 4; j += 2) {
                int mrow = wm * 32 + mi * 16 + gi + ((j >= 2) ? 8 : 0);
                int n = wn * 32 + ni * 8 + 2 * ci;
                float2 t; t.x = acc[mi][ni][j]; t.y = acc[mi][ni][j + 1];
                *(float2*)&P[(size_t)mrow * 64 + n] = t;
            }
}

// ---------------- partial-reduce + silu + residual -> LN1 -> FF -> LN2 ---------
__global__ __launch_bounds__(256) void ffln_kernel(
    const float* __restrict__ uni_b,
    const float* __restrict__ ln1g, const float* __restrict__ ln1b,
    const float* __restrict__ ln2g, const float* __restrict__ ln2b,
    const float* __restrict__ w1, const float* __restrict__ b1,
    const float* __restrict__ w2, const float* __restrict__ b2,
    float* __restrict__ out)
{
    const int R = 16;
    __shared__ float yl[R][64];
    __shared__ float hs[R][256];
    __shared__ float fs[R][64];
    int r0 = blockIdx.x * R;
    int tid = threadIdx.x;
    int lane = tid & 31, w = tid >> 5;

    for (int rr = 0; rr < 2; ++rr) {
        int r = w * 2 + rr;
        size_t rg = (size_t)(r0 + r) * 64;
        float v0 = g_part[rg + lane] + g_part[(size_t)MROWS * 64 + rg + lane] +
                   g_part[(size_t)MROWS * 128 + rg + lane] + g_part[(size_t)MROWS * 192 + rg + lane];
        float v1 = g_part[rg + lane + 32] + g_part[(size_t)MROWS * 64 + rg + lane + 32] +
                   g_part[(size_t)MROWS * 128 + rg + lane + 32] + g_part[(size_t)MROWS * 192 + rg + lane + 32];
        v0 = silu_fast(v0 + uni_b[lane]) + g_xin[rg + lane];
        v1 = silu_fast(v1 + uni_b[lane + 32]) + g_xin[rg + lane + 32];
        float sm = v0 + v1;
#pragma unroll
        for (int o = 16; o; o >>= 1) sm += __shfl_xor_sync(0xffffffffu, sm, o);
        float mean = sm * (1.f / 64.f);
        float d0 = v0 - mean, d1 = v1 - mean;
        float vs = d0 * d0 + d1 * d1;
#pragma unroll
        for (int o = 16; o; o >>= 1) vs += __shfl_xor_sync(0xffffffffu, vs, o);
        float inv = rsqrtf(vs * (1.f / 64.f) + 1e-5f);
        yl[r][lane]      = d0 * inv * ln1g[lane] + ln1b[lane];
        yl[r][lane + 32] = d1 * inv * ln1g[lane + 32] + ln1b[lane + 32];
    }
    __syncthreads();

    {
        float acc[R];
#pragma unroll
        for (int r = 0; r < R; ++r) acc[r] = b1[tid];
        for (int c = 0; c < 64; ++c) {
            float wv = w1[c * 256 + tid];
#pragma unroll
            for (int r = 0; r < R; ++r) acc[r] += yl[r][c] * wv;
        }
#pragma unroll
        for (int r = 0; r < R; ++r) hs[r][tid] = fmaxf(acc[r], 0.f);
    }
    __syncthreads();

    {
        int j2 = tid & 63, rg = tid >> 6;
        float acc[4];
#pragma unroll
        for (int rr = 0; rr < 4; ++rr) acc[rr] = b2[j2];
        for (int c = 0; c < 256; ++c) {
            float wv = w2[c * 64 + j2];
#pragma unroll
            for (int rr = 0; rr < 4; ++rr) acc[rr] += hs[rg * 4 + rr][c] * wv;
        }
#pragma unroll
        for (int rr = 0; rr < 4; ++rr) fs[rg * 4 + rr][j2] = acc[rr] + yl[rg * 4 + rr][j2];
    }
    __syncthreads();

    for (int rr = 0; rr < 2; ++rr) {
        int r = w * 2 + rr;
        float v0 = fs[r][lane], v1 = fs[r][lane + 32];
        float sm = v0 + v1;
#pragma unroll
        for (int o = 16; o; o >>= 1) sm += __shfl_xor_sync(0xffffffffu, sm, o);
        float mean = sm * (1.f / 64.f);
        float d0 = v0 - mean, d1 = v1 - mean;
        float vs = d0 * d0 + d1 * d1;
#pragma unroll
        for (int o = 16; o; o >>= 1) vs += __shfl_xor_sync(0xffffffffu, vs, o);
        float inv = rsqrtf(vs * (1.f / 64.f) + 1e-5f);
        float* orow = out + (size_t)(r0 + r) * 64;
        orow[lane]      = d0 * inv * ln2g[lane] + ln2b[lane];
        orow[lane + 32] = d1 * inv * ln2g[lane + 32] + ln2b[lane + 32];
    }
}

// ---------------- launch ---------------------------------------------------------
extern "C" void kernel_launch(void* const* d_in, const int* in_sizes, int n_in,
                              void* d_out, int out_size)
{
    (void)in_sizes; (void)n_in; (void)out_size;
    const float* x       = (const float*)d_in[0];
    const float* sq_w    = (const float*)d_in[1];
    const float* bn_g    = (const float*)d_in[2];
    const float* bn_b    = (const float*)d_in[3];
    const float* dw_w    = (const float*)d_in[4];
    const float* ex_w    = (const float*)d_in[5];
    const float* pos_emb = (const float*)d_in[6];
    const float* wq      = (const float*)d_in[7];
    const float* bq      = (const float*)d_in[8];
    const float* wk      = (const float*)d_in[9];
    const float* bk      = (const float*)d_in[10];
    const float* wv      = (const float*)d_in[11];
    const float* wl      = (const float*)d_in[12];
    const float* uni_w   = (const float*)d_in[13];
    const float* uni_b   = (const float*)d_in[14];
    const float* ln1_g   = (const float*)d_in[15];
    const float* ln1_b   = (const float*)d_in[16];
    const float* ln2_g   = (const float*)d_in[17];
    const float* ln2_b   = (const float*)d_in[18];
    const float* ff_w1   = (const float*)d_in[19];
    const float* ff_b1   = (const float*)d_in[20];
    const float* ff_w2   = (const float*)d_in[21];
    const float* ff_b2   = (const float*)d_in[22];
    float* out = (float*)d_out;

    const int CONV_SMEM  = (2 * 128 * 36 + 2 * 32 * 68) * 4;   // 54272
    const int FLASH_SMEM = 24576 * 4;                          // 98304 (2 blocks/SM: 192KB)
    cudaFuncSetAttribute(convgemm_kernel, cudaFuncAttributeMaxDynamicSharedMemorySize, CONV_SMEM);
    cudaFuncSetAttribute(flash_mma_kernel, cudaFuncAttributeMaxDynamicSharedMemorySize, FLASH_SMEM);

    fused_xin_kernel<<<dim3(4, 32), 256>>>(x, sq_w, bn_g, bn_b, dw_w, ex_w, pos_emb);
    prep_w_kernel<<<1792, 256>>>(wq, wk, wv, wl, uni_w);

    convgemm_kernel<<<dim3(32, 16, 2), 256, CONV_SMEM>>>(bq, bk);

    flash_mma_kernel<<<dim3(32, 8), 256, FLASH_SMEM>>>();
    local_attn_kernel<<<dim3(32, 16), 256>>>();

    unigemm_kernel<<<dim3(32, 4), 256>>>();

    ffln_kernel<<<256, 256>>>(uni_b, ln1_g, ln1_b, ln2_g, ln2_b,
                              ff_w1, ff_b1, ff_w2, ff_b2, out);
}

// round 10
// speedup vs baseline: 1.0120x; 1.0120x over previous
#include <cuda_runtime.h>
#include <math.h>
#include <stdint.h>

// Problem constants (fixed by setup_inputs)
#define BATCH 4
#define TLEN  1024
#define KD    64
#define HNUM  8
#define R32   32
#define NSEQ  32      // BATCH*HNUM
#define MROWS 4096    // BATCH*TLEN

// ---------------- scratch (static device globals; no allocation) --------------
__device__ float g_xin[BATCH * TLEN * KD];          // tf32-exact
__device__ float g_WB[320 * 1024];                  // tap-major reordered wq|wk, tf32-exact
__device__ float g_WB2[64 * 1024];                  // wv|wl transposed, tf32-exact
__device__ float g_WU[1024 * 64];                   // uni_w, tf32-exact
__device__ float g_q[NSEQ * TLEN * KD];             // [g][t][p64(d)] tf32-exact
__device__ float g_k[NSEQ * TLEN * KD];             // [g][t][p64(d)]
__device__ float g_v[NSEQ * KD * TLEN];             // [g][d][t: 64-tilewise pqk(nom64(key))]
__device__ float g_l[NSEQ * TLEN * KD];             // natural
__device__ float g_og[NSEQ * TLEN * KD];
__device__ float g_ol[NSEQ * TLEN * KD];
__device__ float g_part[8 * MROWS * KD];            // uni GEMM K-split partials (8-way)

__device__ __forceinline__ float sigmoid_exact(float x) { return 1.f / (1.f + expf(-x)); }
__device__ __forceinline__ float sigmoid_fast(float x) {
    float t;
    asm("tanh.approx.f32 %0, %1;" : "=f"(t) : "f"(0.5f * x));
    return 0.5f * t + 0.5f;
}
__device__ __forceinline__ float silu_fast(float x) { return x * sigmoid_fast(x); }

// round f32 -> nearest tf32 (result is a valid f32 with low mantissa zeroed)
__device__ __forceinline__ float tf32r(float x) {
    uint32_t u;
    asm("cvt.rna.tf32.f32 %0, %1;" : "=r"(u) : "f"(x));
    return __uint_as_float(u);
}

// fragment-vectorization permutation of a 64-long contraction dim
__device__ __forceinline__ int pqk(int k) {
    return ((k & 3) << 3) | ((k >> 5) << 5) | (((k >> 4) & 1) << 2) |
           (((k >> 3) & 1) << 1) | ((k >> 2) & 1);
}
// within-8 interleave so S C-fragments serve directly as PV A-fragments
__device__ __forceinline__ int nom64(int t) {
    return (t & 56) | ((t >> 1) & 3) | ((t & 1) << 2);
}

__device__ __forceinline__ void mma8(float* c,
                                     uint32_t a0, uint32_t a1, uint32_t a2, uint32_t a3,
                                     uint32_t b0, uint32_t b1) {
    asm volatile(
        "mma.sync.aligned.m16n8k8.row.col.f32.tf32.tf32.f32 "
        "{%0,%1,%2,%3}, {%4,%5,%6,%7}, {%8,%9}, {%0,%1,%2,%3};"
        : "+f"(c[0]), "+f"(c[1]), "+f"(c[2]), "+f"(c[3])
        : "r"(a0), "r"(a1), "r"(a2), "r"(a3), "r"(b0), "r"(b1));
}

__device__ __forceinline__ void cp16(uint32_t dst, const void* src) {
    asm volatile("cp.async.ca.shared.global [%0], [%1], 16;" :: "r"(dst), "l"(src) : "memory");
}
__device__ __forceinline__ void cp16p(uint32_t dst, const void* src, int sz) {
    asm volatile("cp.async.ca.shared.global [%0], [%1], 16, %2;" :: "r"(dst), "l"(src), "r"(sz) : "memory");
}
#define CPCOMMIT() asm volatile("cp.async.commit_group;" ::: "memory")
#define CPWAIT0()  asm volatile("cp.async.wait_group 0;" ::: "memory")
#define CPWAIT1()  asm volatile("cp.async.wait_group 1;" ::: "memory")
#define CPWAIT2()  asm volatile("cp.async.wait_group 2;" ::: "memory")

__device__ __forceinline__ void barg(int id) {
    asm volatile("bar.sync %0, 128;" :: "r"(id) : "memory");
}

// ================= fused action + pos_emb -> xin (tf32-exact) ==================
__global__ __launch_bounds__(256) void fused_xin_kernel(
    const float* __restrict__ x, const float* __restrict__ sq_w,
    const float* __restrict__ bn_g, const float* __restrict__ bn_b,
    const float* __restrict__ dw_w, const float* __restrict__ ex_w,
    const float* __restrict__ pos_emb)
{
    __shared__ float xs[34][68];
    __shared__ float x3s[34][36];
    __shared__ float xp3[32][32];
    __shared__ float sqT[64][32];
    __shared__ float exT[32][64];
    __shared__ float bng_s[32], bnb_s[32];

    int bi = blockIdx.x;
    int t0 = blockIdx.y * 32;
    int tid = threadIdx.x;
    int nrows = min(34, TLEN - t0);

    for (int i = tid; i < nrows * 16; i += 256) {
        int row = i >> 4, c4 = (i & 15) << 2;
        *(float4*)&xs[row][c4] = *(const float4*)&x[((size_t)bi * TLEN + t0 + row) * KD + c4];
    }
    for (int i = tid; i < 2048; i += 256) { int r = i >> 6, c = i & 63; sqT[c][r] = sq_w[i]; }
    for (int i = tid; i < 2048; i += 256) { int c = i >> 5, r = i & 31; exT[r][c] = ex_w[i]; }
    if (tid < 32) { bng_s[tid] = bn_g[tid] * 0.9999950000374997f; bnb_s[tid] = bn_b[tid]; }
    __syncthreads();

    {
        int j = tid >> 2, rg = (tid & 3) << 3;
        if (j < nrows) {
            float acc[8];
#pragma unroll
            for (int i = 0; i < 8; ++i) acc[i] = 0.f;
#pragma unroll
            for (int c4 = 0; c4 < 64; c4 += 4) {
                float4 xv = *(const float4*)&xs[j][c4];
#pragma unroll
                for (int t = 0; t < 4; ++t) {
                    float xc = (t == 0) ? xv.x : (t == 1) ? xv.y : (t == 2) ? xv.z : xv.w;
                    float4 s0 = *(const float4*)&sqT[c4 + t][rg];
                    float4 s1 = *(const float4*)&sqT[c4 + t][rg + 4];
                    acc[0] += xc * s0.x; acc[1] += xc * s0.y;
                    acc[2] += xc * s0.z; acc[3] += xc * s0.w;
                    acc[4] += xc * s1.x; acc[5] += xc * s1.y;
                    acc[6] += xc * s1.z; acc[7] += xc * s1.w;
                }
            }
#pragma unroll
            for (int i = 0; i < 8; ++i)
                x3s[j][rg + i] = acc[i] * bng_s[rg + i] + bnb_s[rg + i];
        }
    }
    __syncthreads();

    for (int idx = tid; idx < 32 * 32; idx += 256) {
        int r = idx & 31, jj = idx >> 5;
        int pos = t0 + jj;
        float base = x3s[jj][r];
        float v;
        if (pos == TLEN - 1) {
            v = base;
        } else {
            float d0 = dw_w[r * 3 + 0], d1 = dw_w[r * 3 + 1], d2 = dw_w[r * 3 + 2];
            float a = base * d0 + x3s[jj + 1][r] * d1 +
                      ((pos + 2 < TLEN) ? x3s[jj + 2][r] * d2 : 0.f);
            v = a - base;
        }
        xp3[jj][r] = v;
    }
    __syncthreads();

    for (int idx = tid; idx < 32 * 64; idx += 256) {
        int c = idx & 63, j = idx >> 6;
        int pos = t0 + j;
        float gsum = 0.f;
#pragma unroll
        for (int r = 0; r < R32; ++r) gsum += xp3[j][r] * exT[r][c];
        float sig = sigmoid_exact(gsum);
        size_t off = ((size_t)bi * TLEN + pos) * KD + c;
        g_xin[off] = tf32r(xs[j][c] * sig + pos_emb[pos * KD + c]);
    }
}

// ---------------- weight prep (split so convgemm lands at the profiled slot) ---
__global__ __launch_bounds__(256) void prep_wqk_kernel(
    const float* __restrict__ wq, const float* __restrict__ wk)
{
    int idx = blockIdx.x * 256 + threadIdx.x;
    if (idx >= 320 * 1024) return;
    int n = idx & 1023, kcol = idx >> 10;
    int mm = kcol >> 6, c = kcol & 63;
    float w = (n < 512) ? wq[n * 320 + c * 5 + mm] : wk[(n - 512) * 320 + c * 5 + mm];
    g_WB[idx] = tf32r(w);
}

__global__ __launch_bounds__(256) void prep_wvl_uni_kernel(
    const float* __restrict__ wv, const float* __restrict__ wl,
    const float* __restrict__ uni_w)
{
    int idx = blockIdx.x * 256 + threadIdx.x;
    if (idx < 65536) {
        int n = idx & 1023, c = idx >> 10;
        g_WB2[idx] = tf32r((n < 512) ? wv[n * 64 + c] : wl[(n - 512) * 64 + c]);
    } else if (idx < 131072) {
        int j = idx - 65536;
        g_WU[j] = tf32r(uni_w[j]);
    }
}

// ---------------- conv GEMMs (tf32 mma, cp.async dbl-buffered, mode=blockIdx.z) --
__global__ __launch_bounds__(256, 2) void convgemm_kernel(
    const float* __restrict__ bias0, const float* __restrict__ bias1)
{
    int mode = blockIdx.z;
    const int NSTAGE = (mode == 0) ? 10 : 2;
    extern __shared__ float sm[];
    float* As = sm;                   // [2][128][36]
    float* Bs = sm + 2 * 128 * 36;    // [2][32][68]
    const float* __restrict__ Bg = (mode == 0) ? g_WB : g_WB2;

    int tid = threadIdx.x, lane = tid & 31, wid = tid >> 5;
    int wm = wid & 3, wn = wid >> 2, gi = lane >> 2, ci = lane & 3;
    int m0 = blockIdx.x * 128, n0 = blockIdx.y * 64;
    int bi = m0 >> 10, tibase = m0 & 1023;
    uint32_t sb = (uint32_t)__cvta_generic_to_shared(sm);
    uint32_t a_sb = sb, b_sb = sb + 2 * 128 * 36 * 4;

    auto issue_stage = [&](int s_, int buf_) {
        int mm_ = (mode == 0) ? (s_ >> 1) : 0;
        int c0_ = (mode == 0) ? ((s_ & 1) << 5) : (s_ << 5);
        int sh_ = (mode == 0) ? (2 * mm_ - 8) : 0;
#pragma unroll
        for (int i_ = 0; i_ < 4; ++i_) {
            int f4 = tid + i_ * 256;
            int row = f4 >> 3, c4 = (f4 & 7) << 2;
            int tsrc = tibase + row + sh_;
            const float* srcp = g_xin + ((size_t)(bi << 10) + tsrc) * 64 + c0_ + c4;
            uint32_t dstp = a_sb + (uint32_t)((buf_ * 4608 + row * 36 + c4) * 4);
            cp16p(dstp, srcp, (tsrc >= 0) ? 16 : 0);
        }
#pragma unroll
        for (int i_ = 0; i_ < 2; ++i_) {
            int f4 = tid + i_ * 256;
            int row = f4 >> 4, c4 = (f4 & 15) << 2;
            const float* srcp = Bg + (size_t)(s_ * 32 + row) * 1024 + n0 + c4;
            uint32_t dstp = b_sb + (uint32_t)((buf_ * 2176 + row * 68 + c4) * 4);
            cp16(dstp, srcp);
        }
        CPCOMMIT();
    };

    float acc[2][4][4];
#pragma unroll
    for (int a = 0; a < 2; ++a)
#pragma unroll
        for (int b = 0; b < 4; ++b)
#pragma unroll
            for (int c = 0; c < 4; ++c) acc[a][b][c] = 0.f;

    issue_stage(0, 0);
    for (int s = 0; s < NSTAGE; ++s) {
        if (s + 1 < NSTAGE) { issue_stage(s + 1, (s + 1) & 1); CPWAIT1(); }
        else CPWAIT0();
        __syncthreads();
        const float* Ab = As + (s & 1) * 4608;
        const float* Bb = Bs + (s & 1) * 2176;
#pragma unroll
        for (int kk = 0; kk < 4; ++kk) {
            int k = kk * 8;
            uint32_t af[2][4];
#pragma unroll
            for (int mi = 0; mi < 2; ++mi) {
                int r = wm * 32 + mi * 16 + gi;
                af[mi][0] = __float_as_uint(Ab[r * 36 + k + ci]);
                af[mi][1] = __float_as_uint(Ab[(r + 8) * 36 + k + ci]);
                af[mi][2] = __float_as_uint(Ab[r * 36 + k + ci + 4]);
                af[mi][3] = __float_as_uint(Ab[(r + 8) * 36 + k + ci + 4]);
            }
            uint32_t bf[4][2];
#pragma unroll
            for (int ni = 0; ni < 4; ++ni) {
                int n = wn * 32 + ni * 8 + gi;
                bf[ni][0] = __float_as_uint(Bb[(k + ci) * 68 + n]);
                bf[ni][1] = __float_as_uint(Bb[(k + ci + 4) * 68 + n]);
            }
#pragma unroll
            for (int mi = 0; mi < 2; ++mi)
#pragma unroll
                for (int ni = 0; ni < 4; ++ni)
                    mma8(acc[mi][ni], af[mi][0], af[mi][1], af[mi][2], af[mi][3],
                         bf[ni][0], bf[ni][1]);
        }
        __syncthreads();
    }

#pragma unroll
    for (int mi = 0; mi < 2; ++mi)
#pragma unroll
        for (int ni = 0; ni < 4; ++ni)
#pragma unroll
            for (int j = 0; j < 4; ++j) {
                int m = m0 + wm * 32 + mi * 16 + gi + ((j >= 2) ? 8 : 0);
                int n = n0 + wn * 32 + ni * 8 + 2 * ci + (j & 1);
                float v = acc[mi][ni][j];
                int o = n & 511, ki = o >> 3, h = o & 7;
                int bb = m >> 10, ti = m & 1023;
                int gg = bb * 8 + (ti >> 7);
                int tj = ((ti & 127) << 3) | h;
                if (mode == 0) {
                    float bias = (n < 512) ? bias0[n] : bias1[n - 512];
                    float s = silu_fast(v + bias) * 0.35355339059327373f;  // / 64^0.25
                    float* dst = (n < 512) ? g_q : g_k;
                    dst[((size_t)gg * TLEN + tj) * KD + pqk(ki)] = tf32r(s);
                } else {
                    float s = silu_fast(v);
                    if (n < 512) {
                        g_v[((size_t)gg * KD + ki) * TLEN + (tj & ~63) + pqk(nom64(tj & 63))] = tf32r(s);
                    } else {
                        g_l[((size_t)gg * TLEN + tj) * KD + ki] = tf32r(s);
                    }
                }
            }
}

// ---------------- flash attention + local attention (merged launch) ------------
// grid (32, 12): p<8 = flash block (g, p); p>=8 = local-attention block over
// 256 queries [ (p-8)*256 .. ). Local blocks fill the slots flash leaves free
// (256 of 296) and backfill as flash blocks drain -> runs in flash's shadow.
__global__ __launch_bounds__(256, 2) void flash_mma_kernel()
{
    extern __shared__ float sm[];   // flash: A K[2][4096] V[4096] | B same @12288
    int g  = blockIdx.x;
    int p  = blockIdx.y;
    int tid = threadIdx.x, lane = tid & 31, wid = tid >> 5;

    if (p >= 8) {
        // ================= local windowed causal attention =================
        int t0 = (p - 8) * 256;
        const float* Lg = g_l + (size_t)g * (TLEN * KD);
        // tile rows t0-5 .. t0+255  (261 rows x 68 floats = 71KB)
        for (int i = tid; i < 261 * 16; i += 256) {
            int r = i >> 4, c4 = (i & 15) << 2;
            int tg = t0 - 5 + r;
            float4 v = make_float4(0.f, 0.f, 0.f, 0.f);
            if (tg >= 0) v = *(const float4*)&Lg[(size_t)tg * 64 + c4];
            *(float4*)&sm[r * 68 + c4] = v;
        }
        __syncthreads();
        int qq = tid >> 2, pi = tid & 3;
#pragma unroll
        for (int pass = 0; pass < 4; ++pass) {
            int q = pass * 64 + qq;       // 0..255 within tile
            int tj = t0 + q;
            const float* Lq = sm + (q + 5) * 68;
            float4 xq[4];
#pragma unroll
            for (int i = 0; i < 4; ++i)
                xq[i] = *(const float4*)&Lq[pi * 4 + i * 16];

            float sc[6], mx = -1e30f;
#pragma unroll
            for (int w = 0; w < 6; ++w) {
                const float* Lr = sm + (q + w) * 68;
                float d = 0.f;
#pragma unroll
                for (int i = 0; i < 4; ++i) {
                    float4 rv = *(const float4*)&Lr[pi * 4 + i * 16];
                    d += xq[i].x * rv.x + xq[i].y * rv.y + xq[i].z * rv.z + xq[i].w * rv.w;
                }
                d += __shfl_xor_sync(0xffffffffu, d, 1);
                d += __shfl_xor_sync(0xffffffffu, d, 2);
                sc[w] = (tj - 5 + w >= 0) ? d * 0.125f : -1e30f;   // / sqrt(64)
                mx = fmaxf(mx, sc[w]);
            }
            float e[6], den = 0.f;
#pragma unroll
            for (int w = 0; w < 6; ++w) { e[w] = __expf(sc[w] - mx); den += e[w]; }
            float inv = 1.f / den;

            float4 acc[4];
#pragma unroll
            for (int i = 0; i < 4; ++i) acc[i] = make_float4(0.f, 0.f, 0.f, 0.f);
#pragma unroll
            for (int w = 0; w < 6; ++w) {
                float ew = e[w];
                const float* Lr = sm + (q + w) * 68;
#pragma unroll
                for (int i = 0; i < 4; ++i) {
                    float4 rv = *(const float4*)&Lr[pi * 4 + i * 16];
                    acc[i].x += ew * rv.x; acc[i].y += ew * rv.y;
                    acc[i].z += ew * rv.z; acc[i].w += ew * rv.w;
                }
            }
            float* Og = g_ol + (size_t)g * (TLEN * KD) + (size_t)tj * 64;
#pragma unroll
            for (int i = 0; i < 4; ++i) {
                float4 t;
                t.x = acc[i].x * inv; t.y = acc[i].y * inv;
                t.z = acc[i].z * inv; t.w = acc[i].w * inv;
                *(float4*)&Og[pi * 4 + i * 16] = t;
            }
        }
        return;
    }

    // ========================= flash attention (v5) =========================
    int qa = p, qb = 15 - p;
    int gi = lane >> 2, ci = lane & 3;
    int wa = wid & 3;
    bool grpB = wid >= 4;
    int barid = grpB ? 2 : 1;
    int Na = p + 1;
    int NIT = grpB ? 9 : 8;
    uint32_t sb = (uint32_t)__cvta_generic_to_shared(sm);
    int KO = grpB ? 12288 : 0;
    int VO = KO + 8192;
    int lt = wa * 32 + lane;

    int offw[4];
#pragma unroll
    for (int t4 = 0; t4 < 4; ++t4)
        offw[t4] = (((2 * ci + (t4 & 1) + ((t4 >> 1) << 3)) ^ gi) << 2);

    const float* Qg  = g_q + (size_t)g * (TLEN * KD);
    const float* Kg0 = g_k + (size_t)g * (TLEN * KD);
    const float* Vg0 = g_v + (size_t)g * (KD * TLEN);

    int qt = grpB ? qb : qa;
    int qbase = qt * 64 + wa * 16;
    int r0 = qbase + gi;

    uint32_t qf[8][4];
    auto load_qf = [&]() {
#pragma unroll
        for (int t4 = 0; t4 < 4; ++t4) {
            int woff = (2 * ci + (t4 & 1) + ((t4 >> 1) << 3)) << 2;
            float4 lo = *(const float4*)&Qg[(size_t)r0 * KD + woff];
            float4 hi = *(const float4*)&Qg[(size_t)(r0 + 8) * KD + woff];
            int kk0 = ((t4 >> 1) << 2) + ((t4 & 1) << 1);
            qf[kk0][0]     = __float_as_uint(lo.x); qf[kk0][2]     = __float_as_uint(lo.y);
            qf[kk0 + 1][0] = __float_as_uint(lo.z); qf[kk0 + 1][2] = __float_as_uint(lo.w);
            qf[kk0][1]     = __float_as_uint(hi.x); qf[kk0][3]     = __float_as_uint(hi.y);
            qf[kk0 + 1][1] = __float_as_uint(hi.z); qf[kk0 + 1][3] = __float_as_uint(hi.w);
        }
    };
    load_qf();

    float o[8][4];
#pragma unroll
    for (int a = 0; a < 8; ++a)
#pragma unroll
        for (int b = 0; b < 4; ++b) o[a][b] = 0.f;
    float m0v = -1e30f, m1v = -1e30f, l0 = 0.f, l1 = 0.f;

    auto kt_of = [&](int i) {
        if (grpB) return i;
        return (i < Na) ? i : (9 + i - Na);
    };

    auto issueK = [&](int i, int buf) {
        int k0 = kt_of(i) * 64;
#pragma unroll
        for (int j = 0; j < 8; ++j) {
            int f4 = lt + j * 128;
            int row = f4 >> 4, chunk = f4 & 15;
            int swc = chunk ^ (row & 7);
            cp16(sb + (uint32_t)((KO + buf * 4096 + row * 64 + swc * 4) * 4),
                 Kg0 + (size_t)(k0 + row) * 64 + chunk * 4);
        }
        CPCOMMIT();
    };
    auto issueV = [&](int i) {
        int k0 = kt_of(i) * 64;
#pragma unroll
        for (int j = 0; j < 8; ++j) {
            int f4 = lt + j * 128;
            int row = f4 >> 4, chunk = f4 & 15;
            int swc = chunk ^ (row & 7);
            cp16(sb + (uint32_t)((VO + row * 64 + swc * 4) * 4),
                 Vg0 + (size_t)row * TLEN + k0 + chunk * 4);
        }
        CPCOMMIT();
    };

    auto epilogue_store = [&]() {
        float inv0 = 1.f / l0, inv1 = 1.f / l1;
        float* Og = g_og + (size_t)g * (TLEN * KD);
#pragma unroll
        for (int nd = 0; nd < 8; ++nd) {
            int c = nd * 8 + 2 * ci;
            float2 t0; t0.x = o[nd][0] * inv0; t0.y = o[nd][1] * inv0;
            float2 t1; t1.x = o[nd][2] * inv1; t1.y = o[nd][3] * inv1;
            *(float2*)&Og[(size_t)r0 * KD + c] = t0;
            *(float2*)&Og[(size_t)(r0 + 8) * KD + c] = t1;
        }
    };
    auto reset_state = [&]() {
#pragma unroll
        for (int a = 0; a < 8; ++a)
#pragma unroll
            for (int b = 0; b < 4; ++b) o[a][b] = 0.f;
        m0v = -1e30f; m1v = -1e30f; l0 = 0.f; l1 = 0.f;
    };

    issueK(0, 0);
    for (int i = 0; i < NIT; ++i) {
        if (!grpB && i == Na) {
            epilogue_store();
            reset_state();
            qt = qb; qbase = qt * 64 + wa * 16; r0 = qbase + gi;
            load_qf();
        }
        bool more = (i + 1 < NIT);
        issueV(i);
        if (more) issueK(i + 1, (i + 1) & 1);
        if (more) CPWAIT2(); else CPWAIT1();    // K(i) ready
        barg(barid);

        int k0 = kt_of(i) * 64;
        const float* Ks = sm + KO + (i & 1) * 4096;
        const float* Vs = sm + VO;

        float s[8][4];
#pragma unroll
        for (int ni = 0; ni < 8; ++ni) {
            s[ni][0] = s[ni][1] = s[ni][2] = s[ni][3] = 0.f;
            const uint32_t* Krow = (const uint32_t*)(Ks + (ni * 8 + gi) * 64);
#pragma unroll
            for (int t4 = 0; t4 < 4; ++t4) {
                uint4 F = *(const uint4*)(Krow + offw[t4]);
                int kk0 = ((t4 >> 1) << 2) + ((t4 & 1) << 1);
                mma8(s[ni], qf[kk0][0], qf[kk0][1], qf[kk0][2], qf[kk0][3], F.x, F.y);
                mma8(s[ni], qf[kk0 + 1][0], qf[kk0 + 1][1], qf[kk0 + 1][2], qf[kk0 + 1][3], F.z, F.w);
            }
        }
        if (k0 + 63 > qbase) {   // diagonal tile: causal mask
#pragma unroll
            for (int ni = 0; ni < 8; ++ni)
#pragma unroll
                for (int j = 0; j < 4; ++j) {
                    int col = k0 + ni * 8 + 2 * ci + (j & 1);
                    int row = r0 + ((j >= 2) ? 8 : 0);
                    if (col > row) s[ni][j] = -1e30f;
                }
        }
        float mx0 = -1e30f, mx1 = -1e30f;
#pragma unroll
        for (int ni = 0; ni < 8; ++ni) {
            mx0 = fmaxf(mx0, fmaxf(s[ni][0], s[ni][1]));
            mx1 = fmaxf(mx1, fmaxf(s[ni][2], s[ni][3]));
        }
        mx0 = fmaxf(mx0, __shfl_xor_sync(0xffffffffu, mx0, 1));
        mx0 = fmaxf(mx0, __shfl_xor_sync(0xffffffffu, mx0, 2));
        mx1 = fmaxf(mx1, __shfl_xor_sync(0xffffffffu, mx1, 1));
        mx1 = fmaxf(mx1, __shfl_xor_sync(0xffffffffu, mx1, 2));
        float m0n = fmaxf(m0v, mx0), m1n = fmaxf(m1v, mx1);
        float corr0 = __expf(m0v - m0n), corr1 = __expf(m1v - m1n);

        float sum0 = 0.f, sum1 = 0.f;
#pragma unroll
        for (int ni = 0; ni < 8; ++ni) {
            s[ni][0] = tf32r(__expf(s[ni][0] - m0n));
            s[ni][1] = tf32r(__expf(s[ni][1] - m0n));
            s[ni][2] = tf32r(__expf(s[ni][2] - m1n));
            s[ni][3] = tf32r(__expf(s[ni][3] - m1n));
            sum0 += s[ni][0] + s[ni][1];
            sum1 += s[ni][2] + s[ni][3];
        }
        sum0 += __shfl_xor_sync(0xffffffffu, sum0, 1);
        sum0 += __shfl_xor_sync(0xffffffffu, sum0, 2);
        sum1 += __shfl_xor_sync(0xffffffffu, sum1, 1);
        sum1 += __shfl_xor_sync(0xffffffffu, sum1, 2);
        l0 = l0 * corr0 + sum0;
        l1 = l1 * corr1 + sum1;
        m0v = m0n; m1v = m1n;
#pragma unroll
        for (int nd = 0; nd < 8; ++nd) {
            o[nd][0] *= corr0; o[nd][1] *= corr0;
            o[nd][2] *= corr1; o[nd][3] *= corr1;
        }
        if (more) CPWAIT1(); else CPWAIT0();    // V(i) ready
        barg(barid);
        // P @ V : S C-frags ARE the A-frags (a0=c0,a1=c2,a2=c1,a3=c3)
#pragma unroll
        for (int nd = 0; nd < 8; ++nd) {
            const uint32_t* Vrow = (const uint32_t*)(Vs + (nd * 8 + gi) * 64);
#pragma unroll
            for (int t4 = 0; t4 < 4; ++t4) {
                uint4 F = *(const uint4*)(Vrow + offw[t4]);
                int kg0 = ((t4 >> 1) << 2) + ((t4 & 1) << 1);
                mma8(o[nd], __float_as_uint(s[kg0][0]), __float_as_uint(s[kg0][2]),
                     __float_as_uint(s[kg0][1]), __float_as_uint(s[kg0][3]), F.x, F.y);
                mma8(o[nd], __float_as_uint(s[kg0 + 1][0]), __float_as_uint(s[kg0 + 1][2]),
                     __float_as_uint(s[kg0 + 1][1]), __float_as_uint(s[kg0 + 1][3]), F.z, F.w);
            }
        }
        barg(barid);   // protect V buffer before next issues
    }

    if (!grpB && Na == NIT) {    // p==7: finalize qa, empty qb partial
        epilogue_store();
        reset_state();
        qt = qb; qbase = qt * 64 + wa * 16; r0 = qbase + gi;
    }

    // ---- split-KV merge for q-tile qb
    float* ob = sm + 12288;
    float* mb = sm + 12288 + 4352;
    float* lb = mb + 64;
    if (grpB) {
        int rr = wa * 16 + gi;
#pragma unroll
        for (int nd = 0; nd < 8; ++nd) {
            int c = nd * 8 + 2 * ci;
            *(float2*)&ob[rr * 68 + c]       = make_float2(o[nd][0], o[nd][1]);
            *(float2*)&ob[(rr + 8) * 68 + c] = make_float2(o[nd][2], o[nd][3]);
        }
        if (ci == 0) {
            mb[rr] = m0v; lb[rr] = l0;
            mb[rr + 8] = m1v; lb[rr + 8] = l1;
        }
    }
    __syncthreads();
    if (!grpB) {
        int rr = wa * 16 + gi;
        float mB0 = mb[rr], lB0 = lb[rr], mB1 = mb[rr + 8], lB1 = lb[rr + 8];
        float mS0 = fmaxf(m0v, mB0), mS1 = fmaxf(m1v, mB1);
        float cA0 = __expf(m0v - mS0), cB0 = __expf(mB0 - mS0);
        float cA1 = __expf(m1v - mS1), cB1 = __expf(mB1 - mS1);
        l0 = l0 * cA0 + lB0 * cB0;
        l1 = l1 * cA1 + lB1 * cB1;
#pragma unroll
        for (int nd = 0; nd < 8; ++nd) {
            int c = nd * 8 + 2 * ci;
            float2 b0 = *(float2*)&ob[rr * 68 + c];
            float2 b1 = *(float2*)&ob[(rr + 8) * 68 + c];
            o[nd][0] = o[nd][0] * cA0 + b0.x * cB0;
            o[nd][1] = o[nd][1] * cA0 + b0.y * cB0;
            o[nd][2] = o[nd][2] * cA1 + b1.x * cB1;
            o[nd][3] = o[nd][3] * cA1 + b1.y * cB1;
        }
        epilogue_store();
    }
}

// ---------------- uni projection: fused gating + K-split(8) tf32 GEMM ----------
__global__ __launch_bounds__(256, 2) void unigemm_kernel()
{
    __shared__ float As[128][36];
    __shared__ float Bs[32][68];
    int tid = threadIdx.x, lane = tid & 31, wid = tid >> 5;
    int wm = wid & 3, wn = wid >> 2, gi = lane >> 2, ci = lane & 3;
    int m0 = blockIdx.x * 128;
    int kz = blockIdx.y;                 // 0..7
    int bi = m0 >> 10, tib = m0 & 1023;
    uint32_t b_sb = (uint32_t)__cvta_generic_to_shared(&Bs[0][0]);

    float acc[2][4][4];
#pragma unroll
    for (int a = 0; a < 2; ++a)
#pragma unroll
        for (int b = 0; b < 4; ++b)
#pragma unroll
            for (int c = 0; c < 4; ++c) acc[a][b][c] = 0.f;

    for (int s = 0; s < 4; ++s) {
        int k0 = kz * 128 + s * 32;
        int ch = k0 >> 6, ki0 = k0 & 63;
        int h2 = ch & 7;
        bool lohalf = ch < 8;
        const float* Og = g_og + (size_t)(bi * 8 + h2) * (TLEN * KD);
        const float* Lg = g_ol + (size_t)(bi * 8 + h2) * (TLEN * KD);
        __syncthreads();
#pragma unroll
        for (int i = 0; i < 2; ++i) {
            int f4 = tid + i * 256;
            int row = f4 >> 4, c4 = (f4 & 15) << 2;
            cp16(b_sb + (uint32_t)((row * 68 + c4) * 4), g_WU + (size_t)(k0 + row) * 64 + c4);
        }
        CPCOMMIT();
#pragma unroll
        for (int i = 0; i < 4; ++i) {
            int f4 = tid + i * 256;
            int row = f4 >> 3, c4 = (f4 & 7) << 2;
            int ti2 = tib + row;
            const float4 o4 = *(const float4*)(Og + (size_t)ti2 * 64 + ki0 + c4);
            const float4 l4 = *(const float4*)(Lg + (size_t)ti2 * 64 + ki0 + c4);
            float g0 = sigmoid_fast(o4.x), g1 = sigmoid_fast(o4.y);
            float g2 = sigmoid_fast(o4.z), g3 = sigmoid_fast(o4.w);
            float r0 = lohalf ? (1.f - g0) * l4.x : g0 * o4.x;
            float r1 = lohalf ? (1.f - g1) * l4.y : g1 * o4.y;
            float r2 = lohalf ? (1.f - g2) * l4.z : g2 * o4.z;
            float r3 = lohalf ? (1.f - g3) * l4.w : g3 * o4.w;
            As[row][c4 + 0] = tf32r(r0);
            As[row][c4 + 1] = tf32r(r1);
            As[row][c4 + 2] = tf32r(r2);
            As[row][c4 + 3] = tf32r(r3);
        }
        CPWAIT0();
        __syncthreads();
#pragma unroll
        for (int kk = 0; kk < 4; ++kk) {
            int k = kk * 8;
            uint32_t af[2][4];
#pragma unroll
            for (int mi = 0; mi < 2; ++mi) {
                int r = wm * 32 + mi * 16 + gi;
                af[mi][0] = __float_as_uint(As[r][k + ci]);
                af[mi][1] = __float_as_uint(As[r + 8][k + ci]);
                af[mi][2] = __float_as_uint(As[r][k + ci + 4]);
                af[mi][3] = __float_as_uint(As[r + 8][k + ci + 4]);
            }
            uint32_t bf[4][2];
#pragma unroll
            for (int ni = 0; ni < 4; ++ni) {
                int n = wn * 32 + ni * 8 + gi;
                bf[ni][0] = __float_as_uint(Bs[k + ci][n]);
                bf[ni][1] = __float_as_uint(Bs[k + ci + 4][n]);
            }
#pragma unroll
            for (int mi = 0; mi < 2; ++mi)
#pragma unroll
                for (int ni = 0; ni < 4; ++ni)
                    mma8(acc[mi][ni], af[mi][0], af[mi][1], af[mi][2], af[mi][3],
                         bf[ni][0], bf[ni][1]);
        }
    }

    float* P = g_part + ((size_t)kz * MROWS + m0) * 64;
#pragma unroll
    for (int mi = 0; mi < 2; ++mi)
#pragma unroll
        for (int ni = 0; ni < 4; ++ni)
#pragma unroll
            for (int j = 0; j < 4; j += 2) {
                int mrow = wm * 32 + mi * 16 + gi + ((j >= 2) ? 8 : 0);
                int n = wn * 32 + ni * 8 + 2 * ci;
                float2 t; t.x = acc[mi][ni][j]; t.y = acc[mi][ni][j + 1];
                *(float2*)&P[(size_t)mrow * 64 + n] = t;
            }
}

// ---------------- partial-reduce(8) + silu + residual -> LN1 -> FF -> LN2 ------
__global__ __launch_bounds__(256) void ffln_kernel(
    const float* __restrict__ uni_b,
    const float* __restrict__ ln1g, const float* __restrict__ ln1b,
    const float* __restrict__ ln2g, const float* __restrict__ ln2b,
    const float* __restrict__ w1, const float* __restrict__ b1,
    const float* __restrict__ w2, const float* __restrict__ b2,
    float* __restrict__ out)
{
    const int R = 16;
    __shared__ float yl[R][64];
    __shared__ float hs[R][256];
    __shared__ float fs[R][64];
    int r0 = blockIdx.x * R;
    int tid = threadIdx.x;
    int lane = tid & 31, w = tid >> 5;

    for (int rr = 0; rr < 2; ++rr) {
        int r = w * 2 + rr;
        size_t rg = (size_t)(r0 + r) * 64;
        float v0 = 0.f, v1 = 0.f;
#pragma unroll
        for (int kz = 0; kz < 8; ++kz) {
            v0 += g_part[(size_t)kz * MROWS * 64 + rg + lane];
            v1 += g_part[(size_t)kz * MROWS * 64 + rg + lane + 32];
        }
        v0 = silu_fast(v0 + uni_b[lane]) + g_xin[rg + lane];
        v1 = silu_fast(v1 + uni_b[lane + 32]) + g_xin[rg + lane + 32];
        float sm = v0 + v1;
#pragma unroll
        for (int o = 16; o; o >>= 1) sm += __shfl_xor_sync(0xffffffffu, sm, o);
        float mean = sm * (1.f / 64.f);
        float d0 = v0 - mean, d1 = v1 - mean;
        float vs = d0 * d0 + d1 * d1;
#pragma unroll
        for (int o = 16; o; o >>= 1) vs += __shfl_xor_sync(0xffffffffu, vs, o);
        float inv = rsqrtf(vs * (1.f / 64.f) + 1e-5f);
        yl[r][lane]      = d0 * inv * ln1g[lane] + ln1b[lane];
        yl[r][lane + 32] = d1 * inv * ln1g[lane + 32] + ln1b[lane + 32];
    }
    __syncthreads();

    {
        float acc[R];
#pragma unroll
        for (int r = 0; r < R; ++r) acc[r] = b1[tid];
        for (int c = 0; c < 64; ++c) {
            float wv = w1[c * 256 + tid];
#pragma unroll
            for (int r = 0; r < R; ++r) acc[r] += yl[r][c] * wv;
        }
#pragma unroll
        for (int r = 0; r < R; ++r) hs[r][tid] = fmaxf(acc[r], 0.f);
    }
    __syncthreads();

    {
        int j2 = tid & 63, rg = tid >> 6;
        float acc[4];
#pragma unroll
        for (int rr = 0; rr < 4; ++rr) acc[rr] = b2[j2];
        for (int c = 0; c < 256; ++c) {
            float wv = w2[c * 64 + j2];
#pragma unroll
            for (int rr = 0; rr < 4; ++rr) acc[rr] += hs[rg * 4 + rr][c] * wv;
        }
#pragma unroll
        for (int rr = 0; rr < 4; ++rr) fs[rg * 4 + rr][j2] = acc[rr] + yl[rg * 4 + rr][j2];
    }
    __syncthreads();

    for (int rr = 0; rr < 2; ++rr) {
        int r = w * 2 + rr;
        float v0 = fs[r][lane], v1 = fs[r][lane + 32];
        float sm = v0 + v1;
#pragma unroll
        for (int o = 16; o; o >>= 1) sm += __shfl_xor_sync(0xffffffffu, sm, o);
        float mean = sm * (1.f / 64.f);
        float d0 = v0 - mean, d1 = v1 - mean;
        float vs = d0 * d0 + d1 * d1;
#pragma unroll
        for (int o = 16; o; o >>= 1) vs += __shfl_xor_sync(0xffffffffu, vs, o);
        float inv = rsqrtf(vs * (1.f / 64.f) + 1e-5f);
        float* orow = out + (size_t)(r0 + r) * 64;
        orow[lane]      = d0 * inv * ln2g[lane] + ln2b[lane];
        orow[lane + 32] = d1 * inv * ln2g[lane + 32] + ln2b[lane + 32];
    }
}

// ---------------- launch ---------------------------------------------------------
extern "C" void kernel_launch(void* const* d_in, const int* in_sizes, int n_in,
                              void* d_out, int out_size)
{
    (void)in_sizes; (void)n_in; (void)out_size;
    const float* x       = (const float*)d_in[0];
    const float* sq_w    = (const float*)d_in[1];
    const float* bn_g    = (const float*)d_in[2];
    const float* bn_b    = (const float*)d_in[3];
    const float* dw_w    = (const float*)d_in[4];
    const float* ex_w    = (const float*)d_in[5];
    const float* pos_emb = (const float*)d_in[6];
    const float* wq      = (const float*)d_in[7];
    const float* bq      = (const float*)d_in[8];
    const float* wk      = (const float*)d_in[9];
    const float* bk      = (const float*)d_in[10];
    const float* wv      = (const float*)d_in[11];
    const float* wl      = (const float*)d_in[12];
    const float* uni_w   = (const float*)d_in[13];
    const float* uni_b   = (const float*)d_in[14];
    const float* ln1_g   = (const float*)d_in[15];
    const float* ln1_b   = (const float*)d_in[16];
    const float* ln2_g   = (const float*)d_in[17];
    const float* ln2_b   = (const float*)d_in[18];
    const float* ff_w1   = (const float*)d_in[19];
    const float* ff_b1   = (const float*)d_in[20];
    const float* ff_w2   = (const float*)d_in[21];
    const float* ff_b2   = (const float*)d_in[22];
    float* out = (float*)d_out;

    const int CONV_SMEM  = (2 * 128 * 36 + 2 * 32 * 68) * 4;   // 54272
    const int FLASH_SMEM = 24576 * 4;                          // 98304 (2 blocks/SM)
    cudaFuncSetAttribute(convgemm_kernel, cudaFuncAttributeMaxDynamicSharedMemorySize, CONV_SMEM);
    cudaFuncSetAttribute(flash_mma_kernel, cudaFuncAttributeMaxDynamicSharedMemorySize, FLASH_SMEM);

    fused_xin_kernel<<<dim3(4, 32), 256>>>(x, sq_w, bn_g, bn_b, dw_w, ex_w, pos_emb);
    prep_wqk_kernel<<<1280, 256>>>(wq, wk);
    prep_wvl_uni_kernel<<<512, 256>>>(wv, wl, uni_w);

    convgemm_kernel<<<dim3(32, 16, 2), 256, CONV_SMEM>>>(bq, bk);   // profiled slot

    flash_mma_kernel<<<dim3(32, 12), 256, FLASH_SMEM>>>();          // flash + local

    unigemm_kernel<<<dim3(32, 8), 256>>>();

    ffln_kernel<<<256, 256>>>(uni_b, ln1_g, ln1_b, ln2_g, ln2_b,
                              ff_w1, ff_b1, ff_w2, ff_b2, out);
}

// round 11
// speedup vs baseline: 1.0537x; 1.0413x over previous
#include <cuda_runtime.h>
#include <math.h>
#include <stdint.h>

// Problem constants (fixed by setup_inputs)
#define BATCH 4
#define TLEN  1024
#define KD    64
#define HNUM  8
#define R32   32
#define NSEQ  32      // BATCH*HNUM
#define MROWS 4096    // BATCH*TLEN

// ---------------- scratch (static device globals; no allocation) --------------
__device__ float g_xin[BATCH * TLEN * KD];          // [b][t][ (c&32)|p32(c&31) ] tf32-exact
__device__ float g_WB[1024 * 320];                  // [n][kcol: per-32 p32] wq|wk, tf32-exact
__device__ float g_WB2[1024 * 64];                  // [n][c: per-32 p32] wv|wl, tf32-exact
__device__ float g_WU[1024 * 64];                   // uni_w, tf32-exact
__device__ float g_q[NSEQ * TLEN * KD];             // [g][t][pqk(d)] tf32-exact
__device__ float g_k[NSEQ * TLEN * KD];             // [g][t][pqk(d)]
__device__ float g_v[NSEQ * KD * TLEN];             // [g][d][t: 64-tilewise pqk(nom64(key))]
__device__ float g_l[NSEQ * TLEN * KD];             // natural
__device__ float g_og[NSEQ * TLEN * KD];
__device__ float g_ol[NSEQ * TLEN * KD];
__device__ float g_part[8 * MROWS * KD];            // uni GEMM K-split partials (8-way)

__device__ __forceinline__ float sigmoid_exact(float x) { return 1.f / (1.f + expf(-x)); }
__device__ __forceinline__ float sigmoid_fast(float x) {
    float t;
    asm("tanh.approx.f32 %0, %1;" : "=f"(t) : "f"(0.5f * x));
    return 0.5f * t + 0.5f;
}
__device__ __forceinline__ float silu_fast(float x) { return x * sigmoid_fast(x); }

// round f32 -> nearest tf32 (result is a valid f32 with low mantissa zeroed)
__device__ __forceinline__ float tf32r(float x) {
    uint32_t u;
    asm("cvt.rna.tf32.f32 %0, %1;" : "=r"(u) : "f"(x));
    return __uint_as_float(u);
}

// fragment-vectorization permutation of a 64-long contraction dim (flash Q/K/V)
__device__ __forceinline__ int pqk(int k) {
    return ((k & 3) << 3) | ((k >> 5) << 5) | (((k >> 4) & 1) << 2) |
           (((k >> 3) & 1) << 1) | ((k >> 2) & 1);
}
// within-8 interleave so S C-fragments serve directly as PV A-fragments
__device__ __forceinline__ int nom64(int t) {
    return (t & 56) | ((t >> 1) & 3) | ((t & 1) << 2);
}
// 32-wide contraction permutation: slot kappa=8*kg+ci+4*v (kg=2u+w)
//   -> word ci<<3 | u<<2 | w<<1 | v  (thread ci's 8 slots = chunks 2ci,2ci+1)
__device__ __forceinline__ int p32(int t) {
    return ((t & 3) << 3) | (((t >> 4) & 1) << 2) | (((t >> 3) & 1) << 1) | ((t >> 2) & 1);
}

__device__ __forceinline__ void mma8(float* c,
                                     uint32_t a0, uint32_t a1, uint32_t a2, uint32_t a3,
                                     uint32_t b0, uint32_t b1) {
    asm volatile(
        "mma.sync.aligned.m16n8k8.row.col.f32.tf32.tf32.f32 "
        "{%0,%1,%2,%3}, {%4,%5,%6,%7}, {%8,%9}, {%0,%1,%2,%3};"
        : "+f"(c[0]), "+f"(c[1]), "+f"(c[2]), "+f"(c[3])
        : "r"(a0), "r"(a1), "r"(a2), "r"(a3), "r"(b0), "r"(b1));
}

__device__ __forceinline__ void cp16(uint32_t dst, const void* src) {
    asm volatile("cp.async.ca.shared.global [%0], [%1], 16;" :: "r"(dst), "l"(src) : "memory");
}
__device__ __forceinline__ void cp16p(uint32_t dst, const void* src, int sz) {
    asm volatile("cp.async.ca.shared.global [%0], [%1], 16, %2;" :: "r"(dst), "l"(src), "r"(sz) : "memory");
}
#define CPCOMMIT() asm volatile("cp.async.commit_group;" ::: "memory")
#define CPWAIT0()  asm volatile("cp.async.wait_group 0;" ::: "memory")
#define CPWAIT1()  asm volatile("cp.async.wait_group 1;" ::: "memory")
#define CPWAIT2()  asm volatile("cp.async.wait_group 2;" ::: "memory")

__device__ __forceinline__ void barg(int id) {
    asm volatile("bar.sync %0, 128;" :: "r"(id) : "memory");
}

// ================= fused action + pos_emb -> xin (p32-permuted, tf32-exact) ====
__global__ __launch_bounds__(256) void fused_xin_kernel(
    const float* __restrict__ x, const float* __restrict__ sq_w,
    const float* __restrict__ bn_g, const float* __restrict__ bn_b,
    const float* __restrict__ dw_w, const float* __restrict__ ex_w,
    const float* __restrict__ pos_emb)
{
    __shared__ float xs[34][68];
    __shared__ float x3s[34][36];
    __shared__ float xp3[32][32];
    __shared__ float sqT[64][32];
    __shared__ float exT[32][64];
    __shared__ float bng_s[32], bnb_s[32];

    int bi = blockIdx.x;
    int t0 = blockIdx.y * 32;
    int tid = threadIdx.x;
    int nrows = min(34, TLEN - t0);

    for (int i = tid; i < nrows * 16; i += 256) {
        int row = i >> 4, c4 = (i & 15) << 2;
        *(float4*)&xs[row][c4] = *(const float4*)&x[((size_t)bi * TLEN + t0 + row) * KD + c4];
    }
    for (int i = tid; i < 2048; i += 256) { int r = i >> 6, c = i & 63; sqT[c][r] = sq_w[i]; }
    for (int i = tid; i < 2048; i += 256) { int c = i >> 5, r = i & 31; exT[r][c] = ex_w[i]; }
    if (tid < 32) { bng_s[tid] = bn_g[tid] * 0.9999950000374997f; bnb_s[tid] = bn_b[tid]; }
    __syncthreads();

    {
        int j = tid >> 2, rg = (tid & 3) << 3;
        if (j < nrows) {
            float acc[8];
#pragma unroll
            for (int i = 0; i < 8; ++i) acc[i] = 0.f;
#pragma unroll
            for (int c4 = 0; c4 < 64; c4 += 4) {
                float4 xv = *(const float4*)&xs[j][c4];
#pragma unroll
                for (int t = 0; t < 4; ++t) {
                    float xc = (t == 0) ? xv.x : (t == 1) ? xv.y : (t == 2) ? xv.z : xv.w;
                    float4 s0 = *(const float4*)&sqT[c4 + t][rg];
                    float4 s1 = *(const float4*)&sqT[c4 + t][rg + 4];
                    acc[0] += xc * s0.x; acc[1] += xc * s0.y;
                    acc[2] += xc * s0.z; acc[3] += xc * s0.w;
                    acc[4] += xc * s1.x; acc[5] += xc * s1.y;
                    acc[6] += xc * s1.z; acc[7] += xc * s1.w;
                }
            }
#pragma unroll
            for (int i = 0; i < 8; ++i)
                x3s[j][rg + i] = acc[i] * bng_s[rg + i] + bnb_s[rg + i];
        }
    }
    __syncthreads();

    for (int idx = tid; idx < 32 * 32; idx += 256) {
        int r = idx & 31, jj = idx >> 5;
        int pos = t0 + jj;
        float base = x3s[jj][r];
        float v;
        if (pos == TLEN - 1) {
            v = base;
        } else {
            float d0 = dw_w[r * 3 + 0], d1 = dw_w[r * 3 + 1], d2 = dw_w[r * 3 + 2];
            float a = base * d0 + x3s[jj + 1][r] * d1 +
                      ((pos + 2 < TLEN) ? x3s[jj + 2][r] * d2 : 0.f);
            v = a - base;
        }
        xp3[jj][r] = v;
    }
    __syncthreads();

    for (int idx = tid; idx < 32 * 64; idx += 256) {
        int c = idx & 63, j = idx >> 6;
        int pos = t0 + j;
        float gsum = 0.f;
#pragma unroll
        for (int r = 0; r < R32; ++r) gsum += xp3[j][r] * exT[r][c];
        float sig = sigmoid_exact(gsum);
        size_t off = ((size_t)bi * TLEN + pos) * KD + ((c & 32) | p32(c & 31));
        g_xin[off] = tf32r(xs[j][c] * sig + pos_emb[pos * KD + c]);
    }
}

// ---------------- weight prep ([n][K] layout, per-32 p32 permuted) ------------
__global__ __launch_bounds__(256) void prep_wqk_kernel(
    const float* __restrict__ wq, const float* __restrict__ wk)
{
    int idx = blockIdx.x * 256 + threadIdx.x;
    if (idx >= 320 * 1024) return;
    int n = idx & 1023, kcol = idx >> 10;      // kcol tap-major: mm*64 + c
    int mm = kcol >> 6, c = kcol & 63;
    float w = (n < 512) ? wq[n * 320 + c * 5 + mm] : wk[(n - 512) * 320 + c * 5 + mm];
    g_WB[(size_t)n * 320 + (kcol & ~31) + p32(kcol & 31)] = tf32r(w);
}

__global__ __launch_bounds__(256) void prep_wvl_uni_kernel(
    const float* __restrict__ wv, const float* __restrict__ wl,
    const float* __restrict__ uni_w)
{
    int idx = blockIdx.x * 256 + threadIdx.x;
    if (idx < 65536) {
        int n = idx & 1023, c = idx >> 10;
        float w = (n < 512) ? wv[n * 64 + c] : wl[(n - 512) * 64 + c];
        g_WB2[(size_t)n * 64 + (c & 32) + p32(c & 31)] = tf32r(w);
    } else if (idx < 131072) {
        int j = idx - 65536;
        g_WU[j] = tf32r(uni_w[j]);
    }
}

// ---------------- conv GEMMs (vectorized LDS128 fragments, mode=blockIdx.z) -----
// As [2][128][36] (p32 k-layout), Bs [2][64][36] (B transposed [n][k], p32)
__global__ __launch_bounds__(256, 2) void convgemm_kernel(
    const float* __restrict__ bias0, const float* __restrict__ bias1)
{
    int mode = blockIdx.z;
    const int NSTAGE = (mode == 0) ? 10 : 2;
    extern __shared__ float sm[];
    float* As = sm;                   // 2 x 128x36
    float* Bs = sm + 2 * 128 * 36;    // 2 x 64x36
    const float* __restrict__ Bg = (mode == 0) ? g_WB : g_WB2;
    const int BK = (mode == 0) ? 320 : 64;

    int tid = threadIdx.x, lane = tid & 31, wid = tid >> 5;
    int wm = wid & 3, wn = wid >> 2, gi = lane >> 2, ci = lane & 3;
    int m0 = blockIdx.x * 128, n0 = blockIdx.y * 64;
    int bi = m0 >> 10, tibase = m0 & 1023;
    uint32_t sb = (uint32_t)__cvta_generic_to_shared(sm);
    uint32_t a_sb = sb, b_sb = sb + 2 * 128 * 36 * 4;

    auto issue_stage = [&](int s_, int buf_) {
        int mm_ = (mode == 0) ? (s_ >> 1) : 0;
        int c0_ = (mode == 0) ? ((s_ & 1) << 5) : (s_ << 5);
        int sh_ = (mode == 0) ? (2 * mm_ - 8) : 0;
#pragma unroll
        for (int i_ = 0; i_ < 4; ++i_) {
            int f4 = tid + i_ * 256;
            int row = f4 >> 3, c4 = (f4 & 7) << 2;
            int tsrc = tibase + row + sh_;
            const float* srcp = g_xin + ((size_t)(bi << 10) + tsrc) * 64 + c0_ + c4;
            uint32_t dstp = a_sb + (uint32_t)((buf_ * 4608 + row * 36 + c4) * 4);
            cp16p(dstp, srcp, (tsrc >= 0) ? 16 : 0);
        }
#pragma unroll
        for (int i_ = 0; i_ < 2; ++i_) {
            int f4 = tid + i_ * 256;             // 0..511
            int rowN = f4 >> 3, c4 = (f4 & 7) << 2;
            const float* srcp = Bg + (size_t)(n0 + rowN) * BK + s_ * 32 + c4;
            uint32_t dstp = b_sb + (uint32_t)((buf_ * 2304 + rowN * 36 + c4) * 4);
            cp16(dstp, srcp);
        }
        CPCOMMIT();
    };

    float acc[2][4][4];
#pragma unroll
    for (int a = 0; a < 2; ++a)
#pragma unroll
        for (int b = 0; b < 4; ++b)
#pragma unroll
            for (int c = 0; c < 4; ++c) acc[a][b][c] = 0.f;

    issue_stage(0, 0);
    for (int s = 0; s < NSTAGE; ++s) {
        if (s + 1 < NSTAGE) { issue_stage(s + 1, (s + 1) & 1); CPWAIT1(); }
        else CPWAIT0();
        __syncthreads();
        const float* Ab = As + (s & 1) * 4608;
        const float* Bb = Bs + (s & 1) * 2304;

        // A fragments: per mi, 4 LDS128 give all 4 k-steps for rows r and r+8
        uint4 Aq[2][4];
#pragma unroll
        for (int mi = 0; mi < 2; ++mi) {
            int r = wm * 32 + mi * 16 + gi;
            const uint4* p0 = (const uint4*)(Ab + r * 36) + 2 * ci;
            const uint4* p8 = (const uint4*)(Ab + (r + 8) * 36) + 2 * ci;
            Aq[mi][0] = p0[0]; Aq[mi][1] = p0[1];
            Aq[mi][2] = p8[0]; Aq[mi][3] = p8[1];
        }
#pragma unroll
        for (int ni = 0; ni < 4; ++ni) {
            int n = wn * 32 + ni * 8 + gi;
            const uint4* pb = (const uint4*)(Bb + n * 36) + 2 * ci;
            uint4 B0 = pb[0], B1 = pb[1];
#pragma unroll
            for (int mi = 0; mi < 2; ++mi) {
                mma8(acc[mi][ni], Aq[mi][0].x, Aq[mi][2].x, Aq[mi][0].y, Aq[mi][2].y, B0.x, B0.y); // kk0
                mma8(acc[mi][ni], Aq[mi][0].z, Aq[mi][2].z, Aq[mi][0].w, Aq[mi][2].w, B0.z, B0.w); // kk1
                mma8(acc[mi][ni], Aq[mi][1].x, Aq[mi][3].x, Aq[mi][1].y, Aq[mi][3].y, B1.x, B1.y); // kk2
                mma8(acc[mi][ni], Aq[mi][1].z, Aq[mi][3].z, Aq[mi][1].w, Aq[mi][3].w, B1.z, B1.w); // kk3
            }
        }
        __syncthreads();
    }

#pragma unroll
    for (int mi = 0; mi < 2; ++mi)
#pragma unroll
        for (int ni = 0; ni < 4; ++ni)
#pragma unroll
            for (int j = 0; j < 4; ++j) {
                int m = m0 + wm * 32 + mi * 16 + gi + ((j >= 2) ? 8 : 0);
                int n = n0 + wn * 32 + ni * 8 + 2 * ci + (j & 1);
                float v = acc[mi][ni][j];
                int o = n & 511, ki = o >> 3, h = o & 7;
                int bb = m >> 10, ti = m & 1023;
                int gg = bb * 8 + (ti >> 7);
                int tj = ((ti & 127) << 3) | h;
                if (mode == 0) {
                    float bias = (n < 512) ? bias0[n] : bias1[n - 512];
                    float s = silu_fast(v + bias) * 0.35355339059327373f;  // / 64^0.25
                    float* dst = (n < 512) ? g_q : g_k;
                    dst[((size_t)gg * TLEN + tj) * KD + pqk(ki)] = tf32r(s);
                } else {
                    float s = silu_fast(v);
                    if (n < 512) {
                        g_v[((size_t)gg * KD + ki) * TLEN + (tj & ~63) + pqk(nom64(tj & 63))] = tf32r(s);
                    } else {
                        g_l[((size_t)gg * TLEN + tj) * KD + ki] = tf32r(s);
                    }
                }
            }
}

// ---------------- flash attention + local attention (merged launch) ------------
__global__ __launch_bounds__(256, 2) void flash_mma_kernel()
{
    extern __shared__ float sm[];
    int g  = blockIdx.x;
    int p  = blockIdx.y;
    int tid = threadIdx.x, lane = tid & 31, wid = tid >> 5;

    if (p >= 8) {
        // ================= local windowed causal attention =================
        int t0 = (p - 8) * 256;
        const float* Lg = g_l + (size_t)g * (TLEN * KD);
        for (int i = tid; i < 261 * 16; i += 256) {
            int r = i >> 4, c4 = (i & 15) << 2;
            int tg = t0 - 5 + r;
            float4 v = make_float4(0.f, 0.f, 0.f, 0.f);
            if (tg >= 0) v = *(const float4*)&Lg[(size_t)tg * 64 + c4];
            *(float4*)&sm[r * 68 + c4] = v;
        }
        __syncthreads();
        int qq = tid >> 2, pi = tid & 3;
#pragma unroll
        for (int pass = 0; pass < 4; ++pass) {
            int q = pass * 64 + qq;
            int tj = t0 + q;
            const float* Lq = sm + (q + 5) * 68;
            float4 xq[4];
#pragma unroll
            for (int i = 0; i < 4; ++i)
                xq[i] = *(const float4*)&Lq[pi * 4 + i * 16];

            float sc[6], mx = -1e30f;
#pragma unroll
            for (int w = 0; w < 6; ++w) {
                const float* Lr = sm + (q + w) * 68;
                float d = 0.f;
#pragma unroll
                for (int i = 0; i < 4; ++i) {
                    float4 rv = *(const float4*)&Lr[pi * 4 + i * 16];
                    d += xq[i].x * rv.x + xq[i].y * rv.y + xq[i].z * rv.z + xq[i].w * rv.w;
                }
                d += __shfl_xor_sync(0xffffffffu, d, 1);
                d += __shfl_xor_sync(0xffffffffu, d, 2);
                sc[w] = (tj - 5 + w >= 0) ? d * 0.125f : -1e30f;
                mx = fmaxf(mx, sc[w]);
            }
            float e[6], den = 0.f;
#pragma unroll
            for (int w = 0; w < 6; ++w) { e[w] = __expf(sc[w] - mx); den += e[w]; }
            float inv = 1.f / den;

            float4 acc[4];
#pragma unroll
            for (int i = 0; i < 4; ++i) acc[i] = make_float4(0.f, 0.f, 0.f, 0.f);
#pragma unroll
            for (int w = 0; w < 6; ++w) {
                float ew = e[w];
                const float* Lr = sm + (q + w) * 68;
#pragma unroll
                for (int i = 0; i < 4; ++i) {
                    float4 rv = *(const float4*)&Lr[pi * 4 + i * 16];
                    acc[i].x += ew * rv.x; acc[i].y += ew * rv.y;
                    acc[i].z += ew * rv.z; acc[i].w += ew * rv.w;
                }
            }
            float* Og = g_ol + (size_t)g * (TLEN * KD) + (size_t)tj * 64;
#pragma unroll
            for (int i = 0; i < 4; ++i) {
                float4 t;
                t.x = acc[i].x * inv; t.y = acc[i].y * inv;
                t.z = acc[i].z * inv; t.w = acc[i].w * inv;
                *(float4*)&Og[pi * 4 + i * 16] = t;
            }
        }
        return;
    }

    // ========================= flash attention (v5) =========================
    int qa = p, qb = 15 - p;
    int gi = lane >> 2, ci = lane & 3;
    int wa = wid & 3;
    bool grpB = wid >= 4;
    int barid = grpB ? 2 : 1;
    int Na = p + 1;
    int NIT = grpB ? 9 : 8;
    uint32_t sb = (uint32_t)__cvta_generic_to_shared(sm);
    int KO = grpB ? 12288 : 0;
    int VO = KO + 8192;
    int lt = wa * 32 + lane;

    int offw[4];
#pragma unroll
    for (int t4 = 0; t4 < 4; ++t4)
        offw[t4] = (((2 * ci + (t4 & 1) + ((t4 >> 1) << 3)) ^ gi) << 2);

    const float* Qg  = g_q + (size_t)g * (TLEN * KD);
    const float* Kg0 = g_k + (size_t)g * (TLEN * KD);
    const float* Vg0 = g_v + (size_t)g * (KD * TLEN);

    int qt = grpB ? qb : qa;
    int qbase = qt * 64 + wa * 16;
    int r0 = qbase + gi;

    uint32_t qf[8][4];
    auto load_qf = [&]() {
#pragma unroll
        for (int t4 = 0; t4 < 4; ++t4) {
            int woff = (2 * ci + (t4 & 1) + ((t4 >> 1) << 3)) << 2;
            float4 lo = *(const float4*)&Qg[(size_t)r0 * KD + woff];
            float4 hi = *(const float4*)&Qg[(size_t)(r0 + 8) * KD + woff];
            int kk0 = ((t4 >> 1) << 2) + ((t4 & 1) << 1);
            qf[kk0][0]     = __float_as_uint(lo.x); qf[kk0][2]     = __float_as_uint(lo.y);
            qf[kk0 + 1][0] = __float_as_uint(lo.z); qf[kk0 + 1][2] = __float_as_uint(lo.w);
            qf[kk0][1]     = __float_as_uint(hi.x); qf[kk0][3]     = __float_as_uint(hi.y);
            qf[kk0 + 1][1] = __float_as_uint(hi.z); qf[kk0 + 1][3] = __float_as_uint(hi.w);
        }
    };
    load_qf();

    float o[8][4];
#pragma unroll
    for (int a = 0; a < 8; ++a)
#pragma unroll
        for (int b = 0; b < 4; ++b) o[a][b] = 0.f;
    float m0v = -1e30f, m1v = -1e30f, l0 = 0.f, l1 = 0.f;

    auto kt_of = [&](int i) {
        if (grpB) return i;
        return (i < Na) ? i : (9 + i - Na);
    };

    auto issueK = [&](int i, int buf) {
        int k0 = kt_of(i) * 64;
#pragma unroll
        for (int j = 0; j < 8; ++j) {
            int f4 = lt + j * 128;
            int row = f4 >> 4, chunk = f4 & 15;
            int swc = chunk ^ (row & 7);
            cp16(sb + (uint32_t)((KO + buf * 4096 + row * 64 + swc * 4) * 4),
                 Kg0 + (size_t)(k0 + row) * 64 + chunk * 4);
        }
        CPCOMMIT();
    };
    auto issueV = [&](int i) {
        int k0 = kt_of(i) * 64;
#pragma unroll
        for (int j = 0; j < 8; ++j) {
            int f4 = lt + j * 128;
            int row = f4 >> 4, chunk = f4 & 15;
            int swc = chunk ^ (row & 7);
            cp16(sb + (uint32_t)((VO + row * 64 + swc * 4) * 4),
                 Vg0 + (size_t)row * TLEN + k0 + chunk * 4);
        }
        CPCOMMIT();
    };

    auto epilogue_store = [&]() {
        float inv0 = 1.f / l0, inv1 = 1.f / l1;
        float* Og = g_og + (size_t)g * (TLEN * KD);
#pragma unroll
        for (int nd = 0; nd < 8; ++nd) {
            int c = nd * 8 + 2 * ci;
            float2 t0; t0.x = o[nd][0] * inv0; t0.y = o[nd][1] * inv0;
            float2 t1; t1.x = o[nd][2] * inv1; t1.y = o[nd][3] * inv1;
            *(float2*)&Og[(size_t)r0 * KD + c] = t0;
            *(float2*)&Og[(size_t)(r0 + 8) * KD + c] = t1;
        }
    };
    auto reset_state = [&]() {
#pragma unroll
        for (int a = 0; a < 8; ++a)
#pragma unroll
            for (int b = 0; b < 4; ++b) o[a][b] = 0.f;
        m0v = -1e30f; m1v = -1e30f; l0 = 0.f; l1 = 0.f;
    };

    issueK(0, 0);
    for (int i = 0; i < NIT; ++i) {
        if (!grpB && i == Na) {
            epilogue_store();
            reset_state();
            qt = qb; qbase = qt * 64 + wa * 16; r0 = qbase + gi;
            load_qf();
        }
        bool more = (i + 1 < NIT);
        issueV(i);
        if (more) issueK(i + 1, (i + 1) & 1);
        if (more) CPWAIT2(); else CPWAIT1();    // K(i) ready
        barg(barid);

        int k0 = kt_of(i) * 64;
        const float* Ks = sm + KO + (i & 1) * 4096;
        const float* Vs = sm + VO;

        float s[8][4];
#pragma unroll
        for (int ni = 0; ni < 8; ++ni) {
            s[ni][0] = s[ni][1] = s[ni][2] = s[ni][3] = 0.f;
            const uint32_t* Krow = (const uint32_t*)(Ks + (ni * 8 + gi) * 64);
#pragma unroll
            for (int t4 = 0; t4 < 4; ++t4) {
                uint4 F = *(const uint4*)(Krow + offw[t4]);
                int kk0 = ((t4 >> 1) << 2) + ((t4 & 1) << 1);
                mma8(s[ni], qf[kk0][0], qf[kk0][1], qf[kk0][2], qf[kk0][3], F.x, F.y);
                mma8(s[ni], qf[kk0 + 1][0], qf[kk0 + 1][1], qf[kk0 + 1][2], qf[kk0 + 1][3], F.z, F.w);
            }
        }
        if (k0 + 63 > qbase) {
#pragma unroll
            for (int ni = 0; ni < 8; ++ni)
#pragma unroll
                for (int j = 0; j < 4; ++j) {
                    int col = k0 + ni * 8 + 2 * ci + (j & 1);
                    int row = r0 + ((j >= 2) ? 8 : 0);
                    if (col > row) s[ni][j] = -1e30f;
                }
        }
        float mx0 = -1e30f, mx1 = -1e30f;
#pragma unroll
        for (int ni = 0; ni < 8; ++ni) {
            mx0 = fmaxf(mx0, fmaxf(s[ni][0], s[ni][1]));
            mx1 = fmaxf(mx1, fmaxf(s[ni][2], s[ni][3]));
        }
        mx0 = fmaxf(mx0, __shfl_xor_sync(0xffffffffu, mx0, 1));
        mx0 = fmaxf(mx0, __shfl_xor_sync(0xffffffffu, mx0, 2));
        mx1 = fmaxf(mx1, __shfl_xor_sync(0xffffffffu, mx1, 1));
        mx1 = fmaxf(mx1, __shfl_xor_sync(0xffffffffu, mx1, 2));
        float m0n = fmaxf(m0v, mx0), m1n = fmaxf(m1v, mx1);
        float corr0 = __expf(m0v - m0n), corr1 = __expf(m1v - m1n);

        float sum0 = 0.f, sum1 = 0.f;
#pragma unroll
        for (int ni = 0; ni < 8; ++ni) {
            s[ni][0] = tf32r(__expf(s[ni][0] - m0n));
            s[ni][1] = tf32r(__expf(s[ni][1] - m0n));
            s[ni][2] = tf32r(__expf(s[ni][2] - m1n));
            s[ni][3] = tf32r(__expf(s[ni][3] - m1n));
            sum0 += s[ni][0] + s[ni][1];
            sum1 += s[ni][2] + s[ni][3];
        }
        sum0 += __shfl_xor_sync(0xffffffffu, sum0, 1);
        sum0 += __shfl_xor_sync(0xffffffffu, sum0, 2);
        sum1 += __shfl_xor_sync(0xffffffffu, sum1, 1);
        sum1 += __shfl_xor_sync(0xffffffffu, sum1, 2);
        l0 = l0 * corr0 + sum0;
        l1 = l1 * corr1 + sum1;
        m0v = m0n; m1v = m1n;
#pragma unroll
        for (int nd = 0; nd < 8; ++nd) {
            o[nd][0] *= corr0; o[nd][1] *= corr0;
            o[nd][2] *= corr1; o[nd][3] *= corr1;
        }
        if (more) CPWAIT1(); else CPWAIT0();    // V(i) ready
        barg(barid);
#pragma unroll
        for (int nd = 0; nd < 8; ++nd) {
            const uint32_t* Vrow = (const uint32_t*)(Vs + (nd * 8 + gi) * 64);
#pragma unroll
            for (int t4 = 0; t4 < 4; ++t4) {
                uint4 F = *(const uint4*)(Vrow + offw[t4]);
                int kg0 = ((t4 >> 1) << 2) + ((t4 & 1) << 1);
                mma8(o[nd], __float_as_uint(s[kg0][0]), __float_as_uint(s[kg0][2]),
                     __float_as_uint(s[kg0][1]), __float_as_uint(s[kg0][3]), F.x, F.y);
                mma8(o[nd], __float_as_uint(s[kg0 + 1][0]), __float_as_uint(s[kg0 + 1][2]),
                     __float_as_uint(s[kg0 + 1][1]), __float_as_uint(s[kg0 + 1][3]), F.z, F.w);
            }
        }
        barg(barid);
    }

    if (!grpB && Na == NIT) {
        epilogue_store();
        reset_state();
        qt = qb; qbase = qt * 64 + wa * 16; r0 = qbase + gi;
    }

    // ---- split-KV merge for q-tile qb
    float* ob = sm + 12288;
    float* mb = sm + 12288 + 4352;
    float* lb = mb + 64;
    if (grpB) {
        int rr = wa * 16 + gi;
#pragma unroll
        for (int nd = 0; nd < 8; ++nd) {
            int c = nd * 8 + 2 * ci;
            *(float2*)&ob[rr * 68 + c]       = make_float2(o[nd][0], o[nd][1]);
            *(float2*)&ob[(rr + 8) * 68 + c] = make_float2(o[nd][2], o[nd][3]);
        }
        if (ci == 0) {
            mb[rr] = m0v; lb[rr] = l0;
            mb[rr + 8] = m1v; lb[rr + 8] = l1;
        }
    }
    __syncthreads();
    if (!grpB) {
        int rr = wa * 16 + gi;
        float mB0 = mb[rr], lB0 = lb[rr], mB1 = mb[rr + 8], lB1 = lb[rr + 8];
        float mS0 = fmaxf(m0v, mB0), mS1 = fmaxf(m1v, mB1);
        float cA0 = __expf(m0v - mS0), cB0 = __expf(mB0 - mS0);
        float cA1 = __expf(m1v - mS1), cB1 = __expf(mB1 - mS1);
        l0 = l0 * cA0 + lB0 * cB0;
        l1 = l1 * cA1 + lB1 * cB1;
#pragma unroll
        for (int nd = 0; nd < 8; ++nd) {
            int c = nd * 8 + 2 * ci;
            float2 b0 = *(float2*)&ob[rr * 68 + c];
            float2 b1 = *(float2*)&ob[(rr + 8) * 68 + c];
            o[nd][0] = o[nd][0] * cA0 + b0.x * cB0;
            o[nd][1] = o[nd][1] * cA0 + b0.y * cB0;
            o[nd][2] = o[nd][2] * cA1 + b1.x * cB1;
            o[nd][3] = o[nd][3] * cA1 + b1.y * cB1;
        }
        epilogue_store();
    }
}

// ---------------- uni projection: fused gating + K-split(8) tf32 GEMM ----------
__global__ __launch_bounds__(256, 2) void unigemm_kernel()
{
    __shared__ float As[128][36];
    __shared__ float Bs[32][68];
    int tid = threadIdx.x, lane = tid & 31, wid = tid >> 5;
    int wm = wid & 3, wn = wid >> 2, gi = lane >> 2, ci = lane & 3;
    int m0 = blockIdx.x * 128;
    int kz = blockIdx.y;
    int bi = m0 >> 10, tib = m0 & 1023;
    uint32_t b_sb = (uint32_t)__cvta_generic_to_shared(&Bs[0][0]);

    float acc[2][4][4];
#pragma unroll
    for (int a = 0; a < 2; ++a)
#pragma unroll
        for (int b = 0; b < 4; ++b)
#pragma unroll
            for (int c = 0; c < 4; ++c) acc[a][b][c] = 0.f;

    for (int s = 0; s < 4; ++s) {
        int k0 = kz * 128 + s * 32;
        int ch = k0 >> 6, ki0 = k0 & 63;
        int h2 = ch & 7;
        bool lohalf = ch < 8;
        const float* Og = g_og + (size_t)(bi * 8 + h2) * (TLEN * KD);
        const float* Lg = g_ol + (size_t)(bi * 8 + h2) * (TLEN * KD);
        __syncthreads();
#pragma unroll
        for (int i = 0; i < 2; ++i) {
            int f4 = tid + i * 256;
            int row = f4 >> 4, c4 = (f4 & 15) << 2;
            cp16(b_sb + (uint32_t)((row * 68 + c4) * 4), g_WU + (size_t)(k0 + row) * 64 + c4);
        }
        CPCOMMIT();
#pragma unroll
        for (int i = 0; i < 4; ++i) {
            int f4 = tid + i * 256;
            int row = f4 >> 3, c4 = (f4 & 7) << 2;
            int ti2 = tib + row;
            const float4 o4 = *(const float4*)(Og + (size_t)ti2 * 64 + ki0 + c4);
            const float4 l4 = *(const float4*)(Lg + (size_t)ti2 * 64 + ki0 + c4);
            float g0 = sigmoid_fast(o4.x), g1 = sigmoid_fast(o4.y);
            float g2 = sigmoid_fast(o4.z), g3 = sigmoid_fast(o4.w);
            float r0 = lohalf ? (1.f - g0) * l4.x : g0 * o4.x;
            float r1 = lohalf ? (1.f - g1) * l4.y : g1 * o4.y;
            float r2 = lohalf ? (1.f - g2) * l4.z : g2 * o4.z;
            float r3 = lohalf ? (1.f - g3) * l4.w : g3 * o4.w;
            As[row][c4 + 0] = tf32r(r0);
            As[row][c4 + 1] = tf32r(r1);
            As[row][c4 + 2] = tf32r(r2);
            As[row][c4 + 3] = tf32r(r3);
        }
        CPWAIT0();
        __syncthreads();
#pragma unroll
        for (int kk = 0; kk < 4; ++kk) {
            int k = kk * 8;
            uint32_t af[2][4];
#pragma unroll
            for (int mi = 0; mi < 2; ++mi) {
                int r = wm * 32 + mi * 16 + gi;
                af[mi][0] = __float_as_uint(As[r][k + ci]);
                af[mi][1] = __float_as_uint(As[r + 8][k + ci]);
                af[mi][2] = __float_as_uint(As[r][k + ci + 4]);
                af[mi][3] = __float_as_uint(As[r + 8][k + ci + 4]);
            }
            uint32_t bf[4][2];
#pragma unroll
            for (int ni = 0; ni < 4; ++ni) {
                int n = wn * 32 + ni * 8 + gi;
                bf[ni][0] = __float_as_uint(Bs[k + ci][n]);
                bf[ni][1] = __float_as_uint(Bs[k + ci + 4][n]);
            }
#pragma unroll
            for (int mi = 0; mi < 2; ++mi)
#pragma unroll
                for (int ni = 0; ni < 4; ++ni)
                    mma8(acc[mi][ni], af[mi][0], af[mi][1], af[mi][2], af[mi][3],
                         bf[ni][0], bf[ni][1]);
        }
    }

    float* P = g_part + ((size_t)kz * MROWS + m0) * 64;
#pragma unroll
    for (int mi = 0; mi < 2; ++mi)
#pragma unroll
        for (int ni = 0; ni < 4; ++ni)
#pragma unroll
            for (int j = 0; j < 4; j += 2) {
                int mrow = wm * 32 + mi * 16 + gi + ((j >= 2) ? 8 : 0);
                int n = wn * 32 + ni * 8 + 2 * ci;
                float2 t; t.x = acc[mi][ni][j]; t.y = acc[mi][ni][j + 1];
                *(float2*)&P[(size_t)mrow * 64 + n] = t;
            }
}

// ---------------- partial-reduce(8) + silu + residual -> LN1 -> FF -> LN2 ------
__global__ __launch_bounds__(256) void ffln_kernel(
    const float* __restrict__ uni_b,
    const float* __restrict__ ln1g, const float* __restrict__ ln1b,
    const float* __restrict__ ln2g, const float* __restrict__ ln2b,
    const float* __restrict__ w1, const float* __restrict__ b1,
    const float* __restrict__ w2, const float* __restrict__ b2,
    float* __restrict__ out)
{
    const int R = 16;
    __shared__ float yl[R][64];
    __shared__ float hs[R][256];
    __shared__ float fs[R][64];
    int r0 = blockIdx.x * R;
    int tid = threadIdx.x;
    int lane = tid & 31, w = tid >> 5;

    for (int rr = 0; rr < 2; ++rr) {
        int r = w * 2 + rr;
        size_t rg = (size_t)(r0 + r) * 64;
        float v0 = 0.f, v1 = 0.f;
#pragma unroll
        for (int kz = 0; kz < 8; ++kz) {
            v0 += g_part[(size_t)kz * MROWS * 64 + rg + lane];
            v1 += g_part[(size_t)kz * MROWS * 64 + rg + lane + 32];
        }
        // g_xin is p32-permuted within each 32-channel half
        v0 = silu_fast(v0 + uni_b[lane]) + g_xin[rg + p32(lane)];
        v1 = silu_fast(v1 + uni_b[lane + 32]) + g_xin[rg + 32 + p32(lane)];
        float sm = v0 + v1;
#pragma unroll
        for (int o = 16; o; o >>= 1) sm += __shfl_xor_sync(0xffffffffu, sm, o);
        float mean = sm * (1.f / 64.f);
        float d0 = v0 - mean, d1 = v1 - mean;
        float vs = d0 * d0 + d1 * d1;
#pragma unroll
        for (int o = 16; o; o >>= 1) vs += __shfl_xor_sync(0xffffffffu, vs, o);
        float inv = rsqrtf(vs * (1.f / 64.f) + 1e-5f);
        yl[r][lane]      = d0 * inv * ln1g[lane] + ln1b[lane];
        yl[r][lane + 32] = d1 * inv * ln1g[lane + 32] + ln1b[lane + 32];
    }
    __syncthreads();

    {
        float acc[R];
#pragma unroll
        for (int r = 0; r < R; ++r) acc[r] = b1[tid];
        for (int c = 0; c < 64; ++c) {
            float wv = w1[c * 256 + tid];
#pragma unroll
            for (int r = 0; r < R; ++r) acc[r] += yl[r][c] * wv;
        }
#pragma unroll
        for (int r = 0; r < R; ++r) hs[r][tid] = fmaxf(acc[r], 0.f);
    }
    __syncthreads();

    {
        int j2 = tid & 63, rg = tid >> 6;
        float acc[4];
#pragma unroll
        for (int rr = 0; rr < 4; ++rr) acc[rr] = b2[j2];
        for (int c = 0; c < 256; ++c) {
            float wv = w2[c * 64 + j2];
#pragma unroll
            for (int rr = 0; rr < 4; ++rr) acc[rr] += hs[rg * 4 + rr][c] * wv;
        }
#pragma unroll
        for (int rr = 0; rr < 4; ++rr) fs[rg * 4 + rr][j2] = acc[rr] + yl[rg * 4 + rr][j2];
    }
    __syncthreads();

    for (int rr = 0; rr < 2; ++rr) {
        int r = w * 2 + rr;
        float v0 = fs[r][lane], v1 = fs[r][lane + 32];
        float sm = v0 + v1;
#pragma unroll
        for (int o = 16; o; o >>= 1) sm += __shfl_xor_sync(0xffffffffu, sm, o);
        float mean = sm * (1.f / 64.f);
        float d0 = v0 - mean, d1 = v1 - mean;
        float vs = d0 * d0 + d1 * d1;
#pragma unroll
        for (int o = 16; o; o >>= 1) vs += __shfl_xor_sync(0xffffffffu, vs, o);
        float inv = rsqrtf(vs * (1.f / 64.f) + 1e-5f);
        float* orow = out + (size_t)(r0 + r) * 64;
        orow[lane]      = d0 * inv * ln2g[lane] + ln2b[lane];
        orow[lane + 32] = d1 * inv * ln2g[lane + 32] + ln2b[lane + 32];
    }
}

// ---------------- launch ---------------------------------------------------------
extern "C" void kernel_launch(void* const* d_in, const int* in_sizes, int n_in,
                              void* d_out, int out_size)
{
    (void)in_sizes; (void)n_in; (void)out_size;
    const float* x       = (const float*)d_in[0];
    const float* sq_w    = (const float*)d_in[1];
    const float* bn_g    = (const float*)d_in[2];
    const float* bn_b    = (const float*)d_in[3];
    const float* dw_w    = (const float*)d_in[4];
    const float* ex_w    = (const float*)d_in[5];
    const float* pos_emb = (const float*)d_in[6];
    const float* wq      = (const float*)d_in[7];
    const float* bq      = (const float*)d_in[8];
    const float* wk      = (const float*)d_in[9];
    const float* bk      = (const float*)d_in[10];
    const float* wv      = (const float*)d_in[11];
    const float* wl      = (const float*)d_in[12];
    const float* uni_w   = (const float*)d_in[13];
    const float* uni_b   = (const float*)d_in[14];
    const float* ln1_g   = (const float*)d_in[15];
    const float* ln1_b   = (const float*)d_in[16];
    const float* ln2_g   = (const float*)d_in[17];
    const float* ln2_b   = (const float*)d_in[18];
    const float* ff_w1   = (const float*)d_in[19];
    const float* ff_b1   = (const float*)d_in[20];
    const float* ff_w2   = (const float*)d_in[21];
    const float* ff_b2   = (const float*)d_in[22];
    float* out = (float*)d_out;

    const int CONV_SMEM  = (2 * 128 * 36 + 2 * 64 * 36) * 4;   // 55296
    const int FLASH_SMEM = 24576 * 4;                          // 98304 (2 blocks/SM)
    cudaFuncSetAttribute(convgemm_kernel, cudaFuncAttributeMaxDynamicSharedMemorySize, CONV_SMEM);
    cudaFuncSetAttribute(flash_mma_kernel, cudaFuncAttributeMaxDynamicSharedMemorySize, FLASH_SMEM);

    fused_xin_kernel<<<dim3(4, 32), 256>>>(x, sq_w, bn_g, bn_b, dw_w, ex_w, pos_emb);
    prep_wqk_kernel<<<1280, 256>>>(wq, wk);
    prep_wvl_uni_kernel<<<512, 256>>>(wv, wl, uni_w);

    convgemm_kernel<<<dim3(32, 16, 2), 256, CONV_SMEM>>>(bq, bk);   // profiled slot

    flash_mma_kernel<<<dim3(32, 12), 256, FLASH_SMEM>>>();          // flash + local

    unigemm_kernel<<<dim3(32, 8), 256>>>();

    ffln_kernel<<<256, 256>>>(uni_b, ln1_g, ln1_b, ln2_g, ln2_b,
                              ff_w1, ff_b1, ff_w2, ff_b2, out);
}

// round 12
// speedup vs baseline: 1.1700x; 1.1103x over previous
#include <cuda_runtime.h>
#include <math.h>
#include <stdint.h>

// Problem constants (fixed by setup_inputs)
#define BATCH 4
#define TLEN  1024
#define KD    64
#define HNUM  8
#define R32   32
#define NSEQ  32      // BATCH*HNUM
#define MROWS 4096    // BATCH*TLEN

// ---------------- scratch (static device globals; no allocation) --------------
__device__ float g_xin[BATCH * TLEN * KD];          // [b][t][ (c&32)|p32(c&31) ] tf32-exact
__device__ float g_WB[1024 * 320];                  // [n][kcol: per-32 p32] wq|wk, tf32-exact
__device__ float g_WB2[1024 * 64];                  // [n][c: per-32 p32] wv|wl, tf32-exact
__device__ float g_WU[1024 * 64];                   // uni_w, tf32-exact
__device__ float g_q[NSEQ * TLEN * KD];             // [g][t][d] identity words, tf32-exact
__device__ float g_k[NSEQ * TLEN * KD];             // [g][t][d] identity words
__device__ float g_v[NSEQ * KD * TLEN];             // [g][d][t: 64-tilewise pqk(nom64(key))]
__device__ float g_l[NSEQ * TLEN * KD];             // natural
__device__ float g_og[NSEQ * TLEN * KD];
__device__ float g_ol[NSEQ * TLEN * KD];
__device__ float g_part[8 * MROWS * KD];            // uni GEMM K-split partials (8-way)

__device__ __forceinline__ float sigmoid_exact(float x) { return 1.f / (1.f + expf(-x)); }
__device__ __forceinline__ float sigmoid_fast(float x) {
    float t;
    asm("tanh.approx.f32 %0, %1;" : "=f"(t) : "f"(0.5f * x));
    return 0.5f * t + 0.5f;
}
__device__ __forceinline__ float silu_fast(float x) { return x * sigmoid_fast(x); }

// round f32 -> nearest tf32 (result is a valid f32 with low mantissa zeroed)
__device__ __forceinline__ float tf32r(float x) {
    uint32_t u;
    asm("cvt.rna.tf32.f32 %0, %1;" : "=r"(u) : "f"(x));
    return __uint_as_float(u);
}

// fragment-vectorization permutation of a 64-long contraction dim (V keys only)
__device__ __forceinline__ int pqk(int k) {
    return ((k & 3) << 3) | ((k >> 5) << 5) | (((k >> 4) & 1) << 2) |
           (((k >> 3) & 1) << 1) | ((k >> 2) & 1);
}
// within-8 interleave so S C-fragments serve directly as PV A-fragments
__device__ __forceinline__ int nom64(int t) {
    return (t & 56) | ((t >> 1) & 3) | ((t & 1) << 2);
}
// 32-wide contraction permutation (conv GEMM k-dim)
__device__ __forceinline__ int p32(int t) {
    return ((t & 3) << 3) | (((t >> 4) & 1) << 2) | (((t >> 3) & 1) << 1) | ((t >> 2) & 1);
}

__device__ __forceinline__ void mma8(float* c,
                                     uint32_t a0, uint32_t a1, uint32_t a2, uint32_t a3,
                                     uint32_t b0, uint32_t b1) {
    asm volatile(
        "mma.sync.aligned.m16n8k8.row.col.f32.tf32.tf32.f32 "
        "{%0,%1,%2,%3}, {%4,%5,%6,%7}, {%8,%9}, {%0,%1,%2,%3};"
        : "+f"(c[0]), "+f"(c[1]), "+f"(c[2]), "+f"(c[3])
        : "r"(a0), "r"(a1), "r"(a2), "r"(a3), "r"(b0), "r"(b1));
}

__device__ __forceinline__ void cp16(uint32_t dst, const void* src) {
    asm volatile("cp.async.ca.shared.global [%0], [%1], 16;" :: "r"(dst), "l"(src) : "memory");
}
__device__ __forceinline__ void cp16p(uint32_t dst, const void* src, int sz) {
    asm volatile("cp.async.ca.shared.global [%0], [%1], 16, %2;" :: "r"(dst), "l"(src), "r"(sz) : "memory");
}
#define CPCOMMIT() asm volatile("cp.async.commit_group;" ::: "memory")
#define CPWAIT0()  asm volatile("cp.async.wait_group 0;" ::: "memory")
#define CPWAIT1()  asm volatile("cp.async.wait_group 1;" ::: "memory")
#define CPWAIT2()  asm volatile("cp.async.wait_group 2;" ::: "memory")

__device__ __forceinline__ void barg(int id) {
    asm volatile("bar.sync %0, 128;" :: "r"(id) : "memory");
}

// ================= fused action + pos_emb -> xin (p32-permuted, tf32-exact) ====
__global__ __launch_bounds__(256) void fused_xin_kernel(
    const float* __restrict__ x, const float* __restrict__ sq_w,
    const float* __restrict__ bn_g, const float* __restrict__ bn_b,
    const float* __restrict__ dw_w, const float* __restrict__ ex_w,
    const float* __restrict__ pos_emb)
{
    __shared__ float xs[34][68];
    __shared__ float x3s[34][36];
    __shared__ float xp3[32][32];
    __shared__ float sqT[64][32];
    __shared__ float exT[32][64];
    __shared__ float bng_s[32], bnb_s[32];

    int bi = blockIdx.x;
    int t0 = blockIdx.y * 32;
    int tid = threadIdx.x;
    int nrows = min(34, TLEN - t0);

    for (int i = tid; i < nrows * 16; i += 256) {
        int row = i >> 4, c4 = (i & 15) << 2;
        *(float4*)&xs[row][c4] = *(const float4*)&x[((size_t)bi * TLEN + t0 + row) * KD + c4];
    }
    for (int i = tid; i < 2048; i += 256) { int r = i >> 6, c = i & 63; sqT[c][r] = sq_w[i]; }
    for (int i = tid; i < 2048; i += 256) { int c = i >> 5, r = i & 31; exT[r][c] = ex_w[i]; }
    if (tid < 32) { bng_s[tid] = bn_g[tid] * 0.9999950000374997f; bnb_s[tid] = bn_b[tid]; }
    __syncthreads();

    {
        int j = tid >> 2, rg = (tid & 3) << 3;
        if (j < nrows) {
            float acc[8];
#pragma unroll
            for (int i = 0; i < 8; ++i) acc[i] = 0.f;
#pragma unroll
            for (int c4 = 0; c4 < 64; c4 += 4) {
                float4 xv = *(const float4*)&xs[j][c4];
#pragma unroll
                for (int t = 0; t < 4; ++t) {
                    float xc = (t == 0) ? xv.x : (t == 1) ? xv.y : (t == 2) ? xv.z : xv.w;
                    float4 s0 = *(const float4*)&sqT[c4 + t][rg];
                    float4 s1 = *(const float4*)&sqT[c4 + t][rg + 4];
                    acc[0] += xc * s0.x; acc[1] += xc * s0.y;
                    acc[2] += xc * s0.z; acc[3] += xc * s0.w;
                    acc[4] += xc * s1.x; acc[5] += xc * s1.y;
                    acc[6] += xc * s1.z; acc[7] += xc * s1.w;
                }
            }
#pragma unroll
            for (int i = 0; i < 8; ++i)
                x3s[j][rg + i] = acc[i] * bng_s[rg + i] + bnb_s[rg + i];
        }
    }
    __syncthreads();

    for (int idx = tid; idx < 32 * 32; idx += 256) {
        int r = idx & 31, jj = idx >> 5;
        int pos = t0 + jj;
        float base = x3s[jj][r];
        float v;
        if (pos == TLEN - 1) {
            v = base;
        } else {
            float d0 = dw_w[r * 3 + 0], d1 = dw_w[r * 3 + 1], d2 = dw_w[r * 3 + 2];
            float a = base * d0 + x3s[jj + 1][r] * d1 +
                      ((pos + 2 < TLEN) ? x3s[jj + 2][r] * d2 : 0.f);
            v = a - base;
        }
        xp3[jj][r] = v;
    }
    __syncthreads();

    for (int idx = tid; idx < 32 * 64; idx += 256) {
        int c = idx & 63, j = idx >> 6;
        int pos = t0 + j;
        float gsum = 0.f;
#pragma unroll
        for (int r = 0; r < R32; ++r) gsum += xp3[j][r] * exT[r][c];
        float sig = sigmoid_exact(gsum);
        size_t off = ((size_t)bi * TLEN + pos) * KD + ((c & 32) | p32(c & 31));
        g_xin[off] = tf32r(xs[j][c] * sig + pos_emb[pos * KD + c]);
    }
}

// ---------------- weight prep ([n][K] layout, per-32 p32 permuted) ------------
__global__ __launch_bounds__(256) void prep_wqk_kernel(
    const float* __restrict__ wq, const float* __restrict__ wk)
{
    int idx = blockIdx.x * 256 + threadIdx.x;
    if (idx >= 320 * 1024) return;
    int n = idx & 1023, kcol = idx >> 10;      // kcol tap-major: mm*64 + c
    int mm = kcol >> 6, c = kcol & 63;
    float w = (n < 512) ? wq[n * 320 + c * 5 + mm] : wk[(n - 512) * 320 + c * 5 + mm];
    g_WB[(size_t)n * 320 + (kcol & ~31) + p32(kcol & 31)] = tf32r(w);
}

__global__ __launch_bounds__(256) void prep_wvl_uni_kernel(
    const float* __restrict__ wv, const float* __restrict__ wl,
    const float* __restrict__ uni_w)
{
    int idx = blockIdx.x * 256 + threadIdx.x;
    if (idx < 65536) {
        int n = idx & 1023, c = idx >> 10;
        float w = (n < 512) ? wv[n * 64 + c] : wl[(n - 512) * 64 + c];
        g_WB2[(size_t)n * 64 + (c & 32) + p32(c & 31)] = tf32r(w);
    } else if (idx < 131072) {
        int j = idx - 65536;
        g_WU[j] = tf32r(uni_w[j]);
    }
}

// ---------------- conv GEMMs (vectorized LDS128 frags + staged epilogue) --------
__global__ __launch_bounds__(256, 2) void convgemm_kernel(
    const float* __restrict__ bias0, const float* __restrict__ bias1)
{
    int mode = blockIdx.z;
    const int NSTAGE = (mode == 0) ? 10 : 2;
    extern __shared__ float sm[];
    float* As = sm;                   // 2 x 128x36
    float* Bs = sm + 2 * 128 * 36;    // 2 x 64x36
    const float* __restrict__ Bg = (mode == 0) ? g_WB : g_WB2;
    const int BK = (mode == 0) ? 320 : 64;

    int tid = threadIdx.x, lane = tid & 31, wid = tid >> 5;
    int wm = wid & 3, wn = wid >> 2, gi = lane >> 2, ci = lane & 3;
    int m0 = blockIdx.x * 128, n0 = blockIdx.y * 64;
    int bi = m0 >> 10, tibase = m0 & 1023;
    uint32_t sb = (uint32_t)__cvta_generic_to_shared(sm);
    uint32_t a_sb = sb, b_sb = sb + 2 * 128 * 36 * 4;

    auto issue_stage = [&](int s_, int buf_) {
        int mm_ = (mode == 0) ? (s_ >> 1) : 0;
        int c0_ = (mode == 0) ? ((s_ & 1) << 5) : (s_ << 5);
        int sh_ = (mode == 0) ? (2 * mm_ - 8) : 0;
#pragma unroll
        for (int i_ = 0; i_ < 4; ++i_) {
            int f4 = tid + i_ * 256;
            int row = f4 >> 3, c4 = (f4 & 7) << 2;
            int tsrc = tibase + row + sh_;
            const float* srcp = g_xin + ((size_t)(bi << 10) + tsrc) * 64 + c0_ + c4;
            uint32_t dstp = a_sb + (uint32_t)((buf_ * 4608 + row * 36 + c4) * 4);
            cp16p(dstp, srcp, (tsrc >= 0) ? 16 : 0);
        }
#pragma unroll
        for (int i_ = 0; i_ < 2; ++i_) {
            int f4 = tid + i_ * 256;             // 0..511
            int rowN = f4 >> 3, c4 = (f4 & 7) << 2;
            const float* srcp = Bg + (size_t)(n0 + rowN) * BK + s_ * 32 + c4;
            uint32_t dstp = b_sb + (uint32_t)((buf_ * 2304 + rowN * 36 + c4) * 4);
            cp16(dstp, srcp);
        }
        CPCOMMIT();
    };

    float acc[2][4][4];
#pragma unroll
    for (int a = 0; a < 2; ++a)
#pragma unroll
        for (int b = 0; b < 4; ++b)
#pragma unroll
            for (int c = 0; c < 4; ++c) acc[a][b][c] = 0.f;

    issue_stage(0, 0);
    for (int s = 0; s < NSTAGE; ++s) {
        if (s + 1 < NSTAGE) { issue_stage(s + 1, (s + 1) & 1); CPWAIT1(); }
        else CPWAIT0();
        __syncthreads();
        const float* Ab = As + (s & 1) * 4608;
        const float* Bb = Bs + (s & 1) * 2304;

        uint4 Aq[2][4];
#pragma unroll
        for (int mi = 0; mi < 2; ++mi) {
            int r = wm * 32 + mi * 16 + gi;
            const uint4* p0 = (const uint4*)(Ab + r * 36) + 2 * ci;
            const uint4* p8 = (const uint4*)(Ab + (r + 8) * 36) + 2 * ci;
            Aq[mi][0] = p0[0]; Aq[mi][1] = p0[1];
            Aq[mi][2] = p8[0]; Aq[mi][3] = p8[1];
        }
#pragma unroll
        for (int ni = 0; ni < 4; ++ni) {
            int n = wn * 32 + ni * 8 + gi;
            const uint4* pb = (const uint4*)(Bb + n * 36) + 2 * ci;
            uint4 B0 = pb[0], B1 = pb[1];
#pragma unroll
            for (int mi = 0; mi < 2; ++mi) {
                mma8(acc[mi][ni], Aq[mi][0].x, Aq[mi][2].x, Aq[mi][0].y, Aq[mi][2].y, B0.x, B0.y);
                mma8(acc[mi][ni], Aq[mi][0].z, Aq[mi][2].z, Aq[mi][0].w, Aq[mi][2].w, B0.z, B0.w);
                mma8(acc[mi][ni], Aq[mi][1].x, Aq[mi][3].x, Aq[mi][1].y, Aq[mi][3].y, B1.x, B1.y);
                mma8(acc[mi][ni], Aq[mi][1].z, Aq[mi][3].z, Aq[mi][1].w, Aq[mi][3].w, B1.z, B1.w);
            }
        }
        __syncthreads();
    }

    if (mode == 0 || n0 >= 512) {
        // ---- staged, coalesced epilogue (q / k / l) ----
        float* Cs = sm;        // 128 x 65 floats (reuses A buffers; mainloop done)
#pragma unroll
        for (int mi = 0; mi < 2; ++mi)
#pragma unroll
            for (int ni = 0; ni < 4; ++ni)
#pragma unroll
                for (int j = 0; j < 4; ++j) {
                    int ml = wm * 32 + mi * 16 + gi + ((j >= 2) ? 8 : 0);
                    int nl = wn * 32 + ni * 8 + 2 * ci + (j & 1);
                    float v = acc[mi][ni][j];
                    float s;
                    if (mode == 0) {
                        int n = n0 + nl;
                        float bias = (n < 512) ? bias0[n] : bias1[n - 512];
                        s = tf32r(silu_fast(v + bias) * 0.35355339059327373f);
                    } else {
                        s = tf32r(silu_fast(v));
                    }
                    Cs[ml * 65 + nl] = s;
                }
        __syncthreads();
        float* dst = (mode == 0) ? ((n0 < 512) ? g_q : g_k) : g_l;
        int ki0 = (n0 & 511) >> 3;          // multiple of 8
        int gg = bi * 8 + (tibase >> 7);
        int q = tid >> 1;
        int hb = (tid & 1) * 4;
        const float* Cq = Cs + q * 65;
        size_t rb = (size_t)gg * TLEN * KD;
#pragma unroll
        for (int h = hb; h < hb + 4; ++h) {
            float4 lo = make_float4(Cq[h], Cq[8 + h], Cq[16 + h], Cq[24 + h]);
            float4 hi4 = make_float4(Cq[32 + h], Cq[40 + h], Cq[48 + h], Cq[56 + h]);
            float* drow = dst + rb + (size_t)(q * 8 + h) * KD + ki0;
            *(float4*)drow = lo;
            *(float4*)(drow + 4) = hi4;
        }
    } else {
        // ---- mode1 V: permuted layout, direct stores ----
#pragma unroll
        for (int mi = 0; mi < 2; ++mi)
#pragma unroll
            for (int ni = 0; ni < 4; ++ni)
#pragma unroll
                for (int j = 0; j < 4; ++j) {
                    int m = m0 + wm * 32 + mi * 16 + gi + ((j >= 2) ? 8 : 0);
                    int n = n0 + wn * 32 + ni * 8 + 2 * ci + (j & 1);
                    float s = silu_fast(acc[mi][ni][j]);
                    int o = n & 511, ki = o >> 3, h = o & 7;
                    int bb = m >> 10, ti = m & 1023;
                    int gg = bb * 8 + (ti >> 7);
                    int tj = ((ti & 127) << 3) | h;
                    g_v[((size_t)gg * KD + ki) * TLEN + (tj & ~63) + pqk(nom64(tj & 63))] = tf32r(s);
                }
    }
}

// ---------------- flash attention + local attention (merged launch) ------------
__global__ __launch_bounds__(256, 2) void flash_mma_kernel()
{
    extern __shared__ float sm[];
    int g  = blockIdx.x;
    int p  = blockIdx.y;
    int tid = threadIdx.x, lane = tid & 31, wid = tid >> 5;

    if (p >= 8) {
        // ================= local windowed causal attention =================
        int t0 = (p - 8) * 256;
        const float* Lg = g_l + (size_t)g * (TLEN * KD);
        for (int i = tid; i < 261 * 16; i += 256) {
            int r = i >> 4, c4 = (i & 15) << 2;
            int tg = t0 - 5 + r;
            float4 v = make_float4(0.f, 0.f, 0.f, 0.f);
            if (tg >= 0) v = *(const float4*)&Lg[(size_t)tg * 64 + c4];
            *(float4*)&sm[r * 68 + c4] = v;
        }
        __syncthreads();
        int qq = tid >> 2, pi = tid & 3;
#pragma unroll
        for (int pass = 0; pass < 4; ++pass) {
            int q = pass * 64 + qq;
            int tj = t0 + q;
            const float* Lq = sm + (q + 5) * 68;
            float4 xq[4];
#pragma unroll
            for (int i = 0; i < 4; ++i)
                xq[i] = *(const float4*)&Lq[pi * 4 + i * 16];

            float sc[6], mx = -1e30f;
#pragma unroll
            for (int w = 0; w < 6; ++w) {
                const float* Lr = sm + (q + w) * 68;
                float d = 0.f;
#pragma unroll
                for (int i = 0; i < 4; ++i) {
                    float4 rv = *(const float4*)&Lr[pi * 4 + i * 16];
                    d += xq[i].x * rv.x + xq[i].y * rv.y + xq[i].z * rv.z + xq[i].w * rv.w;
                }
                d += __shfl_xor_sync(0xffffffffu, d, 1);
                d += __shfl_xor_sync(0xffffffffu, d, 2);
                sc[w] = (tj - 5 + w >= 0) ? d * 0.125f : -1e30f;
                mx = fmaxf(mx, sc[w]);
            }
            float e[6], den = 0.f;
#pragma unroll
            for (int w = 0; w < 6; ++w) { e[w] = __expf(sc[w] - mx); den += e[w]; }
            float inv = 1.f / den;

            float4 acc[4];
#pragma unroll
            for (int i = 0; i < 4; ++i) acc[i] = make_float4(0.f, 0.f, 0.f, 0.f);
#pragma unroll
            for (int w = 0; w < 6; ++w) {
                float ew = e[w];
                const float* Lr = sm + (q + w) * 68;
#pragma unroll
                for (int i = 0; i < 4; ++i) {
                    float4 rv = *(const float4*)&Lr[pi * 4 + i * 16];
                    acc[i].x += ew * rv.x; acc[i].y += ew * rv.y;
                    acc[i].z += ew * rv.z; acc[i].w += ew * rv.w;
                }
            }
            float* Og = g_ol + (size_t)g * (TLEN * KD) + (size_t)tj * 64;
#pragma unroll
            for (int i = 0; i < 4; ++i) {
                float4 t;
                t.x = acc[i].x * inv; t.y = acc[i].y * inv;
                t.z = acc[i].z * inv; t.w = acc[i].w * inv;
                *(float4*)&Og[pi * 4 + i * 16] = t;
            }
        }
        return;
    }

    // ========================= flash attention (v5) =========================
    int qa = p, qb = 15 - p;
    int gi = lane >> 2, ci = lane & 3;
    int wa = wid & 3;
    bool grpB = wid >= 4;
    int barid = grpB ? 2 : 1;
    int Na = p + 1;
    int NIT = grpB ? 9 : 8;
    uint32_t sb = (uint32_t)__cvta_generic_to_shared(sm);
    int KO = grpB ? 12288 : 0;
    int VO = KO + 8192;
    int lt = wa * 32 + lane;

    int offw[4];
#pragma unroll
    for (int t4 = 0; t4 < 4; ++t4)
        offw[t4] = (((2 * ci + (t4 & 1) + ((t4 >> 1) << 3)) ^ gi) << 2);

    const float* Qg  = g_q + (size_t)g * (TLEN * KD);
    const float* Kg0 = g_k + (size_t)g * (TLEN * KD);
    const float* Vg0 = g_v + (size_t)g * (KD * TLEN);

    int qt = grpB ? qb : qa;
    int qbase = qt * 64 + wa * 16;
    int r0 = qbase + gi;

    uint32_t qf[8][4];
    auto load_qf = [&]() {
#pragma unroll
        for (int t4 = 0; t4 < 4; ++t4) {
            int woff = (2 * ci + (t4 & 1) + ((t4 >> 1) << 3)) << 2;
            float4 lo = *(const float4*)&Qg[(size_t)r0 * KD + woff];
            float4 hi = *(const float4*)&Qg[(size_t)(r0 + 8) * KD + woff];
            int kk0 = ((t4 >> 1) << 2) + ((t4 & 1) << 1);
            qf[kk0][0]     = __float_as_uint(lo.x); qf[kk0][2]     = __float_as_uint(lo.y);
            qf[kk0 + 1][0] = __float_as_uint(lo.z); qf[kk0 + 1][2] = __float_as_uint(lo.w);
            qf[kk0][1]     = __float_as_uint(hi.x); qf[kk0][3]     = __float_as_uint(hi.y);
            qf[kk0 + 1][1] = __float_as_uint(hi.z); qf[kk0 + 1][3] = __float_as_uint(hi.w);
        }
    };
    load_qf();

    float o[8][4];
#pragma unroll
    for (int a = 0; a < 8; ++a)
#pragma unroll
        for (int b = 0; b < 4; ++b) o[a][b] = 0.f;
    float m0v = -1e30f, m1v = -1e30f, l0 = 0.f, l1 = 0.f;

    auto kt_of = [&](int i) {
        if (grpB) return i;
        return (i < Na) ? i : (9 + i - Na);
    };

    auto issueK = [&](int i, int buf) {
        int k0 = kt_of(i) * 64;
#pragma unroll
        for (int j = 0; j < 8; ++j) {
            int f4 = lt + j * 128;
            int row = f4 >> 4, chunk = f4 & 15;
            int swc = chunk ^ (row & 7);
            cp16(sb + (uint32_t)((KO + buf * 4096 + row * 64 + swc * 4) * 4),
                 Kg0 + (size_t)(k0 + row) * 64 + chunk * 4);
        }
        CPCOMMIT();
    };
    auto issueV = [&](int i) {
        int k0 = kt_of(i) * 64;
#pragma unroll
        for (int j = 0; j < 8; ++j) {
            int f4 = lt + j * 128;
            int row = f4 >> 4, chunk = f4 & 15;
            int swc = chunk ^ (row & 7);
            cp16(sb + (uint32_t)((VO + row * 64 + swc * 4) * 4),
                 Vg0 + (size_t)row * TLEN + k0 + chunk * 4);
        }
        CPCOMMIT();
    };

    auto epilogue_store = [&]() {
        float inv0 = 1.f / l0, inv1 = 1.f / l1;
        float* Og = g_og + (size_t)g * (TLEN * KD);
#pragma unroll
        for (int nd = 0; nd < 8; ++nd) {
            int c = nd * 8 + 2 * ci;
            float2 t0; t0.x = o[nd][0] * inv0; t0.y = o[nd][1] * inv0;
            float2 t1; t1.x = o[nd][2] * inv1; t1.y = o[nd][3] * inv1;
            *(float2*)&Og[(size_t)r0 * KD + c] = t0;
            *(float2*)&Og[(size_t)(r0 + 8) * KD + c] = t1;
        }
    };
    auto reset_state = [&]() {
#pragma unroll
        for (int a = 0; a < 8; ++a)
#pragma unroll
            for (int b = 0; b < 4; ++b) o[a][b] = 0.f;
        m0v = -1e30f; m1v = -1e30f; l0 = 0.f; l1 = 0.f;
    };

    issueK(0, 0);
    for (int i = 0; i < NIT; ++i) {
        if (!grpB && i == Na) {
            epilogue_store();
            reset_state();
            qt = qb; qbase = qt * 64 + wa * 16; r0 = qbase + gi;
            load_qf();
        }
        bool more = (i + 1 < NIT);
        issueV(i);
        if (more) issueK(i + 1, (i + 1) & 1);
        if (more) CPWAIT2(); else CPWAIT1();    // K(i) ready
        barg(barid);

        int k0 = kt_of(i) * 64;
        const float* Ks = sm + KO + (i & 1) * 4096;
        const float* Vs = sm + VO;

        float s[8][4];
#pragma unroll
        for (int ni = 0; ni < 8; ++ni) {
            s[ni][0] = s[ni][1] = s[ni][2] = s[ni][3] = 0.f;
            const uint32_t* Krow = (const uint32_t*)(Ks + (ni * 8 + gi) * 64);
#pragma unroll
            for (int t4 = 0; t4 < 4; ++t4) {
                uint4 F = *(const uint4*)(Krow + offw[t4]);
                int kk0 = ((t4 >> 1) << 2) + ((t4 & 1) << 1);
                mma8(s[ni], qf[kk0][0], qf[kk0][1], qf[kk0][2], qf[kk0][3], F.x, F.y);
                mma8(s[ni], qf[kk0 + 1][0], qf[kk0 + 1][1], qf[kk0 + 1][2], qf[kk0 + 1][3], F.z, F.w);
            }
        }
        if (k0 + 63 > qbase) {
#pragma unroll
            for (int ni = 0; ni < 8; ++ni)
#pragma unroll
                for (int j = 0; j < 4; ++j) {
                    int col = k0 + ni * 8 + 2 * ci + (j & 1);
                    int row = r0 + ((j >= 2) ? 8 : 0);
                    if (col > row) s[ni][j] = -1e30f;
                }
        }
        float mx0 = -1e30f, mx1 = -1e30f;
#pragma unroll
        for (int ni = 0; ni < 8; ++ni) {
            mx0 = fmaxf(mx0, fmaxf(s[ni][0], s[ni][1]));
            mx1 = fmaxf(mx1, fmaxf(s[ni][2], s[ni][3]));
        }
        mx0 = fmaxf(mx0, __shfl_xor_sync(0xffffffffu, mx0, 1));
        mx0 = fmaxf(mx0, __shfl_xor_sync(0xffffffffu, mx0, 2));
        mx1 = fmaxf(mx1, __shfl_xor_sync(0xffffffffu, mx1, 1));
        mx1 = fmaxf(mx1, __shfl_xor_sync(0xffffffffu, mx1, 2));
        float m0n = fmaxf(m0v, mx0), m1n = fmaxf(m1v, mx1);
        float corr0 = __expf(m0v - m0n), corr1 = __expf(m1v - m1n);

        float sum0 = 0.f, sum1 = 0.f;
#pragma unroll
        for (int ni = 0; ni < 8; ++ni) {
            s[ni][0] = tf32r(__expf(s[ni][0] - m0n));
            s[ni][1] = tf32r(__expf(s[ni][1] - m0n));
            s[ni][2] = tf32r(__expf(s[ni][2] - m1n));
            s[ni][3] = tf32r(__expf(s[ni][3] - m1n));
            sum0 += s[ni][0] + s[ni][1];
            sum1 += s[ni][2] + s[ni][3];
        }
        sum0 += __shfl_xor_sync(0xffffffffu, sum0, 1);
        sum0 += __shfl_xor_sync(0xffffffffu, sum0, 2);
        sum1 += __shfl_xor_sync(0xffffffffu, sum1, 1);
        sum1 += __shfl_xor_sync(0xffffffffu, sum1, 2);
        l0 = l0 * corr0 + sum0;
        l1 = l1 * corr1 + sum1;
        m0v = m0n; m1v = m1n;
#pragma unroll
        for (int nd = 0; nd < 8; ++nd) {
            o[nd][0] *= corr0; o[nd][1] *= corr0;
            o[nd][2] *= corr1; o[nd][3] *= corr1;
        }
        if (more) CPWAIT1(); else CPWAIT0();    // V(i) ready
        barg(barid);
#pragma unroll
        for (int nd = 0; nd < 8; ++nd) {
            const uint32_t* Vrow = (const uint32_t*)(Vs + (nd * 8 + gi) * 64);
#pragma unroll
            for (int t4 = 0; t4 < 4; ++t4) {
                uint4 F = *(const uint4*)(Vrow + offw[t4]);
                int kg0 = ((t4 >> 1) << 2) + ((t4 & 1) << 1);
                mma8(o[nd], __float_as_uint(s[kg0][0]), __float_as_uint(s[kg0][2]),
                     __float_as_uint(s[kg0][1]), __float_as_uint(s[kg0][3]), F.x, F.y);
                mma8(o[nd], __float_as_uint(s[kg0 + 1][0]), __float_as_uint(s[kg0 + 1][2]),
                     __float_as_uint(s[kg0 + 1][1]), __float_as_uint(s[kg0 + 1][3]), F.z, F.w);
            }
        }
        barg(barid);
    }

    if (!grpB && Na == NIT) {
        epilogue_store();
        reset_state();
        qt = qb; qbase = qt * 64 + wa * 16; r0 = qbase + gi;
    }

    // ---- split-KV merge for q-tile qb
    float* ob = sm + 12288;
    float* mb = sm + 12288 + 4352;
    float* lb = mb + 64;
    if (grpB) {
        int rr = wa * 16 + gi;
#pragma unroll
        for (int nd = 0; nd < 8; ++nd) {
            int c = nd * 8 + 2 * ci;
            *(float2*)&ob[rr * 68 + c]       = make_float2(o[nd][0], o[nd][1]);
            *(float2*)&ob[(rr + 8) * 68 + c] = make_float2(o[nd][2], o[nd][3]);
        }
        if (ci == 0) {
            mb[rr] = m0v; lb[rr] = l0;
            mb[rr + 8] = m1v; lb[rr + 8] = l1;
        }
    }
    __syncthreads();
    if (!grpB) {
        int rr = wa * 16 + gi;
        float mB0 = mb[rr], lB0 = lb[rr], mB1 = mb[rr + 8], lB1 = lb[rr + 8];
        float mS0 = fmaxf(m0v, mB0), mS1 = fmaxf(m1v, mB1);
        float cA0 = __expf(m0v - mS0), cB0 = __expf(mB0 - mS0);
        float cA1 = __expf(m1v - mS1), cB1 = __expf(mB1 - mS1);
        l0 = l0 * cA0 + lB0 * cB0;
        l1 = l1 * cA1 + lB1 * cB1;
#pragma unroll
        for (int nd = 0; nd < 8; ++nd) {
            int c = nd * 8 + 2 * ci;
            float2 b0 = *(float2*)&ob[rr * 68 + c];
            float2 b1 = *(float2*)&ob[(rr + 8) * 68 + c];
            o[nd][0] = o[nd][0] * cA0 + b0.x * cB0;
            o[nd][1] = o[nd][1] * cA0 + b0.y * cB0;
            o[nd][2] = o[nd][2] * cA1 + b1.x * cB1;
            o[nd][3] = o[nd][3] * cA1 + b1.y * cB1;
        }
        epilogue_store();
    }
}

// ---------------- uni projection: fused gating + K-split(8) tf32 GEMM ----------
__global__ __launch_bounds__(256, 2) void unigemm_kernel()
{
    __shared__ float As[128][36];
    __shared__ float Bs[32][68];
    int tid = threadIdx.x, lane = tid & 31, wid = tid >> 5;
    int wm = wid & 3, wn = wid >> 2, gi = lane >> 2, ci = lane & 3;
    int m0 = blockIdx.x * 128;
    int kz = blockIdx.y;
    int bi = m0 >> 10, tib = m0 & 1023;
    uint32_t b_sb = (uint32_t)__cvta_generic_to_shared(&Bs[0][0]);

    float acc[2][4][4];
#pragma unroll
    for (int a = 0; a < 2; ++a)
#pragma unroll
        for (int b = 0; b < 4; ++b)
#pragma unroll
            for (int c = 0; c < 4; ++c) acc[a][b][c] = 0.f;

    for (int s = 0; s < 4; ++s) {
        int k0 = kz * 128 + s * 32;
        int ch = k0 >> 6, ki0 = k0 & 63;
        int h2 = ch & 7;
        bool lohalf = ch < 8;
        const float* Og = g_og + (size_t)(bi * 8 + h2) * (TLEN * KD);
        const float* Lg = g_ol + (size_t)(bi * 8 + h2) * (TLEN * KD);
        __syncthreads();
#pragma unroll
        for (int i = 0; i < 2; ++i) {
            int f4 = tid + i * 256;
            int row = f4 >> 4, c4 = (f4 & 15) << 2;
            cp16(b_sb + (uint32_t)((row * 68 + c4) * 4), g_WU + (size_t)(k0 + row) * 64 + c4);
        }
        CPCOMMIT();
#pragma unroll
        for (int i = 0; i < 4; ++i) {
            int f4 = tid + i * 256;
            int row = f4 >> 3, c4 = (f4 & 7) << 2;
            int ti2 = tib + row;
            const float4 o4 = *(const float4*)(Og + (size_t)ti2 * 64 + ki0 + c4);
            const float4 l4 = *(const float4*)(Lg + (size_t)ti2 * 64 + ki0 + c4);
            float g0 = sigmoid_fast(o4.x), g1 = sigmoid_fast(o4.y);
            float g2 = sigmoid_fast(o4.z), g3 = sigmoid_fast(o4.w);
            float r0 = lohalf ? (1.f - g0) * l4.x : g0 * o4.x;
            float r1 = lohalf ? (1.f - g1) * l4.y : g1 * o4.y;
            float r2 = lohalf ? (1.f - g2) * l4.z : g2 * o4.z;
            float r3 = lohalf ? (1.f - g3) * l4.w : g3 * o4.w;
            As[row][c4 + 0] = tf32r(r0);
            As[row][c4 + 1] = tf32r(r1);
            As[row][c4 + 2] = tf32r(r2);
            As[row][c4 + 3] = tf32r(r3);
        }
        CPWAIT0();
        __syncthreads();
#pragma unroll
        for (int kk = 0; kk < 4; ++kk) {
            int k = kk * 8;
            uint32_t af[2][4];
#pragma unroll
            for (int mi = 0; mi < 2; ++mi) {
                int r = wm * 32 + mi * 16 + gi;
                af[mi][0] = __float_as_uint(As[r][k + ci]);
                af[mi][1] = __float_as_uint(As[r + 8][k + ci]);
                af[mi][2] = __float_as_uint(As[r][k + ci + 4]);
                af[mi][3] = __float_as_uint(As[r + 8][k + ci + 4]);
            }
            uint32_t bf[4][2];
#pragma unroll
            for (int ni = 0; ni < 4; ++ni) {
                int n = wn * 32 + ni * 8 + gi;
                bf[ni][0] = __float_as_uint(Bs[k + ci][n]);
                bf[ni][1] = __float_as_uint(Bs[k + ci + 4][n]);
            }
#pragma unroll
            for (int mi = 0; mi < 2; ++mi)
#pragma unroll
                for (int ni = 0; ni < 4; ++ni)
                    mma8(acc[mi][ni], af[mi][0], af[mi][1], af[mi][2], af[mi][3],
                         bf[ni][0], bf[ni][1]);
        }
    }

    float* P = g_part + ((size_t)kz * MROWS + m0) * 64;
#pragma unroll
    for (int mi = 0; mi < 2; ++mi)
#pragma unroll
        for (int ni = 0; ni < 4; ++ni)
#pragma unroll
            for (int j = 0; j < 4; j += 2) {
                int mrow = wm * 32 + mi * 16 + gi + ((j >= 2) ? 8 : 0);
                int n = wn * 32 + ni * 8 + 2 * ci;
                float2 t; t.x = acc[mi][ni][j]; t.y = acc[mi][ni][j + 1];
                *(float2*)&P[(size_t)mrow * 64 + n] = t;
            }
}

// ---------------- partial-reduce(8) + silu + residual -> LN1 -> FF -> LN2 ------
__global__ __launch_bounds__(256) void ffln_kernel(
    const float* __restrict__ uni_b,
    const float* __restrict__ ln1g, const float* __restrict__ ln1b,
    const float* __restrict__ ln2g, const float* __restrict__ ln2b,
    const float* __restrict__ w1, const float* __restrict__ b1,
    const float* __restrict__ w2, const float* __restrict__ b2,
    float* __restrict__ out)
{
    const int R = 16;
    __shared__ float yl[R][64];
    __shared__ float hs[R][256];
    __shared__ float fs[R][64];
    int r0 = blockIdx.x * R;
    int tid = threadIdx.x;
    int lane = tid & 31, w = tid >> 5;

    for (int rr = 0; rr < 2; ++rr) {
        int r = w * 2 + rr;
        size_t rg = (size_t)(r0 + r) * 64;
        float v0 = 0.f, v1 = 0.f;
#pragma unroll
        for (int kz = 0; kz < 8; ++kz) {
            v0 += g_part[(size_t)kz * MROWS * 64 + rg + lane];
            v1 += g_part[(size_t)kz * MROWS * 64 + rg + lane + 32];
        }
        v0 = silu_fast(v0 + uni_b[lane]) + g_xin[rg + p32(lane)];
        v1 = silu_fast(v1 + uni_b[lane + 32]) + g_xin[rg + 32 + p32(lane)];
        float sm = v0 + v1;
#pragma unroll
        for (int o = 16; o; o >>= 1) sm += __shfl_xor_sync(0xffffffffu, sm, o);
        float mean = sm * (1.f / 64.f);
        float d0 = v0 - mean, d1 = v1 - mean;
        float vs = d0 * d0 + d1 * d1;
#pragma unroll
        for (int o = 16; o; o >>= 1) vs += __shfl_xor_sync(0xffffffffu, vs, o);
        float inv = rsqrtf(vs * (1.f / 64.f) + 1e-5f);
        yl[r][lane]      = d0 * inv * ln1g[lane] + ln1b[lane];
        yl[r][lane + 32] = d1 * inv * ln1g[lane + 32] + ln1b[lane + 32];
    }
    __syncthreads();

    {
        float acc[R];
#pragma unroll
        for (int r = 0; r < R; ++r) acc[r] = b1[tid];
        for (int c = 0; c < 64; ++c) {
            float wv = w1[c * 256 + tid];
#pragma unroll
            for (int r = 0; r < R; ++r) acc[r] += yl[r][c] * wv;
        }
#pragma unroll
        for (int r = 0; r < R; ++r) hs[r][tid] = fmaxf(acc[r], 0.f);
    }
    __syncthreads();

    {
        int j2 = tid & 63, rg = tid >> 6;
        float acc[4];
#pragma unroll
        for (int rr = 0; rr < 4; ++rr) acc[rr] = b2[j2];
        for (int c = 0; c < 256; ++c) {
            float wv = w2[c * 64 + j2];
#pragma unroll
            for (int rr = 0; rr < 4; ++rr) acc[rr] += hs[rg * 4 + rr][c] * wv;
        }
#pragma unroll
        for (int rr = 0; rr < 4; ++rr) fs[rg * 4 + rr][j2] = acc[rr] + yl[rg * 4 + rr][j2];
    }
    __syncthreads();

    for (int rr = 0; rr < 2; ++rr) {
        int r = w * 2 + rr;
        float v0 = fs[r][lane], v1 = fs[r][lane + 32];
        float sm = v0 + v1;
#pragma unroll
        for (int o = 16; o; o >>= 1) sm += __shfl_xor_sync(0xffffffffu, sm, o);
        float mean = sm * (1.f / 64.f);
        float d0 = v0 - mean, d1 = v1 - mean;
        float vs = d0 * d0 + d1 * d1;
#pragma unroll
        for (int o = 16; o; o >>= 1) vs += __shfl_xor_sync(0xffffffffu, vs, o);
        float inv = rsqrtf(vs * (1.f / 64.f) + 1e-5f);
        float* orow = out + (size_t)(r0 + r) * 64;
        orow[lane]      = d0 * inv * ln2g[lane] + ln2b[lane];
        orow[lane + 32] = d1 * inv * ln2g[lane + 32] + ln2b[lane + 32];
    }
}

// ---------------- launch ---------------------------------------------------------
extern "C" void kernel_launch(void* const* d_in, const int* in_sizes, int n_in,
                              void* d_out, int out_size)
{
    (void)in_sizes; (void)n_in; (void)out_size;
    const float* x       = (const float*)d_in[0];
    const float* sq_w    = (const float*)d_in[1];
    const float* bn_g    = (const float*)d_in[2];
    const float* bn_b    = (const float*)d_in[3];
    const float* dw_w    = (const float*)d_in[4];
    const float* ex_w    = (const float*)d_in[5];
    const float* pos_emb = (const float*)d_in[6];
    const float* wq      = (const float*)d_in[7];
    const float* bq      = (const float*)d_in[8];
    const float* wk      = (const float*)d_in[9];
    const float* bk      = (const float*)d_in[10];
    const float* wv      = (const float*)d_in[11];
    const float* wl      = (const float*)d_in[12];
    const float* uni_w   = (const float*)d_in[13];
    const float* uni_b   = (const float*)d_in[14];
    const float* ln1_g   = (const float*)d_in[15];
    const float* ln1_b   = (const float*)d_in[16];
    const float* ln2_g   = (const float*)d_in[17];
    const float* ln2_b   = (const float*)d_in[18];
    const float* ff_w1   = (const float*)d_in[19];
    const float* ff_b1   = (const float*)d_in[20];
    const float* ff_w2   = (const float*)d_in[21];
    const float* ff_b2   = (const float*)d_in[22];
    float* out = (float*)d_out;

    const int CONV_SMEM  = (2 * 128 * 36 + 2 * 64 * 36) * 4;   // 55296
    const int FLASH_SMEM = 24576 * 4;                          // 98304 (2 blocks/SM)
    cudaFuncSetAttribute(convgemm_kernel, cudaFuncAttributeMaxDynamicSharedMemorySize, CONV_SMEM);
    cudaFuncSetAttribute(flash_mma_kernel, cudaFuncAttributeMaxDynamicSharedMemorySize, FLASH_SMEM);

    fused_xin_kernel<<<dim3(4, 32), 256>>>(x, sq_w, bn_g, bn_b, dw_w, ex_w, pos_emb);
    prep_wqk_kernel<<<1280, 256>>>(wq, wk);
    prep_wvl_uni_kernel<<<512, 256>>>(wv, wl, uni_w);

    convgemm_kernel<<<dim3(32, 16, 2), 256, CONV_SMEM>>>(bq, bk);   // profiled slot

    flash_mma_kernel<<<dim3(32, 12), 256, FLASH_SMEM>>>();          // flash + local

    unigemm_kernel<<<dim3(32, 8), 256>>>();

    ffln_kernel<<<256, 256>>>(uni_b, ln1_g, ln1_b, ln2_g, ln2_b,
                              ff_w1, ff_b1, ff_w2, ff_b2, out);
}

// round 13
// speedup vs baseline: 1.1728x; 1.0024x over previous
#include <cuda_runtime.h>
#include <math.h>
#include <stdint.h>

// Problem constants (fixed by setup_inputs)
#define BATCH 4
#define TLEN  1024
#define KD    64
#define HNUM  8
#define R32   32
#define NSEQ  32      // BATCH*HNUM
#define MROWS 4096    // BATCH*TLEN

// ---------------- scratch (static device globals; no allocation) --------------
__device__ float g_xin[BATCH * TLEN * KD];          // [b][t][ (c&32)|p32(c&31) ] tf32-exact
__device__ float g_WB[1024 * 320];                  // [n][kcol: per-32 p32] wq|wk, tf32-exact
__device__ float g_WB2[1024 * 64];                  // [n][c: per-32 p32] wv|wl, tf32-exact
__device__ float g_WU[1024 * 64];                   // uni_w, tf32-exact
__device__ float g_q[NSEQ * TLEN * KD];             // [g][t][d] identity words, tf32-exact
__device__ float g_k[NSEQ * TLEN * KD];             // [g][t][d] identity words
__device__ float g_v[NSEQ * KD * TLEN];             // [g][d][t: 64-tilewise pqk(nom64(key))]
__device__ float g_l[NSEQ * TLEN * KD];             // natural
__device__ float g_og[NSEQ * TLEN * KD];
__device__ float g_ol[NSEQ * TLEN * KD];
__device__ float g_part[8 * MROWS * KD];            // uni GEMM K-split partials (8-way)

__device__ __forceinline__ float sigmoid_exact(float x) { return 1.f / (1.f + expf(-x)); }
__device__ __forceinline__ float sigmoid_fast(float x) {
    float t;
    asm("tanh.approx.f32 %0, %1;" : "=f"(t) : "f"(0.5f * x));
    return 0.5f * t + 0.5f;
}
__device__ __forceinline__ float silu_fast(float x) { return x * sigmoid_fast(x); }

// round f32 -> nearest tf32 (result is a valid f32 with low mantissa zeroed)
__device__ __forceinline__ float tf32r(float x) {
    uint32_t u;
    asm("cvt.rna.tf32.f32 %0, %1;" : "=r"(u) : "f"(x));
    return __uint_as_float(u);
}

// fragment-vectorization permutation of a 64-long contraction dim (V keys only)
__device__ __forceinline__ int pqk(int k) {
    return ((k & 3) << 3) | ((k >> 5) << 5) | (((k >> 4) & 1) << 2) |
           (((k >> 3) & 1) << 1) | ((k >> 2) & 1);
}
// within-8 interleave so S C-fragments serve directly as PV A-fragments
__device__ __forceinline__ int nom64(int t) {
    return (t & 56) | ((t >> 1) & 3) | ((t & 1) << 2);
}
// 32-wide contraction permutation (conv GEMM k-dim)
__device__ __forceinline__ int p32(int t) {
    return ((t & 3) << 3) | (((t >> 4) & 1) << 2) | (((t >> 3) & 1) << 1) | ((t >> 2) & 1);
}

__device__ __forceinline__ void mma8(float* c,
                                     uint32_t a0, uint32_t a1, uint32_t a2, uint32_t a3,
                                     uint32_t b0, uint32_t b1) {
    asm volatile(
        "mma.sync.aligned.m16n8k8.row.col.f32.tf32.tf32.f32 "
        "{%0,%1,%2,%3}, {%4,%5,%6,%7}, {%8,%9}, {%0,%1,%2,%3};"
        : "+f"(c[0]), "+f"(c[1]), "+f"(c[2]), "+f"(c[3])
        : "r"(a0), "r"(a1), "r"(a2), "r"(a3), "r"(b0), "r"(b1));
}

__device__ __forceinline__ void cp16(uint32_t dst, const void* src) {
    asm volatile("cp.async.ca.shared.global [%0], [%1], 16;" :: "r"(dst), "l"(src) : "memory");
}
__device__ __forceinline__ void cp16p(uint32_t dst, const void* src, int sz) {
    asm volatile("cp.async.ca.shared.global [%0], [%1], 16, %2;" :: "r"(dst), "l"(src), "r"(sz) : "memory");
}
#define CPCOMMIT() asm volatile("cp.async.commit_group;" ::: "memory")
#define CPWAIT0()  asm volatile("cp.async.wait_group 0;" ::: "memory")
#define CPWAIT1()  asm volatile("cp.async.wait_group 1;" ::: "memory")
#define CPWAIT2()  asm volatile("cp.async.wait_group 2;" ::: "memory")

__device__ __forceinline__ void barg(int id) {
    asm volatile("bar.sync %0, 128;" :: "r"(id) : "memory");
}

// ================= fused action + pos_emb -> xin (p32-permuted, tf32-exact) ====
__global__ __launch_bounds__(256) void fused_xin_kernel(
    const float* __restrict__ x, const float* __restrict__ sq_w,
    const float* __restrict__ bn_g, const float* __restrict__ bn_b,
    const float* __restrict__ dw_w, const float* __restrict__ ex_w,
    const float* __restrict__ pos_emb)
{
    __shared__ float xs[34][68];
    __shared__ float x3s[34][36];
    __shared__ float xp3[32][32];
    __shared__ float sqT[64][32];
    __shared__ float exT[32][64];
    __shared__ float bng_s[32], bnb_s[32];

    int bi = blockIdx.x;
    int t0 = blockIdx.y * 32;
    int tid = threadIdx.x;
    int nrows = min(34, TLEN - t0);

    for (int i = tid; i < nrows * 16; i += 256) {
        int row = i >> 4, c4 = (i & 15) << 2;
        *(float4*)&xs[row][c4] = *(const float4*)&x[((size_t)bi * TLEN + t0 + row) * KD + c4];
    }
    for (int i = tid; i < 2048; i += 256) { int r = i >> 6, c = i & 63; sqT[c][r] = sq_w[i]; }
    for (int i = tid; i < 2048; i += 256) { int c = i >> 5, r = i & 31; exT[r][c] = ex_w[i]; }
    if (tid < 32) { bng_s[tid] = bn_g[tid] * 0.9999950000374997f; bnb_s[tid] = bn_b[tid]; }
    __syncthreads();

    {
        int j = tid >> 2, rg = (tid & 3) << 3;
        if (j < nrows) {
            float acc[8];
#pragma unroll
            for (int i = 0; i < 8; ++i) acc[i] = 0.f;
#pragma unroll
            for (int c4 = 0; c4 < 64; c4 += 4) {
                float4 xv = *(const float4*)&xs[j][c4];
#pragma unroll
                for (int t = 0; t < 4; ++t) {
                    float xc = (t == 0) ? xv.x : (t == 1) ? xv.y : (t == 2) ? xv.z : xv.w;
                    float4 s0 = *(const float4*)&sqT[c4 + t][rg];
                    float4 s1 = *(const float4*)&sqT[c4 + t][rg + 4];
                    acc[0] += xc * s0.x; acc[1] += xc * s0.y;
                    acc[2] += xc * s0.z; acc[3] += xc * s0.w;
                    acc[4] += xc * s1.x; acc[5] += xc * s1.y;
                    acc[6] += xc * s1.z; acc[7] += xc * s1.w;
                }
            }
#pragma unroll
            for (int i = 0; i < 8; ++i)
                x3s[j][rg + i] = acc[i] * bng_s[rg + i] + bnb_s[rg + i];
        }
    }
    __syncthreads();

    for (int idx = tid; idx < 32 * 32; idx += 256) {
        int r = idx & 31, jj = idx >> 5;
        int pos = t0 + jj;
        float base = x3s[jj][r];
        float v;
        if (pos == TLEN - 1) {
            v = base;
        } else {
            float d0 = dw_w[r * 3 + 0], d1 = dw_w[r * 3 + 1], d2 = dw_w[r * 3 + 2];
            float a = base * d0 + x3s[jj + 1][r] * d1 +
                      ((pos + 2 < TLEN) ? x3s[jj + 2][r] * d2 : 0.f);
            v = a - base;
        }
        xp3[jj][r] = v;
    }
    __syncthreads();

    for (int idx = tid; idx < 32 * 64; idx += 256) {
        int c = idx & 63, j = idx >> 6;
        int pos = t0 + j;
        float gsum = 0.f;
#pragma unroll
        for (int r = 0; r < R32; ++r) gsum += xp3[j][r] * exT[r][c];
        float sig = sigmoid_exact(gsum);
        size_t off = ((size_t)bi * TLEN + pos) * KD + ((c & 32) | p32(c & 31));
        g_xin[off] = tf32r(xs[j][c] * sig + pos_emb[pos * KD + c]);
    }
}

// ---------------- weight prep ([n][K] layout, per-32 p32 permuted) ------------
__global__ __launch_bounds__(256) void prep_wqk_kernel(
    const float* __restrict__ wq, const float* __restrict__ wk)
{
    int idx = blockIdx.x * 256 + threadIdx.x;
    if (idx >= 320 * 1024) return;
    int n = idx & 1023, kcol = idx >> 10;      // kcol tap-major: mm*64 + c
    int mm = kcol >> 6, c = kcol & 63;
    float w = (n < 512) ? wq[n * 320 + c * 5 + mm] : wk[(n - 512) * 320 + c * 5 + mm];
    g_WB[(size_t)n * 320 + (kcol & ~31) + p32(kcol & 31)] = tf32r(w);
}

__global__ __launch_bounds__(256) void prep_wvl_uni_kernel(
    const float* __restrict__ wv, const float* __restrict__ wl,
    const float* __restrict__ uni_w)
{
    int idx = blockIdx.x * 256 + threadIdx.x;
    if (idx < 65536) {
        int n = idx & 1023, c = idx >> 10;
        float w = (n < 512) ? wv[n * 64 + c] : wl[(n - 512) * 64 + c];
        g_WB2[(size_t)n * 64 + (c & 32) + p32(c & 31)] = tf32r(w);
    } else if (idx < 131072) {
        int j = idx - 65536;
        g_WU[j] = tf32r(uni_w[j]);
    }
}

// ---------------- conv GEMMs (resident A-tile + dbl-buffered B) ----------------
// Xs: xin rows [tibase-8 .. tibase+127] x 64ch, stride 68 (conflict-free frags).
// All 10 mode0 stages (5 taps x 2 halves) read shifted windows of Xs.
__global__ __launch_bounds__(256, 2) void convgemm_kernel(
    const float* __restrict__ bias0, const float* __restrict__ bias1)
{
    int mode = blockIdx.z;
    const int NSTAGE = (mode == 0) ? 10 : 2;
    extern __shared__ float sm[];
    float* Xs = sm;                   // up to 136 x 68 = 9248 floats
    float* Bs = sm + 9248;            // 2 x 64x36 = 4608 floats
    const float* __restrict__ Bg = (mode == 0) ? g_WB : g_WB2;
    const int BK = (mode == 0) ? 320 : 64;

    int tid = threadIdx.x, lane = tid & 31, wid = tid >> 5;
    int wm = wid & 3, wn = wid >> 2, gi = lane >> 2, ci = lane & 3;
    int m0 = blockIdx.x * 128, n0 = blockIdx.y * 64;
    int bi = m0 >> 10, tibase = m0 & 1023;
    uint32_t sb = (uint32_t)__cvta_generic_to_shared(sm);
    uint32_t x_sb = sb, b_sb = sb + 9248 * 4;

    int nxrows = (mode == 0) ? 136 : 128;
    int rowoff = (mode == 0) ? 8 : 0;

    // one-time resident X tile load (group 0)
    for (int i = tid; i < nxrows * 16; i += 256) {
        int rr = i >> 4, c4 = (i & 15) << 2;
        int tsrc = tibase + rr - rowoff;
        const float* srcp = g_xin + ((size_t)(bi << 10) + tsrc) * 64 + c4;
        cp16p(x_sb + (uint32_t)((rr * 68 + c4) * 4), srcp, (tsrc >= 0) ? 16 : 0);
    }
    CPCOMMIT();

    auto issueB = [&](int s_, int buf_) {
#pragma unroll
        for (int i_ = 0; i_ < 2; ++i_) {
            int f4 = tid + i_ * 256;             // 0..511
            int rowN = f4 >> 3, c4 = (f4 & 7) << 2;
            const float* srcp = Bg + (size_t)(n0 + rowN) * BK + s_ * 32 + c4;
            uint32_t dstp = b_sb + (uint32_t)((buf_ * 2304 + rowN * 36 + c4) * 4);
            cp16(dstp, srcp);
        }
        CPCOMMIT();
    };

    float acc[2][4][4];
#pragma unroll
    for (int a = 0; a < 2; ++a)
#pragma unroll
        for (int b = 0; b < 4; ++b)
#pragma unroll
            for (int c = 0; c < 4; ++c) acc[a][b][c] = 0.f;

    issueB(0, 0);
    for (int s = 0; s < NSTAGE; ++s) {
        if (s + 1 < NSTAGE) { issueB(s + 1, (s + 1) & 1); CPWAIT1(); }
        else CPWAIT0();
        __syncthreads();
        const float* Bb = Bs + (s & 1) * 2304;
        int mm_ = (mode == 0) ? (s >> 1) : 0;
        int base = ((mode == 0) ? (s & 1) : s) << 5;
        int rsh = 2 * mm_;   // mode1: mm_=0

        uint4 Aq[2][4];
#pragma unroll
        for (int mi = 0; mi < 2; ++mi) {
            int rr = wm * 32 + mi * 16 + gi + rsh;
            const uint4* p0 = (const uint4*)(Xs + rr * 68 + base) + 2 * ci;
            const uint4* p8 = (const uint4*)(Xs + (rr + 8) * 68 + base) + 2 * ci;
            Aq[mi][0] = p0[0]; Aq[mi][1] = p0[1];
            Aq[mi][2] = p8[0]; Aq[mi][3] = p8[1];
        }
#pragma unroll
        for (int ni = 0; ni < 4; ++ni) {
            int n = wn * 32 + ni * 8 + gi;
            const uint4* pb = (const uint4*)(Bb + n * 36) + 2 * ci;
            uint4 B0 = pb[0], B1 = pb[1];
#pragma unroll
            for (int mi = 0; mi < 2; ++mi) {
                mma8(acc[mi][ni], Aq[mi][0].x, Aq[mi][2].x, Aq[mi][0].y, Aq[mi][2].y, B0.x, B0.y);
                mma8(acc[mi][ni], Aq[mi][0].z, Aq[mi][2].z, Aq[mi][0].w, Aq[mi][2].w, B0.z, B0.w);
                mma8(acc[mi][ni], Aq[mi][1].x, Aq[mi][3].x, Aq[mi][1].y, Aq[mi][3].y, B1.x, B1.y);
                mma8(acc[mi][ni], Aq[mi][1].z, Aq[mi][3].z, Aq[mi][1].w, Aq[mi][3].w, B1.z, B1.w);
            }
        }
        __syncthreads();
    }

    if (mode == 0 || n0 >= 512) {
        // ---- staged, coalesced epilogue (q / k / l) ----
        float* Cs = sm;        // 128 x 65 floats (reuses X tile; mainloop done)
#pragma unroll
        for (int mi = 0; mi < 2; ++mi)
#pragma unroll
            for (int ni = 0; ni < 4; ++ni)
#pragma unroll
                for (int j = 0; j < 4; ++j) {
                    int ml = wm * 32 + mi * 16 + gi + ((j >= 2) ? 8 : 0);
                    int nl = wn * 32 + ni * 8 + 2 * ci + (j & 1);
                    float v = acc[mi][ni][j];
                    float s;
                    if (mode == 0) {
                        int n = n0 + nl;
                        float bias = (n < 512) ? bias0[n] : bias1[n - 512];
                        s = tf32r(silu_fast(v + bias) * 0.35355339059327373f);
                    } else {
                        s = tf32r(silu_fast(v));
                    }
                    Cs[ml * 65 + nl] = s;
                }
        __syncthreads();
        float* dst = (mode == 0) ? ((n0 < 512) ? g_q : g_k) : g_l;
        int ki0 = (n0 & 511) >> 3;          // multiple of 8
        int gg = bi * 8 + (tibase >> 7);
        int q = tid >> 1;
        int hb = (tid & 1) * 4;
        const float* Cq = Cs + q * 65;
        size_t rb = (size_t)gg * TLEN * KD;
#pragma unroll
        for (int h = hb; h < hb + 4; ++h) {
            float4 lo = make_float4(Cq[h], Cq[8 + h], Cq[16 + h], Cq[24 + h]);
            float4 hi4 = make_float4(Cq[32 + h], Cq[40 + h], Cq[48 + h], Cq[56 + h]);
            float* drow = dst + rb + (size_t)(q * 8 + h) * KD + ki0;
            *(float4*)drow = lo;
            *(float4*)(drow + 4) = hi4;
        }
    } else {
        // ---- mode1 V: permuted layout, direct stores ----
#pragma unroll
        for (int mi = 0; mi < 2; ++mi)
#pragma unroll
            for (int ni = 0; ni < 4; ++ni)
#pragma unroll
                for (int j = 0; j < 4; ++j) {
                    int m = m0 + wm * 32 + mi * 16 + gi + ((j >= 2) ? 8 : 0);
                    int n = n0 + wn * 32 + ni * 8 + 2 * ci + (j & 1);
                    float s = silu_fast(acc[mi][ni][j]);
                    int o = n & 511, ki = o >> 3, h = o & 7;
                    int bb = m >> 10, ti = m & 1023;
                    int gg = bb * 8 + (ti >> 7);
                    int tj = ((ti & 127) << 3) | h;
                    g_v[((size_t)gg * KD + ki) * TLEN + (tj & ~63) + pqk(nom64(tj & 63))] = tf32r(s);
                }
    }
}

// ---------------- flash attention + local attention (merged launch) ------------
__global__ __launch_bounds__(256, 2) void flash_mma_kernel()
{
    extern __shared__ float sm[];
    int g  = blockIdx.x;
    int p  = blockIdx.y;
    int tid = threadIdx.x, lane = tid & 31, wid = tid >> 5;

    if (p >= 8) {
        // ================= local windowed causal attention =================
        int t0 = (p - 8) * 256;
        const float* Lg = g_l + (size_t)g * (TLEN * KD);
        for (int i = tid; i < 261 * 16; i += 256) {
            int r = i >> 4, c4 = (i & 15) << 2;
            int tg = t0 - 5 + r;
            float4 v = make_float4(0.f, 0.f, 0.f, 0.f);
            if (tg >= 0) v = *(const float4*)&Lg[(size_t)tg * 64 + c4];
            *(float4*)&sm[r * 68 + c4] = v;
        }
        __syncthreads();
        int qq = tid >> 2, pi = tid & 3;
#pragma unroll
        for (int pass = 0; pass < 4; ++pass) {
            int q = pass * 64 + qq;
            int tj = t0 + q;
            const float* Lq = sm + (q + 5) * 68;
            float4 xq[4];
#pragma unroll
            for (int i = 0; i < 4; ++i)
                xq[i] = *(const float4*)&Lq[pi * 4 + i * 16];

            float sc[6], mx = -1e30f;
#pragma unroll
            for (int w = 0; w < 6; ++w) {
                const float* Lr = sm + (q + w) * 68;
                float d = 0.f;
#pragma unroll
                for (int i = 0; i < 4; ++i) {
                    float4 rv = *(const float4*)&Lr[pi * 4 + i * 16];
                    d += xq[i].x * rv.x + xq[i].y * rv.y + xq[i].z * rv.z + xq[i].w * rv.w;
                }
                d += __shfl_xor_sync(0xffffffffu, d, 1);
                d += __shfl_xor_sync(0xffffffffu, d, 2);
                sc[w] = (tj - 5 + w >= 0) ? d * 0.125f : -1e30f;
                mx = fmaxf(mx, sc[w]);
            }
            float e[6], den = 0.f;
#pragma unroll
            for (int w = 0; w < 6; ++w) { e[w] = __expf(sc[w] - mx); den += e[w]; }
            float inv = 1.f / den;

            float4 acc[4];
#pragma unroll
            for (int i = 0; i < 4; ++i) acc[i] = make_float4(0.f, 0.f, 0.f, 0.f);
#pragma unroll
            for (int w = 0; w < 6; ++w) {
                float ew = e[w];
                const float* Lr = sm + (q + w) * 68;
#pragma unroll
                for (int i = 0; i < 4; ++i) {
                    float4 rv = *(const float4*)&Lr[pi * 4 + i * 16];
                    acc[i].x += ew * rv.x; acc[i].y += ew * rv.y;
                    acc[i].z += ew * rv.z; acc[i].w += ew * rv.w;
                }
            }
            float* Og = g_ol + (size_t)g * (TLEN * KD) + (size_t)tj * 64;
#pragma unroll
            for (int i = 0; i < 4; ++i) {
                float4 t;
                t.x = acc[i].x * inv; t.y = acc[i].y * inv;
                t.z = acc[i].z * inv; t.w = acc[i].w * inv;
                *(float4*)&Og[pi * 4 + i * 16] = t;
            }
        }
        return;
    }

    // ========================= flash attention (v5) =========================
    int qa = p, qb = 15 - p;
    int gi = lane >> 2, ci = lane & 3;
    int wa = wid & 3;
    bool grpB = wid >= 4;
    int barid = grpB ? 2 : 1;
    int Na = p + 1;
    int NIT = grpB ? 9 : 8;
    uint32_t sb = (uint32_t)__cvta_generic_to_shared(sm);
    int KO = grpB ? 12288 : 0;
    int VO = KO + 8192;
    int lt = wa * 32 + lane;

    int offw[4];
#pragma unroll
    for (int t4 = 0; t4 < 4; ++t4)
        offw[t4] = (((2 * ci + (t4 & 1) + ((t4 >> 1) << 3)) ^ gi) << 2);

    const float* Qg  = g_q + (size_t)g * (TLEN * KD);
    const float* Kg0 = g_k + (size_t)g * (TLEN * KD);
    const float* Vg0 = g_v + (size_t)g * (KD * TLEN);

    int qt = grpB ? qb : qa;
    int qbase = qt * 64 + wa * 16;
    int r0 = qbase + gi;

    uint32_t qf[8][4];
    auto load_qf = [&]() {
#pragma unroll
        for (int t4 = 0; t4 < 4; ++t4) {
            int woff = (2 * ci + (t4 & 1) + ((t4 >> 1) << 3)) << 2;
            float4 lo = *(const float4*)&Qg[(size_t)r0 * KD + woff];
            float4 hi = *(const float4*)&Qg[(size_t)(r0 + 8) * KD + woff];
            int kk0 = ((t4 >> 1) << 2) + ((t4 & 1) << 1);
            qf[kk0][0]     = __float_as_uint(lo.x); qf[kk0][2]     = __float_as_uint(lo.y);
            qf[kk0 + 1][0] = __float_as_uint(lo.z); qf[kk0 + 1][2] = __float_as_uint(lo.w);
            qf[kk0][1]     = __float_as_uint(hi.x); qf[kk0][3]     = __float_as_uint(hi.y);
            qf[kk0 + 1][1] = __float_as_uint(hi.z); qf[kk0 + 1][3] = __float_as_uint(hi.w);
        }
    };
    load_qf();

    float o[8][4];
#pragma unroll
    for (int a = 0; a < 8; ++a)
#pragma unroll
        for (int b = 0; b < 4; ++b) o[a][b] = 0.f;
    float m0v = -1e30f, m1v = -1e30f, l0 = 0.f, l1 = 0.f;

    auto kt_of = [&](int i) {
        if (grpB) return i;
        return (i < Na) ? i : (9 + i - Na);
    };

    auto issueK = [&](int i, int buf) {
        int k0 = kt_of(i) * 64;
#pragma unroll
        for (int j = 0; j < 8; ++j) {
            int f4 = lt + j * 128;
            int row = f4 >> 4, chunk = f4 & 15;
            int swc = chunk ^ (row & 7);
            cp16(sb + (uint32_t)((KO + buf * 4096 + row * 64 + swc * 4) * 4),
                 Kg0 + (size_t)(k0 + row) * 64 + chunk * 4);
        }
        CPCOMMIT();
    };
    auto issueV = [&](int i) {
        int k0 = kt_of(i) * 64;
#pragma unroll
        for (int j = 0; j < 8; ++j) {
            int f4 = lt + j * 128;
            int row = f4 >> 4, chunk = f4 & 15;
            int swc = chunk ^ (row & 7);
            cp16(sb + (uint32_t)((VO + row * 64 + swc * 4) * 4),
                 Vg0 + (size_t)row * TLEN + k0 + chunk * 4);
        }
        CPCOMMIT();
    };

    auto epilogue_store = [&]() {
        float inv0 = 1.f / l0, inv1 = 1.f / l1;
        float* Og = g_og + (size_t)g * (TLEN * KD);
#pragma unroll
        for (int nd = 0; nd < 8; ++nd) {
            int c = nd * 8 + 2 * ci;
            float2 t0; t0.x = o[nd][0] * inv0; t0.y = o[nd][1] * inv0;
            float2 t1; t1.x = o[nd][2] * inv1; t1.y = o[nd][3] * inv1;
            *(float2*)&Og[(size_t)r0 * KD + c] = t0;
            *(float2*)&Og[(size_t)(r0 + 8) * KD + c] = t1;
        }
    };
    auto reset_state = [&]() {
#pragma unroll
        for (int a = 0; a < 8; ++a)
#pragma unroll
            for (int b = 0; b < 4; ++b) o[a][b] = 0.f;
        m0v = -1e30f; m1v = -1e30f; l0 = 0.f; l1 = 0.f;
    };

    issueK(0, 0);
    for (int i = 0; i < NIT; ++i) {
        if (!grpB && i == Na) {
            epilogue_store();
            reset_state();
            qt = qb; qbase = qt * 64 + wa * 16; r0 = qbase + gi;
            load_qf();
        }
        bool more = (i + 1 < NIT);
        issueV(i);
        if (more) issueK(i + 1, (i + 1) & 1);
        if (more) CPWAIT2(); else CPWAIT1();    // K(i) ready
        barg(barid);

        int k0 = kt_of(i) * 64;
        const float* Ks = sm + KO + (i & 1) * 4096;
        const float* Vs = sm + VO;

        float s[8][4];
#pragma unroll
        for (int ni = 0; ni < 8; ++ni) {
            s[ni][0] = s[ni][1] = s[ni][2] = s[ni][3] = 0.f;
            const uint32_t* Krow = (const uint32_t*)(Ks + (ni * 8 + gi) * 64);
#pragma unroll
            for (int t4 = 0; t4 < 4; ++t4) {
                uint4 F = *(const uint4*)(Krow + offw[t4]);
                int kk0 = ((t4 >> 1) << 2) + ((t4 & 1) << 1);
                mma8(s[ni], qf[kk0][0], qf[kk0][1], qf[kk0][2], qf[kk0][3], F.x, F.y);
                mma8(s[ni], qf[kk0 + 1][0], qf[kk0 + 1][1], qf[kk0 + 1][2], qf[kk0 + 1][3], F.z, F.w);
            }
        }
        if (k0 + 63 > qbase) {
#pragma unroll
            for (int ni = 0; ni < 8; ++ni)
#pragma unroll
                for (int j = 0; j < 4; ++j) {
                    int col = k0 + ni * 8 + 2 * ci + (j & 1);
                    int row = r0 + ((j >= 2) ? 8 : 0);
                    if (col > row) s[ni][j] = -1e30f;
                }
        }
        float mx0 = -1e30f, mx1 = -1e30f;
#pragma unroll
        for (int ni = 0; ni < 8; ++ni) {
            mx0 = fmaxf(mx0, fmaxf(s[ni][0], s[ni][1]));
            mx1 = fmaxf(mx1, fmaxf(s[ni][2], s[ni][3]));
        }
        mx0 = fmaxf(mx0, __shfl_xor_sync(0xffffffffu, mx0, 1));
        mx0 = fmaxf(mx0, __shfl_xor_sync(0xffffffffu, mx0, 2));
        mx1 = fmaxf(mx1, __shfl_xor_sync(0xffffffffu, mx1, 1));
        mx1 = fmaxf(mx1, __shfl_xor_sync(0xffffffffu, mx1, 2));
        float m0n = fmaxf(m0v, mx0), m1n = fmaxf(m1v, mx1);
        float corr0 = __expf(m0v - m0n), corr1 = __expf(m1v - m1n);

        float sum0 = 0.f, sum1 = 0.f;
#pragma unroll
        for (int ni = 0; ni < 8; ++ni) {
            s[ni][0] = tf32r(__expf(s[ni][0] - m0n));
            s[ni][1] = tf32r(__expf(s[ni][1] - m0n));
            s[ni][2] = tf32r(__expf(s[ni][2] - m1n));
            s[ni][3] = tf32r(__expf(s[ni][3] - m1n));
            sum0 += s[ni][0] + s[ni][1];
            sum1 += s[ni][2] + s[ni][3];
        }
        sum0 += __shfl_xor_sync(0xffffffffu, sum0, 1);
        sum0 += __shfl_xor_sync(0xffffffffu, sum0, 2);
        sum1 += __shfl_xor_sync(0xffffffffu, sum1, 1);
        sum1 += __shfl_xor_sync(0xffffffffu, sum1, 2);
        l0 = l0 * corr0 + sum0;
        l1 = l1 * corr1 + sum1;
        m0v = m0n; m1v = m1n;
#pragma unroll
        for (int nd = 0; nd < 8; ++nd) {
            o[nd][0] *= corr0; o[nd][1] *= corr0;
            o[nd][2] *= corr1; o[nd][3] *= corr1;
        }
        if (more) CPWAIT1(); else CPWAIT0();    // V(i) ready
        barg(barid);
#pragma unroll
        for (int nd = 0; nd < 8; ++nd) {
            const uint32_t* Vrow = (const uint32_t*)(Vs + (nd * 8 + gi) * 64);
#pragma unroll
            for (int t4 = 0; t4 < 4; ++t4) {
                uint4 F = *(const uint4*)(Vrow + offw[t4]);
                int kg0 = ((t4 >> 1) << 2) + ((t4 & 1) << 1);
                mma8(o[nd], __float_as_uint(s[kg0][0]), __float_as_uint(s[kg0][2]),
                     __float_as_uint(s[kg0][1]), __float_as_uint(s[kg0][3]), F.x, F.y);
                mma8(o[nd], __float_as_uint(s[kg0 + 1][0]), __float_as_uint(s[kg0 + 1][2]),
                     __float_as_uint(s[kg0 + 1][1]), __float_as_uint(s[kg0 + 1][3]), F.z, F.w);
            }
        }
        barg(barid);
    }

    if (!grpB && Na == NIT) {
        epilogue_store();
        reset_state();
        qt = qb; qbase = qt * 64 + wa * 16; r0 = qbase + gi;
    }

    // ---- split-KV merge for q-tile qb
    float* ob = sm + 12288;
    float* mb = sm + 12288 + 4352;
    float* lb = mb + 64;
    if (grpB) {
        int rr = wa * 16 + gi;
#pragma unroll
        for (int nd = 0; nd < 8; ++nd) {
            int c = nd * 8 + 2 * ci;
            *(float2*)&ob[rr * 68 + c]       = make_float2(o[nd][0], o[nd][1]);
            *(float2*)&ob[(rr + 8) * 68 + c] = make_float2(o[nd][2], o[nd][3]);
        }
        if (ci == 0) {
            mb[rr] = m0v; lb[rr] = l0;
            mb[rr + 8] = m1v; lb[rr + 8] = l1;
        }
    }
    __syncthreads();
    if (!grpB) {
        int rr = wa * 16 + gi;
        float mB0 = mb[rr], lB0 = lb[rr], mB1 = mb[rr + 8], lB1 = lb[rr + 8];
        float mS0 = fmaxf(m0v, mB0), mS1 = fmaxf(m1v, mB1);
        float cA0 = __expf(m0v - mS0), cB0 = __expf(mB0 - mS0);
        float cA1 = __expf(m1v - mS1), cB1 = __expf(mB1 - mS1);
        l0 = l0 * cA0 + lB0 * cB0;
        l1 = l1 * cA1 + lB1 * cB1;
#pragma unroll
        for (int nd = 0; nd < 8; ++nd) {
            int c = nd * 8 + 2 * ci;
            float2 b0 = *(float2*)&ob[rr * 68 + c];
            float2 b1 = *(float2*)&ob[(rr + 8) * 68 + c];
            o[nd][0] = o[nd][0] * cA0 + b0.x * cB0;
            o[nd][1] = o[nd][1] * cA0 + b0.y * cB0;
            o[nd][2] = o[nd][2] * cA1 + b1.x * cB1;
            o[nd][3] = o[nd][3] * cA1 + b1.y * cB1;
        }
        epilogue_store();
    }
}

// ---------------- uni projection: fused gating + K-split(8) tf32 GEMM ----------
__global__ __launch_bounds__(256, 2) void unigemm_kernel()
{
    __shared__ float As[128][36];
    __shared__ float Bs[32][68];
    int tid = threadIdx.x, lane = tid & 31, wid = tid >> 5;
    int wm = wid & 3, wn = wid >> 2, gi = lane >> 2, ci = lane & 3;
    int m0 = blockIdx.x * 128;
    int kz = blockIdx.y;
    int bi = m0 >> 10, tib = m0 & 1023;
    uint32_t b_sb = (uint32_t)__cvta_generic_to_shared(&Bs[0][0]);

    float acc[2][4][4];
#pragma unroll
    for (int a = 0; a < 2; ++a)
#pragma unroll
        for (int b = 0; b < 4; ++b)
#pragma unroll
            for (int c = 0; c < 4; ++c) acc[a][b][c] = 0.f;

    for (int s = 0; s < 4; ++s) {
        int k0 = kz * 128 + s * 32;
        int ch = k0 >> 6, ki0 = k0 & 63;
        int h2 = ch & 7;
        bool lohalf = ch < 8;
        const float* Og = g_og + (size_t)(bi * 8 + h2) * (TLEN * KD);
        const float* Lg = g_ol + (size_t)(bi * 8 + h2) * (TLEN * KD);
        __syncthreads();
#pragma unroll
        for (int i = 0; i < 2; ++i) {
            int f4 = tid + i * 256;
            int row = f4 >> 4, c4 = (f4 & 15) << 2;
            cp16(b_sb + (uint32_t)((row * 68 + c4) * 4), g_WU + (size_t)(k0 + row) * 64 + c4);
        }
        CPCOMMIT();
#pragma unroll
        for (int i = 0; i < 4; ++i) {
            int f4 = tid + i * 256;
            int row = f4 >> 3, c4 = (f4 & 7) << 2;
            int ti2 = tib + row;
            const float4 o4 = *(const float4*)(Og + (size_t)ti2 * 64 + ki0 + c4);
            const float4 l4 = *(const float4*)(Lg + (size_t)ti2 * 64 + ki0 + c4);
            float g0 = sigmoid_fast(o4.x), g1 = sigmoid_fast(o4.y);
            float g2 = sigmoid_fast(o4.z), g3 = sigmoid_fast(o4.w);
            float r0 = lohalf ? (1.f - g0) * l4.x : g0 * o4.x;
            float r1 = lohalf ? (1.f - g1) * l4.y : g1 * o4.y;
            float r2 = lohalf ? (1.f - g2) * l4.z : g2 * o4.z;
            float r3 = lohalf ? (1.f - g3) * l4.w : g3 * o4.w;
            As[row][c4 + 0] = tf32r(r0);
            As[row][c4 + 1] = tf32r(r1);
            As[row][c4 + 2] = tf32r(r2);
            As[row][c4 + 3] = tf32r(r3);
        }
        CPWAIT0();
        __syncthreads();
#pragma unroll
        for (int kk = 0; kk < 4; ++kk) {
            int k = kk * 8;
            uint32_t af[2][4];
#pragma unroll
            for (int mi = 0; mi < 2; ++mi) {
                int r = wm * 32 + mi * 16 + gi;
                af[mi][0] = __float_as_uint(As[r][k + ci]);
                af[mi][1] = __float_as_uint(As[r + 8][k + ci]);
                af[mi][2] = __float_as_uint(As[r][k + ci + 4]);
                af[mi][3] = __float_as_uint(As[r + 8][k + ci + 4]);
            }
            uint32_t bf[4][2];
#pragma unroll
            for (int ni = 0; ni < 4; ++ni) {
                int n = wn * 32 + ni * 8 + gi;
                bf[ni][0] = __float_as_uint(Bs[k + ci][n]);
                bf[ni][1] = __float_as_uint(Bs[k + ci + 4][n]);
            }
#pragma unroll
            for (int mi = 0; mi < 2; ++mi)
#pragma unroll
                for (int ni = 0; ni < 4; ++ni)
                    mma8(acc[mi][ni], af[mi][0], af[mi][1], af[mi][2], af[mi][3],
                         bf[ni][0], bf[ni][1]);
        }
    }

    float* P = g_part + ((size_t)kz * MROWS + m0) * 64;
#pragma unroll
    for (int mi = 0; mi < 2; ++mi)
#pragma unroll
        for (int ni = 0; ni < 4; ++ni)
#pragma unroll
            for (int j = 0; j < 4; j += 2) {
                int mrow = wm * 32 + mi * 16 + gi + ((j >= 2) ? 8 : 0);
                int n = wn * 32 + ni * 8 + 2 * ci;
                float2 t; t.x = acc[mi][ni][j]; t.y = acc[mi][ni][j + 1];
                *(float2*)&P[(size_t)mrow * 64 + n] = t;
            }
}

// ---------------- partial-reduce(8) + silu + residual -> LN1 -> FF -> LN2 ------
__global__ __launch_bounds__(256) void ffln_kernel(
    const float* __restrict__ uni_b,
    const float* __restrict__ ln1g, const float* __restrict__ ln1b,
    const float* __restrict__ ln2g, const float* __restrict__ ln2b,
    const float* __restrict__ w1, const float* __restrict__ b1,
    const float* __restrict__ w2, const float* __restrict__ b2,
    float* __restrict__ out)
{
    const int R = 16;
    __shared__ float yl[R][64];
    __shared__ float hs[R][256];
    __shared__ float fs[R][64];
    int r0 = blockIdx.x * R;
    int tid = threadIdx.x;
    int lane = tid & 31, w = tid >> 5;

    for (int rr = 0; rr < 2; ++rr) {
        int r = w * 2 + rr;
        size_t rg = (size_t)(r0 + r) * 64;
        float v0 = 0.f, v1 = 0.f;
#pragma unroll
        for (int kz = 0; kz < 8; ++kz) {
            v0 += g_part[(size_t)kz * MROWS * 64 + rg + lane];
            v1 += g_part[(size_t)kz * MROWS * 64 + rg + lane + 32];
        }
        v0 = silu_fast(v0 + uni_b[lane]) + g_xin[rg + p32(lane)];
        v1 = silu_fast(v1 + uni_b[lane + 32]) + g_xin[rg + 32 + p32(lane)];
        float sm = v0 + v1;
#pragma unroll
        for (int o = 16; o; o >>= 1) sm += __shfl_xor_sync(0xffffffffu, sm, o);
        float mean = sm * (1.f / 64.f);
        float d0 = v0 - mean, d1 = v1 - mean;
        float vs = d0 * d0 + d1 * d1;
#pragma unroll
        for (int o = 16; o; o >>= 1) vs += __shfl_xor_sync(0xffffffffu, vs, o);
        float inv = rsqrtf(vs * (1.f / 64.f) + 1e-5f);
        yl[r][lane]      = d0 * inv * ln1g[lane] + ln1b[lane];
        yl[r][lane + 32] = d1 * inv * ln1g[lane + 32] + ln1b[lane + 32];
    }
    __syncthreads();

    {
        float acc[R];
#pragma unroll
        for (int r = 0; r < R; ++r) acc[r] = b1[tid];
        for (int c = 0; c < 64; ++c) {
            float wv = w1[c * 256 + tid];
#pragma unroll
            for (int r = 0; r < R; ++r) acc[r] += yl[r][c] * wv;
        }
#pragma unroll
        for (int r = 0; r < R; ++r) hs[r][tid] = fmaxf(acc[r], 0.f);
    }
    __syncthreads();

    {
        int j2 = tid & 63, rg = tid >> 6;
        float acc[4];
#pragma unroll
        for (int rr = 0; rr < 4; ++rr) acc[rr] = b2[j2];
        for (int c = 0; c < 256; ++c) {
            float wv = w2[c * 64 + j2];
#pragma unroll
            for (int rr = 0; rr < 4; ++rr) acc[rr] += hs[rg * 4 + rr][c] * wv;
        }
#pragma unroll
        for (int rr = 0; rr < 4; ++rr) fs[rg * 4 + rr][j2] = acc[rr] + yl[rg * 4 + rr][j2];
    }
    __syncthreads();

    for (int rr = 0; rr < 2; ++rr) {
        int r = w * 2 + rr;
        float v0 = fs[r][lane], v1 = fs[r][lane + 32];
        float sm = v0 + v1;
#pragma unroll
        for (int o = 16; o; o >>= 1) sm += __shfl_xor_sync(0xffffffffu, sm, o);
        float mean = sm * (1.f / 64.f);
        float d0 = v0 - mean, d1 = v1 - mean;
        float vs = d0 * d0 + d1 * d1;
#pragma unroll
        for (int o = 16; o; o >>= 1) vs += __shfl_xor_sync(0xffffffffu, vs, o);
        float inv = rsqrtf(vs * (1.f / 64.f) + 1e-5f);
        float* orow = out + (size_t)(r0 + r) * 64;
        orow[lane]      = d0 * inv * ln2g[lane] + ln2b[lane];
        orow[lane + 32] = d1 * inv * ln2g[lane + 32] + ln2b[lane + 32];
    }
}

// ---------------- launch ---------------------------------------------------------
extern "C" void kernel_launch(void* const* d_in, const int* in_sizes, int n_in,
                              void* d_out, int out_size)
{
    (void)in_sizes; (void)n_in; (void)out_size;
    const float* x       = (const float*)d_in[0];
    const float* sq_w    = (const float*)d_in[1];
    const float* bn_g    = (const float*)d_in[2];
    const float* bn_b    = (const float*)d_in[3];
    const float* dw_w    = (const float*)d_in[4];
    const float* ex_w    = (const float*)d_in[5];
    const float* pos_emb = (const float*)d_in[6];
    const float* wq      = (const float*)d_in[7];
    const float* bq      = (const float*)d_in[8];
    const float* wk      = (const float*)d_in[9];
    const float* bk      = (const float*)d_in[10];
    const float* wv      = (const float*)d_in[11];
    const float* wl      = (const float*)d_in[12];
    const float* uni_w   = (const float*)d_in[13];
    const float* uni_b   = (const float*)d_in[14];
    const float* ln1_g   = (const float*)d_in[15];
    const float* ln1_b   = (const float*)d_in[16];
    const float* ln2_g   = (const float*)d_in[17];
    const float* ln2_b   = (const float*)d_in[18];
    const float* ff_w1   = (const float*)d_in[19];
    const float* ff_b1   = (const float*)d_in[20];
    const float* ff_w2   = (const float*)d_in[21];
    const float* ff_b2   = (const float*)d_in[22];
    float* out = (float*)d_out;

    const int CONV_SMEM  = (9248 + 2 * 64 * 36) * 4;           // 55424
    const int FLASH_SMEM = 24576 * 4;                          // 98304 (2 blocks/SM)
    cudaFuncSetAttribute(convgemm_kernel, cudaFuncAttributeMaxDynamicSharedMemorySize, CONV_SMEM);
    cudaFuncSetAttribute(flash_mma_kernel, cudaFuncAttributeMaxDynamicSharedMemorySize, FLASH_SMEM);

    fused_xin_kernel<<<dim3(4, 32), 256>>>(x, sq_w, bn_g, bn_b, dw_w, ex_w, pos_emb);
    prep_wqk_kernel<<<1280, 256>>>(wq, wk);
    prep_wvl_uni_kernel<<<512, 256>>>(wv, wl, uni_w);

    convgemm_kernel<<<dim3(32, 16, 2), 256, CONV_SMEM>>>(bq, bk);   // profiled slot

    flash_mma_kernel<<<dim3(32, 12), 256, FLASH_SMEM>>>();          // flash + local

    unigemm_kernel<<<dim3(32, 8), 256>>>();

    ffln_kernel<<<256, 256>>>(uni_b, ln1_g, ln1_b, ln2_g, ln2_b,
                              ff_w1, ff_b1, ff_w2, ff_b2, out);
}

// round 14
// speedup vs baseline: 1.2214x; 1.0414x over previous
#include <cuda_runtime.h>
#include <math.h>
#include <stdint.h>

// Problem constants (fixed by setup_inputs)
#define BATCH 4
#define TLEN  1024
#define KD    64
#define HNUM  8
#define R32   32
#define NSEQ  32      // BATCH*HNUM
#define MROWS 4096    // BATCH*TLEN

// ---------------- scratch (static device globals; no allocation) --------------
__device__ float g_xin[BATCH * TLEN * KD];          // [b][t][ (c&32)|p32(c&31) ] tf32-exact
__device__ float g_WB[1024 * 320];                  // [n][kcol: per-32 p32] wq|wk, tf32-exact
__device__ float g_WB2[1024 * 64];                  // [n][c: per-32 p32] wv|wl, tf32-exact
__device__ float g_WU[1024 * 64];                   // uni_w, tf32-exact
__device__ float g_q[NSEQ * TLEN * KD];             // [g][t][d] identity words, tf32-exact
__device__ float g_k[NSEQ * TLEN * KD];             // [g][t][d] identity words
__device__ float g_v[NSEQ * KD * TLEN];             // [g][d][t: 64-tilewise pqk(nom64(key))]
__device__ float g_l[NSEQ * TLEN * KD];             // natural
__device__ float g_og[NSEQ * TLEN * KD];
__device__ float g_ol[NSEQ * TLEN * KD];
__device__ float g_part[8 * MROWS * KD];            // uni GEMM K-split partials (8-way)

__device__ __forceinline__ float sigmoid_exact(float x) { return 1.f / (1.f + expf(-x)); }
__device__ __forceinline__ float sigmoid_fast(float x) {
    float t;
    asm("tanh.approx.f32 %0, %1;" : "=f"(t) : "f"(0.5f * x));
    return 0.5f * t + 0.5f;
}
__device__ __forceinline__ float silu_fast(float x) { return x * sigmoid_fast(x); }

// round f32 -> nearest tf32 (result is a valid f32 with low mantissa zeroed)
__device__ __forceinline__ float tf32r(float x) {
    uint32_t u;
    asm("cvt.rna.tf32.f32 %0, %1;" : "=r"(u) : "f"(x));
    return __uint_as_float(u);
}

// fragment-vectorization permutation of a 64-long contraction dim (V keys only)
__device__ __forceinline__ int pqk(int k) {
    return ((k & 3) << 3) | ((k >> 5) << 5) | (((k >> 4) & 1) << 2) |
           (((k >> 3) & 1) << 1) | ((k >> 2) & 1);
}
// within-8 interleave so S C-fragments serve directly as PV A-fragments
__device__ __forceinline__ int nom64(int t) {
    return (t & 56) | ((t >> 1) & 3) | ((t & 1) << 2);
}
// 32-wide contraction permutation (conv GEMM k-dim)
__device__ __forceinline__ int p32(int t) {
    return ((t & 3) << 3) | (((t >> 4) & 1) << 2) | (((t >> 3) & 1) << 1) | ((t >> 2) & 1);
}

__device__ __forceinline__ void mma8(float* c,
                                     uint32_t a0, uint32_t a1, uint32_t a2, uint32_t a3,
                                     uint32_t b0, uint32_t b1) {
    asm volatile(
        "mma.sync.aligned.m16n8k8.row.col.f32.tf32.tf32.f32 "
        "{%0,%1,%2,%3}, {%4,%5,%6,%7}, {%8,%9}, {%0,%1,%2,%3};"
        : "+f"(c[0]), "+f"(c[1]), "+f"(c[2]), "+f"(c[3])
        : "r"(a0), "r"(a1), "r"(a2), "r"(a3), "r"(b0), "r"(b1));
}

__device__ __forceinline__ void cp16(uint32_t dst, const void* src) {
    asm volatile("cp.async.ca.shared.global [%0], [%1], 16;" :: "r"(dst), "l"(src) : "memory");
}
__device__ __forceinline__ void cp16p(uint32_t dst, const void* src, int sz) {
    asm volatile("cp.async.ca.shared.global [%0], [%1], 16, %2;" :: "r"(dst), "l"(src), "r"(sz) : "memory");
}
#define CPCOMMIT() asm volatile("cp.async.commit_group;" ::: "memory")
#define CPWAIT0()  asm volatile("cp.async.wait_group 0;" ::: "memory")
#define CPWAIT1()  asm volatile("cp.async.wait_group 1;" ::: "memory")
#define CPWAIT2()  asm volatile("cp.async.wait_group 2;" ::: "memory")

__device__ __forceinline__ void barg(int id) {
    asm volatile("bar.sync %0, 128;" :: "r"(id) : "memory");
}

// ========== front kernel: xin (blocks 0-127) | wqk prep | wvl/uni prep =========
__global__ __launch_bounds__(256) void front_kernel(
    const float* __restrict__ x, const float* __restrict__ sq_w,
    const float* __restrict__ bn_g, const float* __restrict__ bn_b,
    const float* __restrict__ dw_w, const float* __restrict__ ex_w,
    const float* __restrict__ pos_emb,
    const float* __restrict__ wq, const float* __restrict__ wk,
    const float* __restrict__ wv, const float* __restrict__ wl,
    const float* __restrict__ uni_w)
{
    __shared__ float xs[34][68];
    __shared__ float x3s[34][36];
    __shared__ float xp3[32][32];
    __shared__ float sqT[64][32];
    __shared__ float exT[32][64];
    __shared__ float bng_s[32], bnb_s[32];

    int bid = blockIdx.x;
    int tid = threadIdx.x;

    if (bid >= 128) {
        if (bid < 1408) {        // wq|wk reorder (1280 blocks)
            int idx = (bid - 128) * 256 + tid;
            int n = idx & 1023, kcol = idx >> 10;      // kcol tap-major: mm*64 + c
            int mm = kcol >> 6, c = kcol & 63;
            float w = (n < 512) ? wq[n * 320 + c * 5 + mm] : wk[(n - 512) * 320 + c * 5 + mm];
            g_WB[(size_t)n * 320 + (kcol & ~31) + p32(kcol & 31)] = tf32r(w);
        } else {                  // wv|wl + uni (512 blocks)
            int idx = (bid - 1408) * 256 + tid;
            if (idx < 65536) {
                int n = idx & 1023, c = idx >> 10;
                float w = (n < 512) ? wv[n * 64 + c] : wl[(n - 512) * 64 + c];
                g_WB2[(size_t)n * 64 + (c & 32) + p32(c & 31)] = tf32r(w);
            } else {
                int j = idx - 65536;
                g_WU[j] = tf32r(uni_w[j]);
            }
        }
        return;
    }

    // ---- fused action + pos_emb -> xin (p32-permuted, tf32-exact) ----
    int bi = bid >> 5;
    int t0 = (bid & 31) * 32;
    int nrows = min(34, TLEN - t0);

    for (int i = tid; i < nrows * 16; i += 256) {
        int row = i >> 4, c4 = (i & 15) << 2;
        *(float4*)&xs[row][c4] = *(const float4*)&x[((size_t)bi * TLEN + t0 + row) * KD + c4];
    }
    for (int i = tid; i < 2048; i += 256) { int r = i >> 6, c = i & 63; sqT[c][r] = sq_w[i]; }
    for (int i = tid; i < 2048; i += 256) { int c = i >> 5, r = i & 31; exT[r][c] = ex_w[i]; }
    if (tid < 32) { bng_s[tid] = bn_g[tid] * 0.9999950000374997f; bnb_s[tid] = bn_b[tid]; }
    __syncthreads();

    {
        int j = tid >> 2, rg = (tid & 3) << 3;
        if (j < nrows) {
            float acc[8];
#pragma unroll
            for (int i = 0; i < 8; ++i) acc[i] = 0.f;
#pragma unroll
            for (int c4 = 0; c4 < 64; c4 += 4) {
                float4 xv = *(const float4*)&xs[j][c4];
#pragma unroll
                for (int t = 0; t < 4; ++t) {
                    float xc = (t == 0) ? xv.x : (t == 1) ? xv.y : (t == 2) ? xv.z : xv.w;
                    float4 s0 = *(const float4*)&sqT[c4 + t][rg];
                    float4 s1 = *(const float4*)&sqT[c4 + t][rg + 4];
                    acc[0] += xc * s0.x; acc[1] += xc * s0.y;
                    acc[2] += xc * s0.z; acc[3] += xc * s0.w;
                    acc[4] += xc * s1.x; acc[5] += xc * s1.y;
                    acc[6] += xc * s1.z; acc[7] += xc * s1.w;
                }
            }
#pragma unroll
            for (int i = 0; i < 8; ++i)
                x3s[j][rg + i] = acc[i] * bng_s[rg + i] + bnb_s[rg + i];
        }
    }
    __syncthreads();

    for (int idx = tid; idx < 32 * 32; idx += 256) {
        int r = idx & 31, jj = idx >> 5;
        int pos = t0 + jj;
        float base = x3s[jj][r];
        float v;
        if (pos == TLEN - 1) {
            v = base;
        } else {
            float d0 = dw_w[r * 3 + 0], d1 = dw_w[r * 3 + 1], d2 = dw_w[r * 3 + 2];
            float a = base * d0 + x3s[jj + 1][r] * d1 +
                      ((pos + 2 < TLEN) ? x3s[jj + 2][r] * d2 : 0.f);
            v = a - base;
        }
        xp3[jj][r] = v;
    }
    __syncthreads();

    for (int idx = tid; idx < 32 * 64; idx += 256) {
        int c = idx & 63, j = idx >> 6;
        int pos = t0 + j;
        float gsum = 0.f;
#pragma unroll
        for (int r = 0; r < R32; ++r) gsum += xp3[j][r] * exT[r][c];
        float sig = sigmoid_exact(gsum);
        size_t off = ((size_t)bi * TLEN + pos) * KD + ((c & 32) | p32(c & 31));
        g_xin[off] = tf32r(xs[j][c] * sig + pos_emb[pos * KD + c]);
    }
}

// ---------------- conv GEMMs: 128x128 tiles, resident A, dbl-buffered B --------
// Grid (32, 8, 2). Warp tile 32x64 (wm 0..3, wn 0..1), acc[2][8][4].
__global__ __launch_bounds__(256, 2) void convgemm_kernel(
    const float* __restrict__ bias0, const float* __restrict__ bias1)
{
    int mode = blockIdx.z;
    const int NSTAGE = (mode == 0) ? 10 : 2;
    extern __shared__ float sm[];
    float* Xs = sm;                   // up to 136 x 68 = 9248 floats
    float* Bs = sm + 9248;            // 2 x 128x36 = 9216 floats
    const float* __restrict__ Bg = (mode == 0) ? g_WB : g_WB2;
    const int BK = (mode == 0) ? 320 : 64;

    int tid = threadIdx.x, lane = tid & 31, wid = tid >> 5;
    int wm = wid & 3, wn = wid >> 2, gi = lane >> 2, ci = lane & 3;
    int m0 = blockIdx.x * 128, n0 = blockIdx.y * 128;
    int bi = m0 >> 10, tibase = m0 & 1023;
    uint32_t sb = (uint32_t)__cvta_generic_to_shared(sm);
    uint32_t x_sb = sb, b_sb = sb + 9248 * 4;

    int nxrows = (mode == 0) ? 136 : 128;
    int rowoff = (mode == 0) ? 8 : 0;

    // one-time resident X tile load
    for (int i = tid; i < nxrows * 16; i += 256) {
        int rr = i >> 4, c4 = (i & 15) << 2;
        int tsrc = tibase + rr - rowoff;
        const float* srcp = g_xin + ((size_t)(bi << 10) + tsrc) * 64 + c4;
        cp16p(x_sb + (uint32_t)((rr * 68 + c4) * 4), srcp, (tsrc >= 0) ? 16 : 0);
    }
    CPCOMMIT();

    auto issueB = [&](int s_, int buf_) {
#pragma unroll
        for (int i_ = 0; i_ < 4; ++i_) {
            int f4 = tid + i_ * 256;             // 0..1023
            int rowN = f4 >> 3, c4 = (f4 & 7) << 2;
            const float* srcp = Bg + (size_t)(n0 + rowN) * BK + s_ * 32 + c4;
            uint32_t dstp = b_sb + (uint32_t)((buf_ * 4608 + rowN * 36 + c4) * 4);
            cp16(dstp, srcp);
        }
        CPCOMMIT();
    };

    float acc[2][8][4];
#pragma unroll
    for (int a = 0; a < 2; ++a)
#pragma unroll
        for (int b = 0; b < 8; ++b)
#pragma unroll
            for (int c = 0; c < 4; ++c) acc[a][b][c] = 0.f;

    issueB(0, 0);
    for (int s = 0; s < NSTAGE; ++s) {
        if (s + 1 < NSTAGE) { issueB(s + 1, (s + 1) & 1); CPWAIT1(); }
        else CPWAIT0();
        __syncthreads();
        const float* Bb = Bs + (s & 1) * 4608;
        int mm_ = (mode == 0) ? (s >> 1) : 0;
        int base = ((mode == 0) ? (s & 1) : s) << 5;
        int rsh = 2 * mm_;   // mode1: mm_=0

        uint4 Aq[2][4];
#pragma unroll
        for (int mi = 0; mi < 2; ++mi) {
            int rr = wm * 32 + mi * 16 + gi + rsh;
            const uint4* p0 = (const uint4*)(Xs + rr * 68 + base) + 2 * ci;
            const uint4* p8 = (const uint4*)(Xs + (rr + 8) * 68 + base) + 2 * ci;
            Aq[mi][0] = p0[0]; Aq[mi][1] = p0[1];
            Aq[mi][2] = p8[0]; Aq[mi][3] = p8[1];
        }
#pragma unroll
        for (int ni = 0; ni < 8; ++ni) {
            int n = wn * 64 + ni * 8 + gi;
            const uint4* pb = (const uint4*)(Bb + n * 36) + 2 * ci;
            uint4 B0 = pb[0], B1 = pb[1];
#pragma unroll
            for (int mi = 0; mi < 2; ++mi) {
                mma8(acc[mi][ni], Aq[mi][0].x, Aq[mi][2].x, Aq[mi][0].y, Aq[mi][2].y, B0.x, B0.y);
                mma8(acc[mi][ni], Aq[mi][0].z, Aq[mi][2].z, Aq[mi][0].w, Aq[mi][2].w, B0.z, B0.w);
                mma8(acc[mi][ni], Aq[mi][1].x, Aq[mi][3].x, Aq[mi][1].y, Aq[mi][3].y, B1.x, B1.y);
                mma8(acc[mi][ni], Aq[mi][1].z, Aq[mi][3].z, Aq[mi][1].w, Aq[mi][3].w, B1.z, B1.w);
            }
        }
        __syncthreads();
    }

    if (mode == 0 || n0 >= 512) {
        // ---- staged, coalesced epilogue (q / k / l) ----
        float* Cs = sm;        // 128 x 130 floats (reuses X+B; mainloop done)
#pragma unroll
        for (int mi = 0; mi < 2; ++mi)
#pragma unroll
            for (int ni = 0; ni < 8; ++ni)
#pragma unroll
                for (int j = 0; j < 4; ++j) {
                    int ml = wm * 32 + mi * 16 + gi + ((j >= 2) ? 8 : 0);
                    int nl = wn * 64 + ni * 8 + 2 * ci + (j & 1);
                    float v = acc[mi][ni][j];
                    float s;
                    if (mode == 0) {
                        int n = n0 + nl;
                        float bias = (n < 512) ? bias0[n] : bias1[n - 512];
                        s = tf32r(silu_fast(v + bias) * 0.35355339059327373f);
                    } else {
                        s = tf32r(silu_fast(v));
                    }
                    Cs[ml * 130 + nl] = s;
                }
        __syncthreads();
        float* dst = (mode == 0) ? ((n0 < 512) ? g_q : g_k) : g_l;
        int ki0 = (n0 & 511) >> 3;          // multiple of 16
        int gg = bi * 8 + (tibase >> 7);
        int q = tid >> 1;
        int hb = (tid & 1) * 4;
        const float* Cq = Cs + q * 130;
        size_t rb = (size_t)gg * TLEN * KD;
#pragma unroll
        for (int h = hb; h < hb + 4; ++h) {
            float* drow = dst + rb + (size_t)(q * 8 + h) * KD + ki0;
#pragma unroll
            for (int j4 = 0; j4 < 4; ++j4) {
                float4 t = make_float4(Cq[(4 * j4 + 0) * 8 + h], Cq[(4 * j4 + 1) * 8 + h],
                                       Cq[(4 * j4 + 2) * 8 + h], Cq[(4 * j4 + 3) * 8 + h]);
                *(float4*)(drow + 4 * j4) = t;
            }
        }
    } else {
        // ---- mode1 V: permuted layout, direct stores ----
#pragma unroll
        for (int mi = 0; mi < 2; ++mi)
#pragma unroll
            for (int ni = 0; ni < 8; ++ni)
#pragma unroll
                for (int j = 0; j < 4; ++j) {
                    int m = m0 + wm * 32 + mi * 16 + gi + ((j >= 2) ? 8 : 0);
                    int n = n0 + wn * 64 + ni * 8 + 2 * ci + (j & 1);
                    float s = silu_fast(acc[mi][ni][j]);
                    int o = n & 511, ki = o >> 3, h = o & 7;
                    int bb = m >> 10, ti = m & 1023;
                    int gg = bb * 8 + (ti >> 7);
                    int tj = ((ti & 127) << 3) | h;
                    g_v[((size_t)gg * KD + ki) * TLEN + (tj & ~63) + pqk(nom64(tj & 63))] = tf32r(s);
                }
    }
}

// ---------------- flash attention + local attention (merged launch) ------------
__global__ __launch_bounds__(256, 2) void flash_mma_kernel()
{
    extern __shared__ float sm[];
    int g  = blockIdx.x;
    int p  = blockIdx.y;
    int tid = threadIdx.x, lane = tid & 31, wid = tid >> 5;

    if (p >= 8) {
        // ================= local windowed causal attention =================
        int t0 = (p - 8) * 256;
        const float* Lg = g_l + (size_t)g * (TLEN * KD);
        for (int i = tid; i < 261 * 16; i += 256) {
            int r = i >> 4, c4 = (i & 15) << 2;
            int tg = t0 - 5 + r;
            float4 v = make_float4(0.f, 0.f, 0.f, 0.f);
            if (tg >= 0) v = *(const float4*)&Lg[(size_t)tg * 64 + c4];
            *(float4*)&sm[r * 68 + c4] = v;
        }
        __syncthreads();
        int qq = tid >> 2, pi = tid & 3;
#pragma unroll
        for (int pass = 0; pass < 4; ++pass) {
            int q = pass * 64 + qq;
            int tj = t0 + q;
            const float* Lq = sm + (q + 5) * 68;
            float4 xq[4];
#pragma unroll
            for (int i = 0; i < 4; ++i)
                xq[i] = *(const float4*)&Lq[pi * 4 + i * 16];

            float sc[6], mx = -1e30f;
#pragma unroll
            for (int w = 0; w < 6; ++w) {
                const float* Lr = sm + (q + w) * 68;
                float d = 0.f;
#pragma unroll
                for (int i = 0; i < 4; ++i) {
                    float4 rv = *(const float4*)&Lr[pi * 4 + i * 16];
                    d += xq[i].x * rv.x + xq[i].y * rv.y + xq[i].z * rv.z + xq[i].w * rv.w;
                }
                d += __shfl_xor_sync(0xffffffffu, d, 1);
                d += __shfl_xor_sync(0xffffffffu, d, 2);
                sc[w] = (tj - 5 + w >= 0) ? d * 0.125f : -1e30f;
                mx = fmaxf(mx, sc[w]);
            }
            float e[6], den = 0.f;
#pragma unroll
            for (int w = 0; w < 6; ++w) { e[w] = __expf(sc[w] - mx); den += e[w]; }
            float inv = 1.f / den;

            float4 acc[4];
#pragma unroll
            for (int i = 0; i < 4; ++i) acc[i] = make_float4(0.f, 0.f, 0.f, 0.f);
#pragma unroll
            for (int w = 0; w < 6; ++w) {
                float ew = e[w];
                const float* Lr = sm + (q + w) * 68;
#pragma unroll
                for (int i = 0; i < 4; ++i) {
                    float4 rv = *(const float4*)&Lr[pi * 4 + i * 16];
                    acc[i].x += ew * rv.x; acc[i].y += ew * rv.y;
                    acc[i].z += ew * rv.z; acc[i].w += ew * rv.w;
                }
            }
            float* Og = g_ol + (size_t)g * (TLEN * KD) + (size_t)tj * 64;
#pragma unroll
            for (int i = 0; i < 4; ++i) {
                float4 t;
                t.x = acc[i].x * inv; t.y = acc[i].y * inv;
                t.z = acc[i].z * inv; t.w = acc[i].w * inv;
                *(float4*)&Og[pi * 4 + i * 16] = t;
            }
        }
        return;
    }

    // ========================= flash attention (v5) =========================
    int qa = p, qb = 15 - p;
    int gi = lane >> 2, ci = lane & 3;
    int wa = wid & 3;
    bool grpB = wid >= 4;
    int barid = grpB ? 2 : 1;
    int Na = p + 1;
    int NIT = grpB ? 9 : 8;
    uint32_t sb = (uint32_t)__cvta_generic_to_shared(sm);
    int KO = grpB ? 12288 : 0;
    int VO = KO + 8192;
    int lt = wa * 32 + lane;

    int offw[4];
#pragma unroll
    for (int t4 = 0; t4 < 4; ++t4)
        offw[t4] = (((2 * ci + (t4 & 1) + ((t4 >> 1) << 3)) ^ gi) << 2);

    const float* Qg  = g_q + (size_t)g * (TLEN * KD);
    const float* Kg0 = g_k + (size_t)g * (TLEN * KD);
    const float* Vg0 = g_v + (size_t)g * (KD * TLEN);

    int qt = grpB ? qb : qa;
    int qbase = qt * 64 + wa * 16;
    int r0 = qbase + gi;

    uint32_t qf[8][4];
    auto load_qf = [&]() {
#pragma unroll
        for (int t4 = 0; t4 < 4; ++t4) {
            int woff = (2 * ci + (t4 & 1) + ((t4 >> 1) << 3)) << 2;
            float4 lo = *(const float4*)&Qg[(size_t)r0 * KD + woff];
            float4 hi = *(const float4*)&Qg[(size_t)(r0 + 8) * KD + woff];
            int kk0 = ((t4 >> 1) << 2) + ((t4 & 1) << 1);
            qf[kk0][0]     = __float_as_uint(lo.x); qf[kk0][2]     = __float_as_uint(lo.y);
            qf[kk0 + 1][0] = __float_as_uint(lo.z); qf[kk0 + 1][2] = __float_as_uint(lo.w);
            qf[kk0][1]     = __float_as_uint(hi.x); qf[kk0][3]     = __float_as_uint(hi.y);
            qf[kk0 + 1][1] = __float_as_uint(hi.z); qf[kk0 + 1][3] = __float_as_uint(hi.w);
        }
    };
    load_qf();

    float o[8][4];
#pragma unroll
    for (int a = 0; a < 8; ++a)
#pragma unroll
        for (int b = 0; b < 4; ++b) o[a][b] = 0.f;
    float m0v = -1e30f, m1v = -1e30f, l0 = 0.f, l1 = 0.f;

    auto kt_of = [&](int i) {
        if (grpB) return i;
        return (i < Na) ? i : (9 + i - Na);
    };

    auto issueK = [&](int i, int buf) {
        int k0 = kt_of(i) * 64;
#pragma unroll
        for (int j = 0; j < 8; ++j) {
            int f4 = lt + j * 128;
            int row = f4 >> 4, chunk = f4 & 15;
            int swc = chunk ^ (row & 7);
            cp16(sb + (uint32_t)((KO + buf * 4096 + row * 64 + swc * 4) * 4),
                 Kg0 + (size_t)(k0 + row) * 64 + chunk * 4);
        }
        CPCOMMIT();
    };
    auto issueV = [&](int i) {
        int k0 = kt_of(i) * 64;
#pragma unroll
        for (int j = 0; j < 8; ++j) {
            int f4 = lt + j * 128;
            int row = f4 >> 4, chunk = f4 & 15;
            int swc = chunk ^ (row & 7);
            cp16(sb + (uint32_t)((VO + row * 64 + swc * 4) * 4),
                 Vg0 + (size_t)row * TLEN + k0 + chunk * 4);
        }
        CPCOMMIT();
    };

    auto epilogue_store = [&]() {
        float inv0 = 1.f / l0, inv1 = 1.f / l1;
        float* Og = g_og + (size_t)g * (TLEN * KD);
#pragma unroll
        for (int nd = 0; nd < 8; ++nd) {
            int c = nd * 8 + 2 * ci;
            float2 t0; t0.x = o[nd][0] * inv0; t0.y = o[nd][1] * inv0;
            float2 t1; t1.x = o[nd][2] * inv1; t1.y = o[nd][3] * inv1;
            *(float2*)&Og[(size_t)r0 * KD + c] = t0;
            *(float2*)&Og[(size_t)(r0 + 8) * KD + c] = t1;
        }
    };
    auto reset_state = [&]() {
#pragma unroll
        for (int a = 0; a < 8; ++a)
#pragma unroll
            for (int b = 0; b < 4; ++b) o[a][b] = 0.f;
        m0v = -1e30f; m1v = -1e30f; l0 = 0.f; l1 = 0.f;
    };

    issueK(0, 0);
    for (int i = 0; i < NIT; ++i) {
        if (!grpB && i == Na) {
            epilogue_store();
            reset_state();
            qt = qb; qbase = qt * 64 + wa * 16; r0 = qbase + gi;
            load_qf();
        }
        bool more = (i + 1 < NIT);
        issueV(i);
        if (more) issueK(i + 1, (i + 1) & 1);
        if (more) CPWAIT2(); else CPWAIT1();    // K(i) ready
        barg(barid);

        int k0 = kt_of(i) * 64;
        const float* Ks = sm + KO + (i & 1) * 4096;
        const float* Vs = sm + VO;

        float s[8][4];
#pragma unroll
        for (int ni = 0; ni < 8; ++ni) {
            s[ni][0] = s[ni][1] = s[ni][2] = s[ni][3] = 0.f;
            const uint32_t* Krow = (const uint32_t*)(Ks + (ni * 8 + gi) * 64);
#pragma unroll
            for (int t4 = 0; t4 < 4; ++t4) {
                uint4 F = *(const uint4*)(Krow + offw[t4]);
                int kk0 = ((t4 >> 1) << 2) + ((t4 & 1) << 1);
                mma8(s[ni], qf[kk0][0], qf[kk0][1], qf[kk0][2], qf[kk0][3], F.x, F.y);
                mma8(s[ni], qf[kk0 + 1][0], qf[kk0 + 1][1], qf[kk0 + 1][2], qf[kk0 + 1][3], F.z, F.w);
            }
        }
        if (k0 + 63 > qbase) {
#pragma unroll
            for (int ni = 0; ni < 8; ++ni)
#pragma unroll
                for (int j = 0; j < 4; ++j) {
                    int col = k0 + ni * 8 + 2 * ci + (j & 1);
                    int row = r0 + ((j >= 2) ? 8 : 0);
                    if (col > row) s[ni][j] = -1e30f;
                }
        }
        float mx0 = -1e30f, mx1 = -1e30f;
#pragma unroll
        for (int ni = 0; ni < 8; ++ni) {
            mx0 = fmaxf(mx0, fmaxf(s[ni][0], s[ni][1]));
            mx1 = fmaxf(mx1, fmaxf(s[ni][2], s[ni][3]));
        }
        mx0 = fmaxf(mx0, __shfl_xor_sync(0xffffffffu, mx0, 1));
        mx0 = fmaxf(mx0, __shfl_xor_sync(0xffffffffu, mx0, 2));
        mx1 = fmaxf(mx1, __shfl_xor_sync(0xffffffffu, mx1, 1));
        mx1 = fmaxf(mx1, __shfl_xor_sync(0xffffffffu, mx1, 2));
        float m0n = fmaxf(m0v, mx0), m1n = fmaxf(m1v, mx1);
        float corr0 = __expf(m0v - m0n), corr1 = __expf(m1v - m1n);

        float sum0 = 0.f, sum1 = 0.f;
#pragma unroll
        for (int ni = 0; ni < 8; ++ni) {
            s[ni][0] = tf32r(__expf(s[ni][0] - m0n));
            s[ni][1] = tf32r(__expf(s[ni][1] - m0n));
            s[ni][2] = tf32r(__expf(s[ni][2] - m1n));
            s[ni][3] = tf32r(__expf(s[ni][3] - m1n));
            sum0 += s[ni][0] + s[ni][1];
            sum1 += s[ni][2] + s[ni][3];
        }
        sum0 += __shfl_xor_sync(0xffffffffu, sum0, 1);
        sum0 += __shfl_xor_sync(0xffffffffu, sum0, 2);
        sum1 += __shfl_xor_sync(0xffffffffu, sum1, 1);
        sum1 += __shfl_xor_sync(0xffffffffu, sum1, 2);
        l0 = l0 * corr0 + sum0;
        l1 = l1 * corr1 + sum1;
        m0v = m0n; m1v = m1n;
#pragma unroll
        for (int nd = 0; nd < 8; ++nd) {
            o[nd][0] *= corr0; o[nd][1] *= corr0;
            o[nd][2] *= corr1; o[nd][3] *= corr1;
        }
        if (more) CPWAIT1(); else CPWAIT0();    // V(i) ready
        barg(barid);
#pragma unroll
        for (int nd = 0; nd < 8; ++nd) {
            const uint32_t* Vrow = (const uint32_t*)(Vs + (nd * 8 + gi) * 64);
#pragma unroll
            for (int t4 = 0; t4 < 4; ++t4) {
                uint4 F = *(const uint4*)(Vrow + offw[t4]);
                int kg0 = ((t4 >> 1) << 2) + ((t4 & 1) << 1);
                mma8(o[nd], __float_as_uint(s[kg0][0]), __float_as_uint(s[kg0][2]),
                     __float_as_uint(s[kg0][1]), __float_as_uint(s[kg0][3]), F.x, F.y);
                mma8(o[nd], __float_as_uint(s[kg0 + 1][0]), __float_as_uint(s[kg0 + 1][2]),
                     __float_as_uint(s[kg0 + 1][1]), __float_as_uint(s[kg0 + 1][3]), F.z, F.w);
            }
        }
        barg(barid);
    }

    if (!grpB && Na == NIT) {
        epilogue_store();
        reset_state();
        qt = qb; qbase = qt * 64 + wa * 16; r0 = qbase + gi;
    }

    // ---- split-KV merge for q-tile qb
    float* ob = sm + 12288;
    float* mb = sm + 12288 + 4352;
    float* lb = mb + 64;
    if (grpB) {
        int rr = wa * 16 + gi;
#pragma unroll
        for (int nd = 0; nd < 8; ++nd) {
            int c = nd * 8 + 2 * ci;
            *(float2*)&ob[rr * 68 + c]       = make_float2(o[nd][0], o[nd][1]);
            *(float2*)&ob[(rr + 8) * 68 + c] = make_float2(o[nd][2], o[nd][3]);
        }
        if (ci == 0) {
            mb[rr] = m0v; lb[rr] = l0;
            mb[rr + 8] = m1v; lb[rr + 8] = l1;
        }
    }
    __syncthreads();
    if (!grpB) {
        int rr = wa * 16 + gi;
        float mB0 = mb[rr], lB0 = lb[rr], mB1 = mb[rr + 8], lB1 = lb[rr + 8];
        float mS0 = fmaxf(m0v, mB0), mS1 = fmaxf(m1v, mB1);
        float cA0 = __expf(m0v - mS0), cB0 = __expf(mB0 - mS0);
        float cA1 = __expf(m1v - mS1), cB1 = __expf(mB1 - mS1);
        l0 = l0 * cA0 + lB0 * cB0;
        l1 = l1 * cA1 + lB1 * cB1;
#pragma unroll
        for (int nd = 0; nd < 8; ++nd) {
            int c = nd * 8 + 2 * ci;
            float2 b0 = *(float2*)&ob[rr * 68 + c];
            float2 b1 = *(float2*)&ob[(rr + 8) * 68 + c];
            o[nd][0] = o[nd][0] * cA0 + b0.x * cB0;
            o[nd][1] = o[nd][1] * cA0 + b0.y * cB0;
            o[nd][2] = o[nd][2] * cA1 + b1.x * cB1;
            o[nd][3] = o[nd][3] * cA1 + b1.y * cB1;
        }
        epilogue_store();
    }
}

// ---------------- uni projection: fused gating + K-split(8) tf32 GEMM ----------
__global__ __launch_bounds__(256, 2) void unigemm_kernel()
{
    __shared__ float As[128][36];
    __shared__ float Bs[32][68];
    int tid = threadIdx.x, lane = tid & 31, wid = tid >> 5;
    int wm = wid & 3, wn = wid >> 2, gi = lane >> 2, ci = lane & 3;
    int m0 = blockIdx.x * 128;
    int kz = blockIdx.y;
    int bi = m0 >> 10, tib = m0 & 1023;
    uint32_t b_sb = (uint32_t)__cvta_generic_to_shared(&Bs[0][0]);

    float acc[2][4][4];
#pragma unroll
    for (int a = 0; a < 2; ++a)
#pragma unroll
        for (int b = 0; b < 4; ++b)
#pragma unroll
            for (int c = 0; c < 4; ++c) acc[a][b][c] = 0.f;

    for (int s = 0; s < 4; ++s) {
        int k0 = kz * 128 + s * 32;
        int ch = k0 >> 6, ki0 = k0 & 63;
        int h2 = ch & 7;
        bool lohalf = ch < 8;
        const float* Og = g_og + (size_t)(bi * 8 + h2) * (TLEN * KD);
        const float* Lg = g_ol + (size_t)(bi * 8 + h2) * (TLEN * KD);
        __syncthreads();
#pragma unroll
        for (int i = 0; i < 2; ++i) {
            int f4 = tid + i * 256;
            int row = f4 >> 4, c4 = (f4 & 15) << 2;
            cp16(b_sb + (uint32_t)((row * 68 + c4) * 4), g_WU + (size_t)(k0 + row) * 64 + c4);
        }
        CPCOMMIT();
#pragma unroll
        for (int i = 0; i < 4; ++i) {
            int f4 = tid + i * 256;
            int row = f4 >> 3, c4 = (f4 & 7) << 2;
            int ti2 = tib + row;
            const float4 o4 = *(const float4*)(Og + (size_t)ti2 * 64 + ki0 + c4);
            const float4 l4 = *(const float4*)(Lg + (size_t)ti2 * 64 + ki0 + c4);
            float g0 = sigmoid_fast(o4.x), g1 = sigmoid_fast(o4.y);
            float g2 = sigmoid_fast(o4.z), g3 = sigmoid_fast(o4.w);
            float r0 = lohalf ? (1.f - g0) * l4.x : g0 * o4.x;
            float r1 = lohalf ? (1.f - g1) * l4.y : g1 * o4.y;
            float r2 = lohalf ? (1.f - g2) * l4.z : g2 * o4.z;
            float r3 = lohalf ? (1.f - g3) * l4.w : g3 * o4.w;
            As[row][c4 + 0] = tf32r(r0);
            As[row][c4 + 1] = tf32r(r1);
            As[row][c4 + 2] = tf32r(r2);
            As[row][c4 + 3] = tf32r(r3);
        }
        CPWAIT0();
        __syncthreads();
#pragma unroll
        for (int kk = 0; kk < 4; ++kk) {
            int k = kk * 8;
            uint32_t af[2][4];
#pragma unroll
            for (int mi = 0; mi < 2; ++mi) {
                int r = wm * 32 + mi * 16 + gi;
                af[mi][0] = __float_as_uint(As[r][k + ci]);
                af[mi][1] = __float_as_uint(As[r + 8][k + ci]);
                af[mi][2] = __float_as_uint(As[r][k + ci + 4]);
                af[mi][3] = __float_as_uint(As[r + 8][k + ci + 4]);
            }
            uint32_t bf[4][2];
#pragma unroll
            for (int ni = 0; ni < 4; ++ni) {
                int n = wn * 32 + ni * 8 + gi;
                bf[ni][0] = __float_as_uint(Bs[k + ci][n]);
                bf[ni][1] = __float_as_uint(Bs[k + ci + 4][n]);
            }
#pragma unroll
            for (int mi = 0; mi < 2; ++mi)
#pragma unroll
                for (int ni = 0; ni < 4; ++ni)
                    mma8(acc[mi][ni], af[mi][0], af[mi][1], af[mi][2], af[mi][3],
                         bf[ni][0], bf[ni][1]);
        }
    }

    float* P = g_part + ((size_t)kz * MROWS + m0) * 64;
#pragma unroll
    for (int mi = 0; mi < 2; ++mi)
#pragma unroll
        for (int ni = 0; ni < 4; ++ni)
#pragma unroll
            for (int j = 0; j < 4; j += 2) {
                int mrow = wm * 32 + mi * 16 + gi + ((j >= 2) ? 8 : 0);
                int n = wn * 32 + ni * 8 + 2 * ci;
                float2 t; t.x = acc[mi][ni][j]; t.y = acc[mi][ni][j + 1];
                *(float2*)&P[(size_t)mrow * 64 + n] = t;
            }
}

// ---------------- partial-reduce(8) + silu + residual -> LN1 -> FF -> LN2 ------
__global__ __launch_bounds__(256) void ffln_kernel(
    const float* __restrict__ uni_b,
    const float* __restrict__ ln1g, const float* __restrict__ ln1b,
    const float* __restrict__ ln2g, const float* __restrict__ ln2b,
    const float* __restrict__ w1, const float* __restrict__ b1,
    const float* __restrict__ w2, const float* __restrict__ b2,
    float* __restrict__ out)
{
    const int R = 16;
    __shared__ float yl[R][64];
    __shared__ float hs[R][256];
    __shared__ float fs[R][64];
    int r0 = blockIdx.x * R;
    int tid = threadIdx.x;
    int lane = tid & 31, w = tid >> 5;

    for (int rr = 0; rr < 2; ++rr) {
        int r = w * 2 + rr;
        size_t rg = (size_t)(r0 + r) * 64;
        float v0 = 0.f, v1 = 0.f;
#pragma unroll
        for (int kz = 0; kz < 8; ++kz) {
            v0 += g_part[(size_t)kz * MROWS * 64 + rg + lane];
            v1 += g_part[(size_t)kz * MROWS * 64 + rg + lane + 32];
        }
        v0 = silu_fast(v0 + uni_b[lane]) + g_xin[rg + p32(lane)];
        v1 = silu_fast(v1 + uni_b[lane + 32]) + g_xin[rg + 32 + p32(lane)];
        float sm = v0 + v1;
#pragma unroll
        for (int o = 16; o; o >>= 1) sm += __shfl_xor_sync(0xffffffffu, sm, o);
        float mean = sm * (1.f / 64.f);
        float d0 = v0 - mean, d1 = v1 - mean;
        float vs = d0 * d0 + d1 * d1;
#pragma unroll
        for (int o = 16; o; o >>= 1) vs += __shfl_xor_sync(0xffffffffu, vs, o);
        float inv = rsqrtf(vs * (1.f / 64.f) + 1e-5f);
        yl[r][lane]      = d0 * inv * ln1g[lane] + ln1b[lane];
        yl[r][lane + 32] = d1 * inv * ln1g[lane + 32] + ln1b[lane + 32];
    }
    __syncthreads();

    {
        float acc[R];
#pragma unroll
        for (int r = 0; r < R; ++r) acc[r] = b1[tid];
        for (int c = 0; c < 64; ++c) {
            float wv = w1[c * 256 + tid];
#pragma unroll
            for (int r = 0; r < R; ++r) acc[r] += yl[r][c] * wv;
        }
#pragma unroll
        for (int r = 0; r < R; ++r) hs[r][tid] = fmaxf(acc[r], 0.f);
    }
    __syncthreads();

    {
        int j2 = tid & 63, rg = tid >> 6;
        float acc[4];
#pragma unroll
        for (int rr = 0; rr < 4; ++rr) acc[rr] = b2[j2];
        for (int c = 0; c < 256; ++c) {
            float wv = w2[c * 64 + j2];
#pragma unroll
            for (int rr = 0; rr < 4; ++rr) acc[rr] += hs[rg * 4 + rr][c] * wv;
        }
#pragma unroll
        for (int rr = 0; rr < 4; ++rr) fs[rg * 4 + rr][j2] = acc[rr] + yl[rg * 4 + rr][j2];
    }
    __syncthreads();

    for (int rr = 0; rr < 2; ++rr) {
        int r = w * 2 + rr;
        float v0 = fs[r][lane], v1 = fs[r][lane + 32];
        float sm = v0 + v1;
#pragma unroll
        for (int o = 16; o; o >>= 1) sm += __shfl_xor_sync(0xffffffffu, sm, o);
        float mean = sm * (1.f / 64.f);
        float d0 = v0 - mean, d1 = v1 - mean;
        float vs = d0 * d0 + d1 * d1;
#pragma unroll
        for (int o = 16; o; o >>= 1) vs += __shfl_xor_sync(0xffffffffu, vs, o);
        float inv = rsqrtf(vs * (1.f / 64.f) + 1e-5f);
        float* orow = out + (size_t)(r0 + r) * 64;
        orow[lane]      = d0 * inv * ln2g[lane] + ln2b[lane];
        orow[lane + 32] = d1 * inv * ln2g[lane + 32] + ln2b[lane + 32];
    }
}

// ---------------- launch ---------------------------------------------------------
extern "C" void kernel_launch(void* const* d_in, const int* in_sizes, int n_in,
                              void* d_out, int out_size)
{
    (void)in_sizes; (void)n_in; (void)out_size;
    const float* x       = (const float*)d_in[0];
    const float* sq_w    = (const float*)d_in[1];
    const float* bn_g    = (const float*)d_in[2];
    const float* bn_b    = (const float*)d_in[3];
    const float* dw_w    = (const float*)d_in[4];
    const float* ex_w    = (const float*)d_in[5];
    const float* pos_emb = (const float*)d_in[6];
    const float* wq      = (const float*)d_in[7];
    const float* bq      = (const float*)d_in[8];
    const float* wk      = (const float*)d_in[9];
    const float* bk      = (const float*)d_in[10];
    const float* wv      = (const float*)d_in[11];
    const float* wl      = (const float*)d_in[12];
    const float* uni_w   = (const float*)d_in[13];
    const float* uni_b   = (const float*)d_in[14];
    const float* ln1_g   = (const float*)d_in[15];
    const float* ln1_b   = (const float*)d_in[16];
    const float* ln2_g   = (const float*)d_in[17];
    const float* ln2_b   = (const float*)d_in[18];
    const float* ff_w1   = (const float*)d_in[19];
    const float* ff_b1   = (const float*)d_in[20];
    const float* ff_w2   = (const float*)d_in[21];
    const float* ff_b2   = (const float*)d_in[22];
    float* out = (float*)d_out;

    const int CONV_SMEM  = (9248 + 2 * 128 * 36) * 4;          // 73856
    const int FLASH_SMEM = 24576 * 4;                          // 98304 (2 blocks/SM)
    cudaFuncSetAttribute(convgemm_kernel, cudaFuncAttributeMaxDynamicSharedMemorySize, CONV_SMEM);
    cudaFuncSetAttribute(flash_mma_kernel, cudaFuncAttributeMaxDynamicSharedMemorySize, FLASH_SMEM);

    front_kernel<<<1920, 256>>>(x, sq_w, bn_g, bn_b, dw_w, ex_w, pos_emb,
                                wq, wk, wv, wl, uni_w);

    convgemm_kernel<<<dim3(32, 8, 2), 256, CONV_SMEM>>>(bq, bk);

    flash_mma_kernel<<<dim3(32, 12), 256, FLASH_SMEM>>>();          // flash + local

    unigemm_kernel<<<dim3(32, 8), 256>>>();

    ffln_kernel<<<256, 256>>>(uni_b, ln1_g, ln1_b, ln2_g, ln2_b,
                              ff_w1, ff_b1, ff_w2, ff_b2, out);
}